// round 2
// baseline (speedup 1.0000x reference)
#include <cuda_runtime.h>
#include <math.h>

// ---------------------------------------------------------------------------
// Problem constants
// ---------------------------------------------------------------------------
#define SEQ_N 2048
#define SEQ_M 2048
#define TOTK  (SEQ_N + SEQ_M)   // 4096
#define DIM   1024
#define HEADS 16
#define DH    64
#define DFF_  4096
#define MASK_VAL (-50000.0f)

// ---------------------------------------------------------------------------
// Scratch (device globals; no allocation allowed)
// ---------------------------------------------------------------------------
__device__ float g_q   [SEQ_N * DIM];        // 8  MB
__device__ float g_kv  [TOTK  * 2 * DIM];    // 32 MB  (k = cols [0,1024), v = cols [1024,2048))
__device__ float g_attn[SEQ_N * DIM];        // 8  MB
__device__ float g_t   [SEQ_N * DIM];        // 8  MB  (residual sums, reused)
__device__ float g_x1  [SEQ_N * DIM];        // 8  MB
__device__ float g_ff  [SEQ_N * DFF_];       // 32 MB

// ---------------------------------------------------------------------------
// SGEMM: C[M,N] = A[M,K] @ B[K,N]  (+ epilogue)
//   EPI 1: += bias
//   EPI 2: += bias, then exact-erf GELU
//   EPI 3: += bias, += resid[M,N]
// A2/splitRow: rows >= splitRow come from A2 (for concat([x,context]))
// BM=BN=128, BK=8, 256 threads, 8x8 per thread.
// ---------------------------------------------------------------------------
template <int EPI>
__global__ void __launch_bounds__(256)
sgemm_kernel(const float* __restrict__ A, const float* __restrict__ A2, int splitRow,
             const float* __restrict__ B, const float* __restrict__ bias,
             const float* __restrict__ resid, float* __restrict__ C,
             int M, int N, int K)
{
    __shared__ float As[8][128];
    __shared__ float Bs[8][128];

    const int tid  = threadIdx.x;
    const int bRow = blockIdx.y * 128;
    const int bCol = blockIdx.x * 128;

    const int aRow  = tid >> 1;          // 0..127
    const int aCol  = (tid & 1) * 4;     // 0 or 4
    const int bRowL = tid >> 5;          // 0..7
    const int bColL = (tid & 31) * 4;    // 0..124

    const int tRow = (tid >> 4) * 8;     // 0..120
    const int tCol = (tid & 15) * 8;     // 0..120

    float acc[8][8];
#pragma unroll
    for (int i = 0; i < 8; i++)
#pragma unroll
        for (int j = 0; j < 8; j++) acc[i][j] = 0.0f;

    const float* Aptr;
    {
        int r = bRow + aRow;
        Aptr = (A2 != nullptr && r >= splitRow) ? (A2 + (long)(r - splitRow) * K)
                                                : (A  + (long)r * K);
    }

    for (int k0 = 0; k0 < K; k0 += 8) {
        float4 a4 = *reinterpret_cast<const float4*>(Aptr + k0 + aCol);
        As[aCol + 0][aRow] = a4.x;
        As[aCol + 1][aRow] = a4.y;
        As[aCol + 2][aRow] = a4.z;
        As[aCol + 3][aRow] = a4.w;
        float4 b4 = *reinterpret_cast<const float4*>(B + (long)(k0 + bRowL) * N + bCol + bColL);
        *reinterpret_cast<float4*>(&Bs[bRowL][bColL]) = b4;
        __syncthreads();

#pragma unroll
        for (int kk = 0; kk < 8; kk++) {
            float regA[8], regB[8];
            *reinterpret_cast<float4*>(&regA[0]) = *reinterpret_cast<const float4*>(&As[kk][tRow]);
            *reinterpret_cast<float4*>(&regA[4]) = *reinterpret_cast<const float4*>(&As[kk][tRow + 4]);
            *reinterpret_cast<float4*>(&regB[0]) = *reinterpret_cast<const float4*>(&Bs[kk][tCol]);
            *reinterpret_cast<float4*>(&regB[4]) = *reinterpret_cast<const float4*>(&Bs[kk][tCol + 4]);
#pragma unroll
            for (int i = 0; i < 8; i++)
#pragma unroll
                for (int j = 0; j < 8; j++)
                    acc[i][j] += regA[i] * regB[j];
        }
        __syncthreads();
    }

#pragma unroll
    for (int i = 0; i < 8; i++) {
        const int r = bRow + tRow + i;
#pragma unroll
        for (int j = 0; j < 8; j++) {
            const int c = bCol + tCol + j;
            float v = acc[i][j];
            v += bias[c];
            if (EPI == 2) {
                v = 0.5f * v * (1.0f + erff(v * 0.70710678118654752f));
            }
            if (EPI == 3) {
                v += resid[(long)r * N + c];
            }
            C[(long)r * N + c] = v;
        }
    }
}

// ---------------------------------------------------------------------------
// Flash attention (fp32, online softmax).
// Grid: (N/64, HEADS). Block: 256 threads = 16x16 thread grid.
// Each thread owns a 4(row) x 4(col) register tile.
// smem: Qs[64][64] | KVs[64][65] | Ps[64][64]  -> 49408 B (dynamic)
// ---------------------------------------------------------------------------
#define ATT_SMEM (64*64*4 + 64*65*4 + 64*64*4)

__global__ void __launch_bounds__(256)
attn_kernel(const float* __restrict__ Q,   // [SEQ_N, DIM]
            const float* __restrict__ KV,  // [TOTK, 2*DIM]
            float* __restrict__ O)         // [SEQ_N, DIM]
{
    extern __shared__ float sm[];
    float* Qs  = sm;                    // [64][64]
    float* KVs = sm + 64 * 64;          // [64][65] (padded)
    float* Ps  = sm + 64 * 64 + 64 * 65;// [64][64]

    const int h   = blockIdx.y;
    const int q0  = blockIdx.x * 64;
    const int tid = threadIdx.x;
    const int ty  = tid >> 4;
    const int tx  = tid & 15;
    const int r0  = ty * 4;   // query rows in tile
    const int c0  = tx * 4;   // key cols (S phase) / dh dims (O phase)

    const float scale = 0.125f;  // 1/sqrt(64)

    // load Q tile (scaled)
    for (int e = tid; e < 64 * 16; e += 256) {
        int row = e >> 4, c4 = e & 15;
        float4 v = *reinterpret_cast<const float4*>(Q + (long)(q0 + row) * DIM + h * DH + c4 * 4);
        float* d = &Qs[row * 64 + c4 * 4];
        d[0] = v.x * scale; d[1] = v.y * scale; d[2] = v.z * scale; d[3] = v.w * scale;
    }

    float m_i[4], l_i[4], accO[4][4];
#pragma unroll
    for (int i = 0; i < 4; i++) {
        m_i[i] = -1e30f; l_i[i] = 0.0f;
#pragma unroll
        for (int j = 0; j < 4; j++) accO[i][j] = 0.0f;
    }
    __syncthreads();

    for (int j0 = 0; j0 < TOTK; j0 += 64) {
        // load K tile -> KVs
        for (int e = tid; e < 64 * 16; e += 256) {
            int row = e >> 4, c4 = e & 15;
            float4 v = *reinterpret_cast<const float4*>(KV + (long)(j0 + row) * (2 * DIM) + h * DH + c4 * 4);
            float* d = &KVs[row * 65 + c4 * 4];
            d[0] = v.x; d[1] = v.y; d[2] = v.z; d[3] = v.w;
        }
        __syncthreads();

        // S = Qs @ Ks^T  (4x4 per thread)
        float s[4][4];
#pragma unroll
        for (int i = 0; i < 4; i++)
#pragma unroll
            for (int j = 0; j < 4; j++) s[i][j] = 0.0f;
#pragma unroll 8
        for (int d = 0; d < DH; d++) {
            float qa[4], kb[4];
#pragma unroll
            for (int i = 0; i < 4; i++) qa[i] = Qs[(r0 + i) * 64 + d];
#pragma unroll
            for (int j = 0; j < 4; j++) kb[j] = KVs[(c0 + j) * 65 + d];
#pragma unroll
            for (int i = 0; i < 4; i++)
#pragma unroll
                for (int j = 0; j < 4; j++) s[i][j] += qa[i] * kb[j];
        }

        // causal mask: self-attention keys (col < SEQ_N) with col > row
#pragma unroll
        for (int i = 0; i < 4; i++) {
            int gq = q0 + r0 + i;
#pragma unroll
            for (int j = 0; j < 4; j++) {
                int gk = j0 + c0 + j;
                if (gk < SEQ_N && gk > gq) s[i][j] = MASK_VAL;
            }
        }

        // online softmax per row (16 lanes share a row-group via shfl width 16)
#pragma unroll
        for (int i = 0; i < 4; i++) {
            float rmax = fmaxf(fmaxf(s[i][0], s[i][1]), fmaxf(s[i][2], s[i][3]));
#pragma unroll
            for (int off = 8; off >= 1; off >>= 1)
                rmax = fmaxf(rmax, __shfl_xor_sync(0xffffffffu, rmax, off, 16));
            float mnew = fmaxf(m_i[i], rmax);
            float factor = __expf(m_i[i] - mnew);
            float rsum = 0.0f;
#pragma unroll
            for (int j = 0; j < 4; j++) {
                float p = __expf(s[i][j] - mnew);
                s[i][j] = p;
                rsum += p;
            }
#pragma unroll
            for (int off = 8; off >= 1; off >>= 1)
                rsum += __shfl_xor_sync(0xffffffffu, rsum, off, 16);
            l_i[i] = l_i[i] * factor + rsum;
            m_i[i] = mnew;
#pragma unroll
            for (int j = 0; j < 4; j++) accO[i][j] *= factor;
#pragma unroll
            for (int j = 0; j < 4; j++) Ps[(r0 + i) * 64 + (c0 + j)] = s[i][j];
        }
        __syncthreads();  // Ps ready; K reads done -> KVs reusable

        // load V tile -> KVs
        for (int e = tid; e < 64 * 16; e += 256) {
            int row = e >> 4, c4 = e & 15;
            float4 v = *reinterpret_cast<const float4*>(KV + (long)(j0 + row) * (2 * DIM) + DIM + h * DH + c4 * 4);
            float* d = &KVs[row * 65 + c4 * 4];
            d[0] = v.x; d[1] = v.y; d[2] = v.z; d[3] = v.w;
        }
        __syncthreads();

        // accO += P @ V   (thread's cols c0..c0+3 are dh dims here)
#pragma unroll 8
        for (int j = 0; j < 64; j++) {
            float pv[4], vv[4];
#pragma unroll
            for (int i = 0; i < 4; i++) pv[i] = Ps[(r0 + i) * 64 + j];
#pragma unroll
            for (int jj = 0; jj < 4; jj++) vv[jj] = KVs[j * 65 + c0 + jj];
#pragma unroll
            for (int i = 0; i < 4; i++)
#pragma unroll
                for (int jj = 0; jj < 4; jj++) accO[i][jj] += pv[i] * vv[jj];
        }
        __syncthreads();  // before next tile overwrites KVs / Ps
    }

    // epilogue: normalize and store
#pragma unroll
    for (int i = 0; i < 4; i++) {
        float inv = 1.0f / l_i[i];
#pragma unroll
        for (int jj = 0; jj < 4; jj++)
            O[(long)(q0 + r0 + i) * DIM + h * DH + c0 + jj] = accO[i][jj] * inv;
    }
}

// ---------------------------------------------------------------------------
// LayerNorm: one block per row (D=1024), 256 threads x 4 elems.
// out = (a - mu) * rsqrt(var + eps) * g + b
// ---------------------------------------------------------------------------
__global__ void __launch_bounds__(256)
ln_kernel(const float* __restrict__ a, const float* __restrict__ g,
          const float* __restrict__ beta, float* __restrict__ out)
{
    const int row = blockIdx.x;
    const float* pa = a + (long)row * DIM;
    __shared__ float sh1[8], sh2[8];

    float v[4];
    float s = 0.0f;
#pragma unroll
    for (int i = 0; i < 4; i++) {
        v[i] = pa[threadIdx.x + i * 256];
        s += v[i];
    }
#pragma unroll
    for (int off = 16; off >= 1; off >>= 1) s += __shfl_xor_sync(0xffffffffu, s, off);
    if ((threadIdx.x & 31) == 0) sh1[threadIdx.x >> 5] = s;
    __syncthreads();
    float mu = 0.0f;
#pragma unroll
    for (int i = 0; i < 8; i++) mu += sh1[i];
    mu *= (1.0f / DIM);

    float vs = 0.0f;
#pragma unroll
    for (int i = 0; i < 4; i++) {
        float d = v[i] - mu;
        vs += d * d;
    }
#pragma unroll
    for (int off = 16; off >= 1; off >>= 1) vs += __shfl_xor_sync(0xffffffffu, vs, off);
    if ((threadIdx.x & 31) == 0) sh2[threadIdx.x >> 5] = vs;
    __syncthreads();
    float var = 0.0f;
#pragma unroll
    for (int i = 0; i < 8; i++) var += sh2[i];
    float inv = rsqrtf(var * (1.0f / DIM) + 1e-5f);

#pragma unroll
    for (int i = 0; i < 4; i++) {
        int c = threadIdx.x + i * 256;
        out[(long)row * DIM + c] = (v[i] - mu) * inv * g[c] + beta[c];
    }
}

// ---------------------------------------------------------------------------
// Launch
// ---------------------------------------------------------------------------
extern "C" void kernel_launch(void* const* d_in, const int* in_sizes, int n_in,
                              void* d_out, int out_size)
{
    const float* x     = (const float*)d_in[0];
    const float* ctx   = (const float*)d_in[1];
    const float* Wq    = (const float*)d_in[2];
    const float* bq    = (const float*)d_in[3];
    const float* Wkv   = (const float*)d_in[4];
    const float* bkv   = (const float*)d_in[5];
    const float* Wo    = (const float*)d_in[6];
    const float* bo    = (const float*)d_in[7];
    const float* ln1g  = (const float*)d_in[8];
    const float* ln1b  = (const float*)d_in[9];
    const float* W1    = (const float*)d_in[10];
    const float* bf1   = (const float*)d_in[11];
    const float* W2    = (const float*)d_in[12];
    const float* bf2   = (const float*)d_in[13];
    const float* ln2g  = (const float*)d_in[14];
    const float* ln2b  = (const float*)d_in[15];
    float* out = (float*)d_out;

    float *q, *kv, *attn, *t, *x1, *ff;
    cudaGetSymbolAddress((void**)&q,    g_q);
    cudaGetSymbolAddress((void**)&kv,   g_kv);
    cudaGetSymbolAddress((void**)&attn, g_attn);
    cudaGetSymbolAddress((void**)&t,    g_t);
    cudaGetSymbolAddress((void**)&x1,   g_x1);
    cudaGetSymbolAddress((void**)&ff,   g_ff);

    cudaFuncSetAttribute(attn_kernel, cudaFuncAttributeMaxDynamicSharedMemorySize, ATT_SMEM);

    // 1) Q = x @ Wq + bq                                [2048,1024]
    sgemm_kernel<1><<<dim3(DIM / 128, SEQ_N / 128), 256>>>(
        x, nullptr, 0, Wq, bq, nullptr, q, SEQ_N, DIM, DIM);

    // 2) KV = concat(x, ctx) @ Wkv + bkv                [4096,2048]
    sgemm_kernel<1><<<dim3(2 * DIM / 128, TOTK / 128), 256>>>(
        x, ctx, SEQ_N, Wkv, bkv, nullptr, kv, TOTK, 2 * DIM, DIM);

    // 3) attention                                      [2048,1024]
    attn_kernel<<<dim3(SEQ_N / 64, HEADS), 256, ATT_SMEM>>>(q, kv, attn);

    // 4) t = attn @ Wo + bo + x
    sgemm_kernel<3><<<dim3(DIM / 128, SEQ_N / 128), 256>>>(
        attn, nullptr, 0, Wo, bo, x, t, SEQ_N, DIM, DIM);

    // 5) x1 = LN1(t)
    ln_kernel<<<SEQ_N, 256>>>(t, ln1g, ln1b, x1);

    // 6) ff = gelu(x1 @ W1 + bf1)                       [2048,4096]
    sgemm_kernel<2><<<dim3(DFF_ / 128, SEQ_N / 128), 256>>>(
        x1, nullptr, 0, W1, bf1, nullptr, ff, SEQ_N, DFF_, DIM);

    // 7) t = ff @ W2 + bf2 + x1
    sgemm_kernel<3><<<dim3(DIM / 128, SEQ_N / 128), 256>>>(
        ff, nullptr, 0, W2, bf2, x1, t, SEQ_N, DIM, DFF_);

    // 8) out = LN2(t)
    ln_kernel<<<SEQ_N, 256>>>(t, ln2g, ln2b, out);
}

// round 4
// speedup vs baseline: 1.6971x; 1.6971x over previous
#include <cuda_runtime.h>
#include <math.h>
#include <stdint.h>

// ---------------------------------------------------------------------------
// Problem constants
// ---------------------------------------------------------------------------
#define SEQ_N 2048
#define SEQ_M 2048
#define TOTK  (SEQ_N + SEQ_M)   // 4096
#define DIM   1024
#define HEADS 16
#define DH    64
#define DFF_  4096
#define MASK_VAL (-50000.0f)

// ---------------------------------------------------------------------------
// Scratch (device globals; no allocation allowed)
// ---------------------------------------------------------------------------
__device__ float g_q   [SEQ_N * DIM];
__device__ float g_kv  [TOTK  * 2 * DIM];
__device__ float g_attn[SEQ_N * DIM];
__device__ float g_t   [SEQ_N * DIM];
__device__ float g_x1  [SEQ_N * DIM];
__device__ float g_ff  [SEQ_N * DFF_];
// transposed weights (K-major [N,K] for mma.sync B operand, .col layout)
__device__ float g_wqT [DIM * DIM];
__device__ float g_wkvT[2 * DIM * DIM];
__device__ float g_woT [DIM * DIM];
__device__ float g_w1T [DFF_ * DIM];
__device__ float g_w2T [DIM * DFF_];

// ---------------------------------------------------------------------------
// PTX helpers (sm_80+ features only — this build targets plain sm_100)
// ---------------------------------------------------------------------------
__device__ __forceinline__ void cp16(uint32_t saddr, const void* g) {
    asm volatile("cp.async.cg.shared.global [%0], [%1], 16;" :: "r"(saddr), "l"(g));
}
__device__ __forceinline__ void cp_commit() {
    asm volatile("cp.async.commit_group;" ::: "memory");
}
template <int NN>
__device__ __forceinline__ void cp_wait() {
    asm volatile("cp.async.wait_group %0;" :: "n"(NN) : "memory");
}
__device__ __forceinline__ uint32_t f2tf(float f) {
    uint32_t r;
    asm("cvt.rna.tf32.f32 %0, %1;" : "=r"(r) : "f"(f));
    return r;
}
__device__ __forceinline__ void mma8(float* c, const uint32_t* a, const uint32_t* b) {
    asm volatile(
        "mma.sync.aligned.m16n8k8.row.col.f32.tf32.tf32.f32 "
        "{%0,%1,%2,%3}, {%4,%5,%6,%7}, {%8,%9}, {%0,%1,%2,%3};"
        : "+f"(c[0]), "+f"(c[1]), "+f"(c[2]), "+f"(c[3])
        : "r"(a[0]), "r"(a[1]), "r"(a[2]), "r"(a[3]), "r"(b[0]), "r"(b[1]));
}

// ---------------------------------------------------------------------------
// Transpose: out[N,K] = in[K,N]^T   (all dims multiples of 32)
// ---------------------------------------------------------------------------
__global__ void __launch_bounds__(256)
transpose_kernel(const float* __restrict__ in, float* __restrict__ out, int K, int N)
{
    __shared__ float t[32][33];
    const int bx = blockIdx.x * 32;   // N dim
    const int by = blockIdx.y * 32;   // K dim
    const int x = threadIdx.x & 31;
    const int y = threadIdx.x >> 5;   // 0..7
#pragma unroll
    for (int i = 0; i < 32; i += 8)
        t[y + i][x] = in[(size_t)(by + y + i) * N + bx + x];
    __syncthreads();
#pragma unroll
    for (int i = 0; i < 32; i += 8)
        out[(size_t)(bx + y + i) * K + by + x] = t[x][y + i];
}

// ---------------------------------------------------------------------------
// tf32 mma.sync GEMM: C[M,N] = A[M,K] @ Bt[N,K]^T  (+ epilogue)
//   EPI 1: += bias; EPI 2: += bias then exact-erf GELU; EPI 3: += bias+resid
// A2/splitRow: rows >= splitRow come from A2 (concat([x,context])).
// Tile 128x128, K-chunk 16, 256 threads (8 warps, 4x2 grid, warp tile 32x64).
// cp.async double buffer. Smem stride 20 floats -> conflict-free frag loads.
// ---------------------------------------------------------------------------
#define SSTR 20
#define SBUF (128 * SSTR)   // floats per stage per matrix

template <int EPI>
__global__ void __launch_bounds__(256)
mma_gemm(const float* __restrict__ A, const float* __restrict__ A2, int splitRow,
         const float* __restrict__ Bt, const float* __restrict__ bias,
         const float* __restrict__ resid, float* __restrict__ C,
         int M, int N, int K)
{
    __shared__ float As[2][SBUF];
    __shared__ float Bs[2][SBUF];

    const int tid  = threadIdx.x;
    const int lane = tid & 31;
    const int wid  = tid >> 5;
    const int warp_m = wid >> 1;   // 0..3
    const int warp_n = wid & 1;    // 0..1
    const int tileM = blockIdx.y * 128;
    const int tileN = blockIdx.x * 128;

    // copy assignment: each thread owns rows rA and rA+64, cols c4..c4+3
    const int rA = tid >> 2;          // 0..63
    const int c4 = (tid & 3) * 4;     // 0,4,8,12

    const float* aptr0;
    const float* aptr1;
    {
        const int r0 = tileM + rA, r1 = tileM + 64 + rA;
        aptr0 = (A2 != nullptr && r0 >= splitRow) ? A2 + (size_t)(r0 - splitRow) * K
                                                  : A + (size_t)r0 * K;
        aptr1 = (A2 != nullptr && r1 >= splitRow) ? A2 + (size_t)(r1 - splitRow) * K
                                                  : A + (size_t)r1 * K;
    }
    const float* bptr0 = Bt + (size_t)(tileN + rA) * K;
    const float* bptr1 = Bt + (size_t)(tileN + 64 + rA) * K;

    const uint32_t sA = (uint32_t)__cvta_generic_to_shared(&As[0][0]);
    const uint32_t sB = (uint32_t)__cvta_generic_to_shared(&Bs[0][0]);
    const uint32_t dA0 = sA + (uint32_t)((rA * SSTR + c4) * 4);
    const uint32_t dA1 = sA + (uint32_t)(((64 + rA) * SSTR + c4) * 4);
    const uint32_t dB0 = sB + (uint32_t)((rA * SSTR + c4) * 4);
    const uint32_t dB1 = sB + (uint32_t)(((64 + rA) * SSTR + c4) * 4);

    float acc[2][8][4];
#pragma unroll
    for (int i = 0; i < 2; i++)
#pragma unroll
        for (int j = 0; j < 8; j++)
#pragma unroll
            for (int l = 0; l < 4; l++) acc[i][j][l] = 0.0f;

    const int NKC = K / 16;

    // prefetch chunk 0 into stage 0
    {
        cp16(dA0, aptr0 + c4);
        cp16(dA1, aptr1 + c4);
        cp16(dB0, bptr0 + c4);
        cp16(dB1, bptr1 + c4);
        cp_commit();
    }

    for (int kc = 0; kc < NKC; kc++) {
        const int s = kc & 1;
        if (kc + 1 < NKC) {
            const int ns = (kc + 1) & 1;
            const int k0 = (kc + 1) * 16;
            const uint32_t off = (uint32_t)(ns * SBUF * 4);
            cp16(dA0 + off, aptr0 + k0 + c4);
            cp16(dA1 + off, aptr1 + k0 + c4);
            cp16(dB0 + off, bptr0 + k0 + c4);
            cp16(dB1 + off, bptr1 + k0 + c4);
            cp_commit();
            cp_wait<1>();
        } else {
            cp_wait<0>();
        }
        __syncthreads();

        const float* as = As[s];
        const float* bs = Bs[s];
#pragma unroll
        for (int k8 = 0; k8 < 16; k8 += 8) {
            uint32_t af[2][4];
            uint32_t bf[8][2];
            const int kk = k8 + (lane & 3);
#pragma unroll
            for (int mt = 0; mt < 2; mt++) {
                const int r = warp_m * 32 + mt * 16 + (lane >> 2);
                af[mt][0] = f2tf(as[r * SSTR + kk]);
                af[mt][1] = f2tf(as[(r + 8) * SSTR + kk]);
                af[mt][2] = f2tf(as[r * SSTR + kk + 4]);
                af[mt][3] = f2tf(as[(r + 8) * SSTR + kk + 4]);
            }
#pragma unroll
            for (int nt = 0; nt < 8; nt++) {
                const int n = warp_n * 64 + nt * 8 + (lane >> 2);
                bf[nt][0] = f2tf(bs[n * SSTR + kk]);
                bf[nt][1] = f2tf(bs[n * SSTR + kk + 4]);
            }
#pragma unroll
            for (int mt = 0; mt < 2; mt++)
#pragma unroll
                for (int nt = 0; nt < 8; nt++)
                    mma8(acc[mt][nt], af[mt], bf[nt]);
        }
        __syncthreads();
    }

    // ---- epilogue ----
#pragma unroll
    for (int mt = 0; mt < 2; mt++) {
        const int r0 = tileM + warp_m * 32 + mt * 16 + (lane >> 2);
#pragma unroll
        for (int nt = 0; nt < 8; nt++) {
            const int col = tileN + warp_n * 64 + nt * 8 + (lane & 3) * 2;
            const float2 bv = *reinterpret_cast<const float2*>(bias + col);
#pragma unroll
            for (int half = 0; half < 2; half++) {
                const int r = r0 + half * 8;
                float v0 = acc[mt][nt][half * 2 + 0] + bv.x;
                float v1 = acc[mt][nt][half * 2 + 1] + bv.y;
                if (EPI == 2) {
                    v0 = 0.5f * v0 * (1.0f + erff(v0 * 0.70710678118654752f));
                    v1 = 0.5f * v1 * (1.0f + erff(v1 * 0.70710678118654752f));
                }
                if (EPI == 3) {
                    const float2 rv = *reinterpret_cast<const float2*>(
                        resid + (size_t)r * N + col);
                    v0 += rv.x; v1 += rv.y;
                }
                float2 o; o.x = v0; o.y = v1;
                *reinterpret_cast<float2*>(C + (size_t)r * N + col) = o;
            }
        }
    }
}

// ---------------------------------------------------------------------------
// Flash attention (fp32, online softmax) — unchanged (proven correct).
// ---------------------------------------------------------------------------
#define ATT_SMEM (64*64*4 + 64*65*4 + 64*64*4)

__global__ void __launch_bounds__(256)
attn_kernel(const float* __restrict__ Q,
            const float* __restrict__ KV,
            float* __restrict__ O)
{
    extern __shared__ float sm[];
    float* Qs  = sm;
    float* KVs = sm + 64 * 64;
    float* Ps  = sm + 64 * 64 + 64 * 65;

    const int h   = blockIdx.y;
    const int q0  = blockIdx.x * 64;
    const int tid = threadIdx.x;
    const int ty  = tid >> 4;
    const int tx  = tid & 15;
    const int r0  = ty * 4;
    const int c0  = tx * 4;
    const float scale = 0.125f;

    for (int e = tid; e < 64 * 16; e += 256) {
        int row = e >> 4, cc = e & 15;
        float4 v = *reinterpret_cast<const float4*>(Q + (long)(q0 + row) * DIM + h * DH + cc * 4);
        float* d = &Qs[row * 64 + cc * 4];
        d[0] = v.x * scale; d[1] = v.y * scale; d[2] = v.z * scale; d[3] = v.w * scale;
    }

    float m_i[4], l_i[4], accO[4][4];
#pragma unroll
    for (int i = 0; i < 4; i++) {
        m_i[i] = -1e30f; l_i[i] = 0.0f;
#pragma unroll
        for (int j = 0; j < 4; j++) accO[i][j] = 0.0f;
    }
    __syncthreads();

    for (int j0 = 0; j0 < TOTK; j0 += 64) {
        for (int e = tid; e < 64 * 16; e += 256) {
            int row = e >> 4, cc = e & 15;
            float4 v = *reinterpret_cast<const float4*>(KV + (long)(j0 + row) * (2 * DIM) + h * DH + cc * 4);
            float* d = &KVs[row * 65 + cc * 4];
            d[0] = v.x; d[1] = v.y; d[2] = v.z; d[3] = v.w;
        }
        __syncthreads();

        float s[4][4];
#pragma unroll
        for (int i = 0; i < 4; i++)
#pragma unroll
            for (int j = 0; j < 4; j++) s[i][j] = 0.0f;
#pragma unroll 8
        for (int d = 0; d < DH; d++) {
            float qa[4], kb[4];
#pragma unroll
            for (int i = 0; i < 4; i++) qa[i] = Qs[(r0 + i) * 64 + d];
#pragma unroll
            for (int j = 0; j < 4; j++) kb[j] = KVs[(c0 + j) * 65 + d];
#pragma unroll
            for (int i = 0; i < 4; i++)
#pragma unroll
                for (int j = 0; j < 4; j++) s[i][j] += qa[i] * kb[j];
        }

#pragma unroll
        for (int i = 0; i < 4; i++) {
            int gq = q0 + r0 + i;
#pragma unroll
            for (int j = 0; j < 4; j++) {
                int gk = j0 + c0 + j;
                if (gk < SEQ_N && gk > gq) s[i][j] = MASK_VAL;
            }
        }

#pragma unroll
        for (int i = 0; i < 4; i++) {
            float rmax = fmaxf(fmaxf(s[i][0], s[i][1]), fmaxf(s[i][2], s[i][3]));
#pragma unroll
            for (int off = 8; off >= 1; off >>= 1)
                rmax = fmaxf(rmax, __shfl_xor_sync(0xffffffffu, rmax, off, 16));
            float mnew = fmaxf(m_i[i], rmax);
            float factor = __expf(m_i[i] - mnew);
            float rsum = 0.0f;
#pragma unroll
            for (int j = 0; j < 4; j++) {
                float p = __expf(s[i][j] - mnew);
                s[i][j] = p;
                rsum += p;
            }
#pragma unroll
            for (int off = 8; off >= 1; off >>= 1)
                rsum += __shfl_xor_sync(0xffffffffu, rsum, off, 16);
            l_i[i] = l_i[i] * factor + rsum;
            m_i[i] = mnew;
#pragma unroll
            for (int j = 0; j < 4; j++) accO[i][j] *= factor;
#pragma unroll
            for (int j = 0; j < 4; j++) Ps[(r0 + i) * 64 + (c0 + j)] = s[i][j];
        }
        __syncthreads();

        for (int e = tid; e < 64 * 16; e += 256) {
            int row = e >> 4, cc = e & 15;
            float4 v = *reinterpret_cast<const float4*>(KV + (long)(j0 + row) * (2 * DIM) + DIM + h * DH + cc * 4);
            float* d = &KVs[row * 65 + cc * 4];
            d[0] = v.x; d[1] = v.y; d[2] = v.z; d[3] = v.w;
        }
        __syncthreads();

#pragma unroll 8
        for (int j = 0; j < 64; j++) {
            float pv[4], vv[4];
#pragma unroll
            for (int i = 0; i < 4; i++) pv[i] = Ps[(r0 + i) * 64 + j];
#pragma unroll
            for (int jj = 0; jj < 4; jj++) vv[jj] = KVs[j * 65 + c0 + jj];
#pragma unroll
            for (int i = 0; i < 4; i++)
#pragma unroll
                for (int jj = 0; jj < 4; jj++) accO[i][jj] += pv[i] * vv[jj];
        }
        __syncthreads();
    }

#pragma unroll
    for (int i = 0; i < 4; i++) {
        float inv = 1.0f / l_i[i];
#pragma unroll
        for (int jj = 0; jj < 4; jj++)
            O[(long)(q0 + r0 + i) * DIM + h * DH + c0 + jj] = accO[i][jj] * inv;
    }
}

// ---------------------------------------------------------------------------
// LayerNorm — unchanged.
// ---------------------------------------------------------------------------
__global__ void __launch_bounds__(256)
ln_kernel(const float* __restrict__ a, const float* __restrict__ g,
          const float* __restrict__ beta, float* __restrict__ out)
{
    const int row = blockIdx.x;
    const float* pa = a + (long)row * DIM;
    __shared__ float sh1[8], sh2[8];

    float v[4];
    float s = 0.0f;
#pragma unroll
    for (int i = 0; i < 4; i++) {
        v[i] = pa[threadIdx.x + i * 256];
        s += v[i];
    }
#pragma unroll
    for (int off = 16; off >= 1; off >>= 1) s += __shfl_xor_sync(0xffffffffu, s, off);
    if ((threadIdx.x & 31) == 0) sh1[threadIdx.x >> 5] = s;
    __syncthreads();
    float mu = 0.0f;
#pragma unroll
    for (int i = 0; i < 8; i++) mu += sh1[i];
    mu *= (1.0f / DIM);

    float vs = 0.0f;
#pragma unroll
    for (int i = 0; i < 4; i++) {
        float d = v[i] - mu;
        vs += d * d;
    }
#pragma unroll
    for (int off = 16; off >= 1; off >>= 1) vs += __shfl_xor_sync(0xffffffffu, vs, off);
    if ((threadIdx.x & 31) == 0) sh2[threadIdx.x >> 5] = vs;
    __syncthreads();
    float var = 0.0f;
#pragma unroll
    for (int i = 0; i < 8; i++) var += sh2[i];
    float inv = rsqrtf(var * (1.0f / DIM) + 1e-5f);

#pragma unroll
    for (int i = 0; i < 4; i++) {
        int c = threadIdx.x + i * 256;
        out[(long)row * DIM + c] = (v[i] - mu) * inv * g[c] + beta[c];
    }
}

// ---------------------------------------------------------------------------
// Launch
// ---------------------------------------------------------------------------
extern "C" void kernel_launch(void* const* d_in, const int* in_sizes, int n_in,
                              void* d_out, int out_size)
{
    const float* x     = (const float*)d_in[0];
    const float* ctx   = (const float*)d_in[1];
    const float* Wq    = (const float*)d_in[2];
    const float* bq    = (const float*)d_in[3];
    const float* Wkv   = (const float*)d_in[4];
    const float* bkv   = (const float*)d_in[5];
    const float* Wo    = (const float*)d_in[6];
    const float* bo    = (const float*)d_in[7];
    const float* ln1g  = (const float*)d_in[8];
    const float* ln1b  = (const float*)d_in[9];
    const float* W1    = (const float*)d_in[10];
    const float* bf1   = (const float*)d_in[11];
    const float* W2    = (const float*)d_in[12];
    const float* bf2   = (const float*)d_in[13];
    const float* ln2g  = (const float*)d_in[14];
    const float* ln2b  = (const float*)d_in[15];
    float* out = (float*)d_out;

    float *q, *kv, *attn, *t, *x1, *ff, *wqT, *wkvT, *woT, *w1T, *w2T;
    cudaGetSymbolAddress((void**)&q,    g_q);
    cudaGetSymbolAddress((void**)&kv,   g_kv);
    cudaGetSymbolAddress((void**)&attn, g_attn);
    cudaGetSymbolAddress((void**)&t,    g_t);
    cudaGetSymbolAddress((void**)&x1,   g_x1);
    cudaGetSymbolAddress((void**)&ff,   g_ff);
    cudaGetSymbolAddress((void**)&wqT,  g_wqT);
    cudaGetSymbolAddress((void**)&wkvT, g_wkvT);
    cudaGetSymbolAddress((void**)&woT,  g_woT);
    cudaGetSymbolAddress((void**)&w1T,  g_w1T);
    cudaGetSymbolAddress((void**)&w2T,  g_w2T);

    cudaFuncSetAttribute(attn_kernel, cudaFuncAttributeMaxDynamicSharedMemorySize, ATT_SMEM);

    // 0) transpose all weights to K-major [N, K]
    transpose_kernel<<<dim3(DIM / 32, DIM / 32), 256>>>(Wq,  wqT,  DIM,  DIM);
    transpose_kernel<<<dim3(2 * DIM / 32, DIM / 32), 256>>>(Wkv, wkvT, DIM, 2 * DIM);
    transpose_kernel<<<dim3(DIM / 32, DIM / 32), 256>>>(Wo,  woT,  DIM,  DIM);
    transpose_kernel<<<dim3(DFF_ / 32, DIM / 32), 256>>>(W1,  w1T,  DIM,  DFF_);
    transpose_kernel<<<dim3(DIM / 32, DFF_ / 32), 256>>>(W2,  w2T,  DFF_, DIM);

    // 1) Q = x @ Wq + bq
    mma_gemm<1><<<dim3(DIM / 128, SEQ_N / 128), 256>>>(
        x, nullptr, 0, wqT, bq, nullptr, q, SEQ_N, DIM, DIM);

    // 2) KV = concat(x, ctx) @ Wkv + bkv
    mma_gemm<1><<<dim3(2 * DIM / 128, TOTK / 128), 256>>>(
        x, ctx, SEQ_N, wkvT, bkv, nullptr, kv, TOTK, 2 * DIM, DIM);

    // 3) attention
    attn_kernel<<<dim3(SEQ_N / 64, HEADS), 256, ATT_SMEM>>>(q, kv, attn);

    // 4) t = attn @ Wo + bo + x
    mma_gemm<3><<<dim3(DIM / 128, SEQ_N / 128), 256>>>(
        attn, nullptr, 0, woT, bo, x, t, SEQ_N, DIM, DIM);

    // 5) x1 = LN1(t)
    ln_kernel<<<SEQ_N, 256>>>(t, ln1g, ln1b, x1);

    // 6) ff = gelu(x1 @ W1 + bf1)
    mma_gemm<2><<<dim3(DFF_ / 128, SEQ_N / 128), 256>>>(
        x1, nullptr, 0, w1T, bf1, nullptr, ff, SEQ_N, DFF_, DIM);

    // 7) t = ff @ W2 + bf2 + x1
    mma_gemm<3><<<dim3(DIM / 128, SEQ_N / 128), 256>>>(
        ff, nullptr, 0, w2T, bf2, x1, t, SEQ_N, DIM, DFF_);

    // 8) out = LN2(t)
    ln_kernel<<<SEQ_N, 256>>>(t, ln2g, ln2b, out);
}

// round 5
// speedup vs baseline: 3.3670x; 1.9839x over previous
#include <cuda_runtime.h>
#include <math.h>
#include <stdint.h>

// ---------------------------------------------------------------------------
// Problem constants
// ---------------------------------------------------------------------------
#define SEQ_N 2048
#define SEQ_M 2048
#define TOTK  (SEQ_N + SEQ_M)   // 4096
#define DIM   1024
#define HEADS 16
#define DH    64
#define DFF_  4096
#define MASK_VAL (-50000.0f)

// ---------------------------------------------------------------------------
// Scratch (device globals; no allocation allowed)
// ---------------------------------------------------------------------------
__device__ float g_q   [SEQ_N * DIM];
__device__ float g_kv  [TOTK  * 2 * DIM];
__device__ float g_attn[SEQ_N * DIM];
__device__ float g_t   [SEQ_N * DIM];
__device__ float g_x1  [SEQ_N * DIM];
__device__ float g_ff  [SEQ_N * DFF_];
__device__ float g_wqT [DIM * DIM];
__device__ float g_wkvT[2 * DIM * DIM];
__device__ float g_woT [DIM * DIM];
__device__ float g_w1T [DFF_ * DIM];
__device__ float g_w2T [DIM * DFF_];

// ---------------------------------------------------------------------------
// PTX helpers (sm_80+ features only — build targets plain sm_100)
// ---------------------------------------------------------------------------
__device__ __forceinline__ float f2tf_f(float f) {
    uint32_t r;
    asm("cvt.rna.tf32.f32 %0, %1;" : "=r"(r) : "f"(f));
    return __uint_as_float(r);
}
__device__ __forceinline__ void mma8(float* c, const uint32_t* a, const uint32_t* b) {
    asm volatile(
        "mma.sync.aligned.m16n8k8.row.col.f32.tf32.tf32.f32 "
        "{%0,%1,%2,%3}, {%4,%5,%6,%7}, {%8,%9}, {%0,%1,%2,%3};"
        : "+f"(c[0]), "+f"(c[1]), "+f"(c[2]), "+f"(c[3])
        : "r"(a[0]), "r"(a[1]), "r"(a[2]), "r"(a[3]), "r"(b[0]), "r"(b[1]));
}

// ---------------------------------------------------------------------------
// Transpose: out[N,K] = in[K,N]^T
// ---------------------------------------------------------------------------
__global__ void __launch_bounds__(256)
transpose_kernel(const float* __restrict__ in, float* __restrict__ out, int K, int N)
{
    __shared__ float t[32][33];
    const int bx = blockIdx.x * 32;
    const int by = blockIdx.y * 32;
    const int x = threadIdx.x & 31;
    const int y = threadIdx.x >> 5;
#pragma unroll
    for (int i = 0; i < 32; i += 8)
        t[y + i][x] = in[(size_t)(by + y + i) * N + bx + x];
    __syncthreads();
#pragma unroll
    for (int i = 0; i < 32; i += 8)
        out[(size_t)(bx + y + i) * K + by + x] = t[x][y + i];
}

// ---------------------------------------------------------------------------
// tf32 mma.sync GEMM v2: producer-side cvt, register double-buffer.
// C[M,N] = A[M,K] @ Bt[N,K]^T (+epilogue). Tile 128x128, K-chunk 16, 256 thr.
// ---------------------------------------------------------------------------
#define SSTR 20
#define SBUF (128 * SSTR)

template <int EPI>
__global__ void __launch_bounds__(256)
mma_gemm(const float* __restrict__ A, const float* __restrict__ A2, int splitRow,
         const float* __restrict__ Bt, const float* __restrict__ bias,
         const float* __restrict__ resid, float* __restrict__ C,
         int M, int N, int K)
{
    __shared__ float As[2][SBUF];
    __shared__ float Bs[2][SBUF];

    const int tid  = threadIdx.x;
    const int lane = tid & 31;
    const int wid  = tid >> 5;
    const int warp_m = wid >> 1;
    const int warp_n = wid & 1;
    const int tileM = blockIdx.y * 128;
    const int tileN = blockIdx.x * 128;

    const int rA = tid >> 2;
    const int c4 = (tid & 3) * 4;

    const float* aptr0;
    const float* aptr1;
    {
        const int r0 = tileM + rA, r1 = tileM + 64 + rA;
        aptr0 = (A2 != nullptr && r0 >= splitRow) ? A2 + (size_t)(r0 - splitRow) * K
                                                  : A + (size_t)r0 * K;
        aptr1 = (A2 != nullptr && r1 >= splitRow) ? A2 + (size_t)(r1 - splitRow) * K
                                                  : A + (size_t)r1 * K;
    }
    const float* bptr0 = Bt + (size_t)(tileN + rA) * K;
    const float* bptr1 = Bt + (size_t)(tileN + 64 + rA) * K;

    float acc[2][8][4];
#pragma unroll
    for (int i = 0; i < 2; i++)
#pragma unroll
        for (int j = 0; j < 8; j++)
#pragma unroll
            for (int l = 0; l < 4; l++) acc[i][j][l] = 0.0f;

    const int NKC = K / 16;

    float4 pa0 = *reinterpret_cast<const float4*>(aptr0 + c4);
    float4 pa1 = *reinterpret_cast<const float4*>(aptr1 + c4);
    float4 pb0 = *reinterpret_cast<const float4*>(bptr0 + c4);
    float4 pb1 = *reinterpret_cast<const float4*>(bptr1 + c4);

    for (int kc = 0; kc < NKC; kc++) {
        const int s = kc & 1;
        __syncthreads();  // stage s free (readers from chunk kc-2 done)
        {
            float4 t0, t1;
            t0.x = f2tf_f(pa0.x); t0.y = f2tf_f(pa0.y); t0.z = f2tf_f(pa0.z); t0.w = f2tf_f(pa0.w);
            t1.x = f2tf_f(pa1.x); t1.y = f2tf_f(pa1.y); t1.z = f2tf_f(pa1.z); t1.w = f2tf_f(pa1.w);
            *reinterpret_cast<float4*>(&As[s][rA * SSTR + c4]) = t0;
            *reinterpret_cast<float4*>(&As[s][(64 + rA) * SSTR + c4]) = t1;
            t0.x = f2tf_f(pb0.x); t0.y = f2tf_f(pb0.y); t0.z = f2tf_f(pb0.z); t0.w = f2tf_f(pb0.w);
            t1.x = f2tf_f(pb1.x); t1.y = f2tf_f(pb1.y); t1.z = f2tf_f(pb1.z); t1.w = f2tf_f(pb1.w);
            *reinterpret_cast<float4*>(&Bs[s][rA * SSTR + c4]) = t0;
            *reinterpret_cast<float4*>(&Bs[s][(64 + rA) * SSTR + c4]) = t1;
        }
        if (kc + 1 < NKC) {
            const int k0 = (kc + 1) * 16;
            pa0 = *reinterpret_cast<const float4*>(aptr0 + k0 + c4);
            pa1 = *reinterpret_cast<const float4*>(aptr1 + k0 + c4);
            pb0 = *reinterpret_cast<const float4*>(bptr0 + k0 + c4);
            pb1 = *reinterpret_cast<const float4*>(bptr1 + k0 + c4);
        }
        __syncthreads();  // stage s visible

        const float* as = As[s];
        const float* bs = Bs[s];
#pragma unroll
        for (int k8 = 0; k8 < 16; k8 += 8) {
            uint32_t af[2][4];
            uint32_t bf[8][2];
            const int kk = k8 + (lane & 3);
#pragma unroll
            for (int mt = 0; mt < 2; mt++) {
                const int r = warp_m * 32 + mt * 16 + (lane >> 2);
                af[mt][0] = __float_as_uint(as[r * SSTR + kk]);
                af[mt][1] = __float_as_uint(as[(r + 8) * SSTR + kk]);
                af[mt][2] = __float_as_uint(as[r * SSTR + kk + 4]);
                af[mt][3] = __float_as_uint(as[(r + 8) * SSTR + kk + 4]);
            }
#pragma unroll
            for (int nt = 0; nt < 8; nt++) {
                const int n = warp_n * 64 + nt * 8 + (lane >> 2);
                bf[nt][0] = __float_as_uint(bs[n * SSTR + kk]);
                bf[nt][1] = __float_as_uint(bs[n * SSTR + kk + 4]);
            }
#pragma unroll
            for (int mt = 0; mt < 2; mt++)
#pragma unroll
                for (int nt = 0; nt < 8; nt++)
                    mma8(acc[mt][nt], af[mt], bf[nt]);
        }
    }

    // ---- epilogue ----
#pragma unroll
    for (int mt = 0; mt < 2; mt++) {
        const int r0 = tileM + warp_m * 32 + mt * 16 + (lane >> 2);
#pragma unroll
        for (int nt = 0; nt < 8; nt++) {
            const int col = tileN + warp_n * 64 + nt * 8 + (lane & 3) * 2;
            const float2 bv = *reinterpret_cast<const float2*>(bias + col);
#pragma unroll
            for (int half = 0; half < 2; half++) {
                const int r = r0 + half * 8;
                float v0 = acc[mt][nt][half * 2 + 0] + bv.x;
                float v1 = acc[mt][nt][half * 2 + 1] + bv.y;
                if (EPI == 2) {
                    v0 = 0.5f * v0 * (1.0f + erff(v0 * 0.70710678118654752f));
                    v1 = 0.5f * v1 * (1.0f + erff(v1 * 0.70710678118654752f));
                }
                if (EPI == 3) {
                    const float2 rv = *reinterpret_cast<const float2*>(
                        resid + (size_t)r * N + col);
                    v0 += rv.x; v1 += rv.y;
                }
                float2 o; o.x = v0; o.y = v1;
                *reinterpret_cast<float2*>(C + (size_t)r * N + col) = o;
            }
        }
    }
}

// ---------------------------------------------------------------------------
// Flash attention v2: tf32 HMMA, 256-row q tiles, 512 threads (16 warps).
// grid (SEQ_N/256, HEADS). smem: Qs[256][68] Ks[64][68] Vs[64][72] Ps[256][68]
// Strides: 68 (≡4 mod 32) conflict-free for row-major frag loads; 72 (≡8)
// conflict-free for the V (k-major) b-frag pattern.
// ---------------------------------------------------------------------------
#define QROWS 256
#define AT_QS   0
#define AT_KS   (QROWS * 68)                 // 17408
#define AT_VS   (AT_KS + 64 * 68)            // 21760
#define AT_PS   (AT_VS + 64 * 72)            // 26368
#define AT_FLOATS (AT_PS + QROWS * 68)       // 43776
#define ATT_SMEM (AT_FLOATS * 4)             // 175104 B

__global__ void __launch_bounds__(512)
attn_kernel(const float* __restrict__ Q,
            const float* __restrict__ KV,
            float* __restrict__ O)
{
    extern __shared__ float sm[];
    float* Qs = sm + AT_QS;
    float* Ks = sm + AT_KS;
    float* Vs = sm + AT_VS;
    float* Ps = sm + AT_PS;

    const int h   = blockIdx.y;
    const int q0  = blockIdx.x * QROWS;
    const int tid = threadIdx.x;
    const int wid = tid >> 5;
    const int lane = tid & 31;
    const int gid = lane >> 2;     // 0..7
    const int tig = lane & 3;      // 0..3
    const int wq0 = wid * 16;      // warp's q-row band within tile
    const float scale = 0.125f;

    // load Q tile (scaled, tf32): 256 rows x 16 float4
    for (int e = tid; e < QROWS * 16; e += 512) {
        const int row = e >> 4, cc = e & 15;
        float4 v = *reinterpret_cast<const float4*>(
            Q + (size_t)(q0 + row) * DIM + h * DH + cc * 4);
        float* d = &Qs[row * 68 + cc * 4];
        d[0] = f2tf_f(v.x * scale); d[1] = f2tf_f(v.y * scale);
        d[2] = f2tf_f(v.z * scale); d[3] = f2tf_f(v.w * scale);
    }

    float m0 = -1e30f, m1 = -1e30f, l0 = 0.0f, l1 = 0.0f;
    float accO[8][4];
#pragma unroll
    for (int nt = 0; nt < 8; nt++)
#pragma unroll
        for (int i = 0; i < 4; i++) accO[nt][i] = 0.0f;

    // prefetch tile 0 K/V into registers (64 rows x 16 float4 / 512 thr = 2 ea)
    float4 kr[2], vr[2];
    {
        const int j0 = 0;
#pragma unroll
        for (int i = 0; i < 2; i++) {
            const int e = tid + i * 512;
            const int row = e >> 4, cc = e & 15;
            kr[i] = *reinterpret_cast<const float4*>(
                KV + (size_t)(j0 + row) * (2 * DIM) + h * DH + cc * 4);
            vr[i] = *reinterpret_cast<const float4*>(
                KV + (size_t)(j0 + row) * (2 * DIM) + DIM + h * DH + cc * 4);
        }
    }

    const int gq0 = q0 + wq0 + gid;   // row for c0,c1
    const int gq1 = gq0 + 8;          // row for c2,c3

    int j0 = 0;
    while (j0 < TOTK) {
        // next valid tile (skip fully-masked self tiles)
        int nj = j0 + 64;
        if (nj >= q0 + QROWS && nj < SEQ_N) nj = SEQ_N;

        __syncthreads();  // all warps done reading Ks/Vs of previous tile
        // store K/V (tf32)
#pragma unroll
        for (int i = 0; i < 2; i++) {
            const int e = tid + i * 512;
            const int row = e >> 4, cc = e & 15;
            float* dk = &Ks[row * 68 + cc * 4];
            dk[0] = f2tf_f(kr[i].x); dk[1] = f2tf_f(kr[i].y);
            dk[2] = f2tf_f(kr[i].z); dk[3] = f2tf_f(kr[i].w);
            float* dv = &Vs[row * 72 + cc * 4];
            dv[0] = f2tf_f(vr[i].x); dv[1] = f2tf_f(vr[i].y);
            dv[2] = f2tf_f(vr[i].z); dv[3] = f2tf_f(vr[i].w);
        }
        if (nj < TOTK) {
#pragma unroll
            for (int i = 0; i < 2; i++) {
                const int e = tid + i * 512;
                const int row = e >> 4, cc = e & 15;
                kr[i] = *reinterpret_cast<const float4*>(
                    KV + (size_t)(nj + row) * (2 * DIM) + h * DH + cc * 4);
                vr[i] = *reinterpret_cast<const float4*>(
                    KV + (size_t)(nj + row) * (2 * DIM) + DIM + h * DH + cc * 4);
            }
        }
        __syncthreads();  // K/V visible

        // ---- S = Q @ K^T ----
        float s[8][4];
#pragma unroll
        for (int nt = 0; nt < 8; nt++)
#pragma unroll
            for (int i = 0; i < 4; i++) s[nt][i] = 0.0f;
#pragma unroll
        for (int kf = 0; kf < 8; kf++) {
            const int kk = kf * 8 + tig;
            uint32_t a[4];
            a[0] = __float_as_uint(Qs[(wq0 + gid) * 68 + kk]);
            a[1] = __float_as_uint(Qs[(wq0 + gid + 8) * 68 + kk]);
            a[2] = __float_as_uint(Qs[(wq0 + gid) * 68 + kk + 4]);
            a[3] = __float_as_uint(Qs[(wq0 + gid + 8) * 68 + kk + 4]);
#pragma unroll
            for (int nt = 0; nt < 8; nt++) {
                uint32_t b[2];
                b[0] = __float_as_uint(Ks[(nt * 8 + gid) * 68 + kk]);
                b[1] = __float_as_uint(Ks[(nt * 8 + gid) * 68 + kk + 4]);
                mma8(s[nt], a, b);
            }
        }

        // ---- causal mask (self-attention keys only) ----
        if (j0 < SEQ_N) {
#pragma unroll
            for (int nt = 0; nt < 8; nt++) {
                const int gk = j0 + nt * 8 + 2 * tig;
                if (gk > gq0)     s[nt][0] = MASK_VAL;
                if (gk + 1 > gq0) s[nt][1] = MASK_VAL;
                if (gk > gq1)     s[nt][2] = MASK_VAL;
                if (gk + 1 > gq1) s[nt][3] = MASK_VAL;
            }
        }

        // ---- online softmax (rows gq0, gq1; 4 lanes per row share cols) ----
        float mx0 = -1e30f, mx1 = -1e30f;
#pragma unroll
        for (int nt = 0; nt < 8; nt++) {
            mx0 = fmaxf(mx0, fmaxf(s[nt][0], s[nt][1]));
            mx1 = fmaxf(mx1, fmaxf(s[nt][2], s[nt][3]));
        }
        mx0 = fmaxf(mx0, __shfl_xor_sync(0xffffffffu, mx0, 1));
        mx0 = fmaxf(mx0, __shfl_xor_sync(0xffffffffu, mx0, 2));
        mx1 = fmaxf(mx1, __shfl_xor_sync(0xffffffffu, mx1, 1));
        mx1 = fmaxf(mx1, __shfl_xor_sync(0xffffffffu, mx1, 2));
        const float mn0 = fmaxf(m0, mx0);
        const float mn1 = fmaxf(m1, mx1);
        const float fac0 = __expf(m0 - mn0);
        const float fac1 = __expf(m1 - mn1);
        float sum0 = 0.0f, sum1 = 0.0f;
#pragma unroll
        for (int nt = 0; nt < 8; nt++) {
            s[nt][0] = __expf(s[nt][0] - mn0);
            s[nt][1] = __expf(s[nt][1] - mn0);
            s[nt][2] = __expf(s[nt][2] - mn1);
            s[nt][3] = __expf(s[nt][3] - mn1);
            sum0 += s[nt][0] + s[nt][1];
            sum1 += s[nt][2] + s[nt][3];
        }
        sum0 += __shfl_xor_sync(0xffffffffu, sum0, 1);
        sum0 += __shfl_xor_sync(0xffffffffu, sum0, 2);
        sum1 += __shfl_xor_sync(0xffffffffu, sum1, 1);
        sum1 += __shfl_xor_sync(0xffffffffu, sum1, 2);
        l0 = l0 * fac0 + sum0;
        l1 = l1 * fac1 + sum1;
        m0 = mn0; m1 = mn1;
#pragma unroll
        for (int nt = 0; nt < 8; nt++) {
            accO[nt][0] *= fac0; accO[nt][1] *= fac0;
            accO[nt][2] *= fac1; accO[nt][3] *= fac1;
        }
        // store P (tf32) — warp-private rows
#pragma unroll
        for (int nt = 0; nt < 8; nt++) {
            float2 p0; p0.x = f2tf_f(s[nt][0]); p0.y = f2tf_f(s[nt][1]);
            float2 p1; p1.x = f2tf_f(s[nt][2]); p1.y = f2tf_f(s[nt][3]);
            *reinterpret_cast<float2*>(&Ps[(wq0 + gid) * 68 + nt * 8 + 2 * tig]) = p0;
            *reinterpret_cast<float2*>(&Ps[(wq0 + gid + 8) * 68 + nt * 8 + 2 * tig]) = p1;
        }
        __syncwarp();

        // ---- accO += P @ V ----
#pragma unroll
        for (int kf = 0; kf < 8; kf++) {
            const int kk = kf * 8 + tig;
            uint32_t a[4];
            a[0] = __float_as_uint(Ps[(wq0 + gid) * 68 + kk]);
            a[1] = __float_as_uint(Ps[(wq0 + gid + 8) * 68 + kk]);
            a[2] = __float_as_uint(Ps[(wq0 + gid) * 68 + kk + 4]);
            a[3] = __float_as_uint(Ps[(wq0 + gid + 8) * 68 + kk + 4]);
#pragma unroll
            for (int nt = 0; nt < 8; nt++) {
                uint32_t b[2];
                b[0] = __float_as_uint(Vs[kk * 72 + nt * 8 + gid]);
                b[1] = __float_as_uint(Vs[(kk + 4) * 72 + nt * 8 + gid]);
                mma8(accO[nt], a, b);
            }
        }
        j0 = nj;
    }

    // ---- epilogue ----
    const float inv0 = 1.0f / l0;
    const float inv1 = 1.0f / l1;
#pragma unroll
    for (int nt = 0; nt < 8; nt++) {
        const int col = h * DH + nt * 8 + 2 * tig;
        float2 o0; o0.x = accO[nt][0] * inv0; o0.y = accO[nt][1] * inv0;
        float2 o1; o1.x = accO[nt][2] * inv1; o1.y = accO[nt][3] * inv1;
        *reinterpret_cast<float2*>(O + (size_t)gq0 * DIM + col) = o0;
        *reinterpret_cast<float2*>(O + (size_t)gq1 * DIM + col) = o1;
    }
}

// ---------------------------------------------------------------------------
// LayerNorm — unchanged.
// ---------------------------------------------------------------------------
__global__ void __launch_bounds__(256)
ln_kernel(const float* __restrict__ a, const float* __restrict__ g,
          const float* __restrict__ beta, float* __restrict__ out)
{
    const int row = blockIdx.x;
    const float* pa = a + (long)row * DIM;
    __shared__ float sh1[8], sh2[8];

    float v[4];
    float s = 0.0f;
#pragma unroll
    for (int i = 0; i < 4; i++) {
        v[i] = pa[threadIdx.x + i * 256];
        s += v[i];
    }
#pragma unroll
    for (int off = 16; off >= 1; off >>= 1) s += __shfl_xor_sync(0xffffffffu, s, off);
    if ((threadIdx.x & 31) == 0) sh1[threadIdx.x >> 5] = s;
    __syncthreads();
    float mu = 0.0f;
#pragma unroll
    for (int i = 0; i < 8; i++) mu += sh1[i];
    mu *= (1.0f / DIM);

    float vs = 0.0f;
#pragma unroll
    for (int i = 0; i < 4; i++) {
        float d = v[i] - mu;
        vs += d * d;
    }
#pragma unroll
    for (int off = 16; off >= 1; off >>= 1) vs += __shfl_xor_sync(0xffffffffu, vs, off);
    if ((threadIdx.x & 31) == 0) sh2[threadIdx.x >> 5] = vs;
    __syncthreads();
    float var = 0.0f;
#pragma unroll
    for (int i = 0; i < 8; i++) var += sh2[i];
    float inv = rsqrtf(var * (1.0f / DIM) + 1e-5f);

#pragma unroll
    for (int i = 0; i < 4; i++) {
        int c = threadIdx.x + i * 256;
        out[(long)row * DIM + c] = (v[i] - mu) * inv * g[c] + beta[c];
    }
}

// ---------------------------------------------------------------------------
// Launch
// ---------------------------------------------------------------------------
extern "C" void kernel_launch(void* const* d_in, const int* in_sizes, int n_in,
                              void* d_out, int out_size)
{
    const float* x     = (const float*)d_in[0];
    const float* ctx   = (const float*)d_in[1];
    const float* Wq    = (const float*)d_in[2];
    const float* bq    = (const float*)d_in[3];
    const float* Wkv   = (const float*)d_in[4];
    const float* bkv   = (const float*)d_in[5];
    const float* Wo    = (const float*)d_in[6];
    const float* bo    = (const float*)d_in[7];
    const float* ln1g  = (const float*)d_in[8];
    const float* ln1b  = (const float*)d_in[9];
    const float* W1    = (const float*)d_in[10];
    const float* bf1   = (const float*)d_in[11];
    const float* W2    = (const float*)d_in[12];
    const float* bf2   = (const float*)d_in[13];
    const float* ln2g  = (const float*)d_in[14];
    const float* ln2b  = (const float*)d_in[15];
    float* out = (float*)d_out;

    float *q, *kv, *attn, *t, *x1, *ff, *wqT, *wkvT, *woT, *w1T, *w2T;
    cudaGetSymbolAddress((void**)&q,    g_q);
    cudaGetSymbolAddress((void**)&kv,   g_kv);
    cudaGetSymbolAddress((void**)&attn, g_attn);
    cudaGetSymbolAddress((void**)&t,    g_t);
    cudaGetSymbolAddress((void**)&x1,   g_x1);
    cudaGetSymbolAddress((void**)&ff,   g_ff);
    cudaGetSymbolAddress((void**)&wqT,  g_wqT);
    cudaGetSymbolAddress((void**)&wkvT, g_wkvT);
    cudaGetSymbolAddress((void**)&woT,  g_woT);
    cudaGetSymbolAddress((void**)&w1T,  g_w1T);
    cudaGetSymbolAddress((void**)&w2T,  g_w2T);

    cudaFuncSetAttribute(attn_kernel, cudaFuncAttributeMaxDynamicSharedMemorySize, ATT_SMEM);

    // 0) transpose all weights to K-major [N, K]
    transpose_kernel<<<dim3(DIM / 32, DIM / 32), 256>>>(Wq,  wqT,  DIM,  DIM);
    transpose_kernel<<<dim3(2 * DIM / 32, DIM / 32), 256>>>(Wkv, wkvT, DIM, 2 * DIM);
    transpose_kernel<<<dim3(DIM / 32, DIM / 32), 256>>>(Wo,  woT,  DIM,  DIM);
    transpose_kernel<<<dim3(DFF_ / 32, DIM / 32), 256>>>(W1,  w1T,  DIM,  DFF_);
    transpose_kernel<<<dim3(DIM / 32, DFF_ / 32), 256>>>(W2,  w2T,  DFF_, DIM);

    // 1) Q = x @ Wq + bq
    mma_gemm<1><<<dim3(DIM / 128, SEQ_N / 128), 256>>>(
        x, nullptr, 0, wqT, bq, nullptr, q, SEQ_N, DIM, DIM);

    // 2) KV = concat(x, ctx) @ Wkv + bkv
    mma_gemm<1><<<dim3(2 * DIM / 128, TOTK / 128), 256>>>(
        x, ctx, SEQ_N, wkvT, bkv, nullptr, kv, TOTK, 2 * DIM, DIM);

    // 3) attention (tensorized, 256-row q tiles)
    attn_kernel<<<dim3(SEQ_N / QROWS, HEADS), 512, ATT_SMEM>>>(q, kv, attn);

    // 4) t = attn @ Wo + bo + x
    mma_gemm<3><<<dim3(DIM / 128, SEQ_N / 128), 256>>>(
        attn, nullptr, 0, woT, bo, x, t, SEQ_N, DIM, DIM);

    // 5) x1 = LN1(t)
    ln_kernel<<<SEQ_N, 256>>>(t, ln1g, ln1b, x1);

    // 6) ff = gelu(x1 @ W1 + bf1)
    mma_gemm<2><<<dim3(DFF_ / 128, SEQ_N / 128), 256>>>(
        x1, nullptr, 0, w1T, bf1, nullptr, ff, SEQ_N, DFF_, DIM);

    // 7) t = ff @ W2 + bf2 + x1
    mma_gemm<3><<<dim3(DIM / 128, SEQ_N / 128), 256>>>(
        ff, nullptr, 0, w2T, bf2, x1, t, SEQ_N, DIM, DFF_);

    // 8) out = LN2(t)
    ln_kernel<<<SEQ_N, 256>>>(t, ln2g, ln2b, out);
}

// round 6
// speedup vs baseline: 5.4047x; 1.6052x over previous
#include <cuda_runtime.h>
#include <cuda_fp16.h>
#include <math.h>
#include <stdint.h>

// ---------------------------------------------------------------------------
// Problem constants
// ---------------------------------------------------------------------------
#define SEQ_N 2048
#define SEQ_M 2048
#define TOTK  (SEQ_N + SEQ_M)   // 4096
#define DIM   1024
#define HEADS 16
#define DH    64
#define DFF_  4096
#define MASK_VAL (-50000.0f)

// ---------------------------------------------------------------------------
// Scratch (device globals; no allocation allowed)
// ---------------------------------------------------------------------------
__device__ float  g_q   [SEQ_N * DIM];
__device__ float  g_kv  [TOTK  * 2 * DIM];   // K = cols [0,1024), V = cols [1024,2048)
__device__ float  g_vT  [DIM * TOTK];        // V transposed [dh_global][seq]
__device__ float  g_attn[SEQ_N * DIM];
__device__ float  g_t   [SEQ_N * DIM];
__device__ float  g_x1  [SEQ_N * DIM];
__device__ float  g_ff  [SEQ_N * DFF_];
// transposed + fp16 weights (K-major [N,K] for mma B operand, .col layout)
__device__ __half g_wqT [DIM * DIM];
__device__ __half g_wkvT[2 * DIM * DIM];
__device__ __half g_woT [DIM * DIM];
__device__ __half g_w1T [DFF_ * DIM];
__device__ __half g_w2T [DIM * DFF_];

// ---------------------------------------------------------------------------
// Helpers
// ---------------------------------------------------------------------------
__device__ __forceinline__ uint32_t pk2(float a, float b) {
    __half2 h = __floats2half2_rn(a, b);
    return *reinterpret_cast<uint32_t*>(&h);
}
__device__ __forceinline__ void mma16(float* c, const uint32_t* a, const uint32_t* b) {
    asm volatile(
        "mma.sync.aligned.m16n8k16.row.col.f32.f16.f16.f32 "
        "{%0,%1,%2,%3}, {%4,%5,%6,%7}, {%8,%9}, {%0,%1,%2,%3};"
        : "+f"(c[0]), "+f"(c[1]), "+f"(c[2]), "+f"(c[3])
        : "r"(a[0]), "r"(a[1]), "r"(a[2]), "r"(a[3]), "r"(b[0]), "r"(b[1]));
}

// ---------------------------------------------------------------------------
// Transpose + fp16 convert: out[N][K] (half) = in[K][N]^T (float)
// ---------------------------------------------------------------------------
__global__ void __launch_bounds__(256)
transpose_h_kernel(const float* __restrict__ in, __half* __restrict__ out, int K, int N)
{
    __shared__ float t[32][33];
    const int bx = blockIdx.x * 32;
    const int by = blockIdx.y * 32;
    const int x = threadIdx.x & 31;
    const int y = threadIdx.x >> 5;
#pragma unroll
    for (int i = 0; i < 32; i += 8)
        t[y + i][x] = in[(size_t)(by + y + i) * N + bx + x];
    __syncthreads();
#pragma unroll
    for (int i = 0; i < 32; i += 8)
        out[(size_t)(bx + y + i) * K + by + x] = __float2half_rn(t[x][y + i]);
}

// ---------------------------------------------------------------------------
// Float transpose with input row stride (for V slice of g_kv):
// out[c][r] = in[r * instride + c],  r < R, c < C
// ---------------------------------------------------------------------------
__global__ void __launch_bounds__(256)
transpose_f_kernel(const float* __restrict__ in, float* __restrict__ out,
                   int R, int C, int instride)
{
    __shared__ float t[32][33];
    const int bx = blockIdx.x * 32;   // C dim
    const int by = blockIdx.y * 32;   // R dim
    const int x = threadIdx.x & 31;
    const int y = threadIdx.x >> 5;
#pragma unroll
    for (int i = 0; i < 32; i += 8)
        t[y + i][x] = in[(size_t)(by + y + i) * instride + bx + x];
    __syncthreads();
#pragma unroll
    for (int i = 0; i < 32; i += 8)
        out[(size_t)(bx + y + i) * R + by + x] = t[x][y + i];
}

// ---------------------------------------------------------------------------
// fp16 mma.sync GEMM: C[M,N] = A[M,K] @ Bt[N,K]^T (+epilogue), fp32 accum.
//   EPI 1: +bias; EPI 2: +bias,GELU; EPI 3: +bias,+resid.
// Tile 128x128, K-chunk 32, 256 thr (8 warps 4x2, warp tile 32x64).
// A float in gmem (converted in producer); Bt half in gmem.
// Smem stride 40 halfs (word=20r+t: conflict-free).
// ---------------------------------------------------------------------------
#define HSTR 40
#define HBUF (128 * HSTR)

template <int EPI>
__global__ void __launch_bounds__(256)
mma_gemm(const float* __restrict__ A, const float* __restrict__ A2, int splitRow,
         const __half* __restrict__ Bt, const float* __restrict__ bias,
         const float* __restrict__ resid, float* __restrict__ C,
         int M, int N, int K)
{
    __shared__ __half As[2][HBUF];
    __shared__ __half Bs[2][HBUF];

    const int tid  = threadIdx.x;
    const int lane = tid & 31;
    const int wid  = tid >> 5;
    const int g    = lane >> 2;
    const int tg   = lane & 3;
    const int warp_m = wid >> 1;
    const int warp_n = wid & 1;
    const int tileM = blockIdx.y * 128;
    const int tileN = blockIdx.x * 128;

    const int rA = tid >> 2;          // 0..63
    const int t4 = tid & 3;

    const float* aptr0;
    const float* aptr1;
    {
        const int r0 = tileM + rA, r1 = tileM + 64 + rA;
        aptr0 = (A2 != nullptr && r0 >= splitRow) ? A2 + (size_t)(r0 - splitRow) * K
                                                  : A + (size_t)r0 * K;
        aptr1 = (A2 != nullptr && r1 >= splitRow) ? A2 + (size_t)(r1 - splitRow) * K
                                                  : A + (size_t)r1 * K;
    }
    const __half* bptr0 = Bt + (size_t)(tileN + rA) * K;
    const __half* bptr1 = Bt + (size_t)(tileN + 64 + rA) * K;

    float acc[2][8][4];
#pragma unroll
    for (int i = 0; i < 2; i++)
#pragma unroll
        for (int j = 0; j < 8; j++)
#pragma unroll
            for (int l = 0; l < 4; l++) acc[i][j][l] = 0.0f;

    const int NKC = K / 32;

    float4 pa[4];
    uint4  pb[2];
    {
        const int off = t4 * 8;
        pa[0] = *reinterpret_cast<const float4*>(aptr0 + off);
        pa[1] = *reinterpret_cast<const float4*>(aptr0 + off + 4);
        pa[2] = *reinterpret_cast<const float4*>(aptr1 + off);
        pa[3] = *reinterpret_cast<const float4*>(aptr1 + off + 4);
        pb[0] = *reinterpret_cast<const uint4*>(bptr0 + off);
        pb[1] = *reinterpret_cast<const uint4*>(bptr1 + off);
    }

    for (int kc = 0; kc < NKC; kc++) {
        const int s = kc & 1;
        __syncthreads();  // stage s free
        {
            uint4 ha;
            ha.x = pk2(pa[0].x, pa[0].y); ha.y = pk2(pa[0].z, pa[0].w);
            ha.z = pk2(pa[1].x, pa[1].y); ha.w = pk2(pa[1].z, pa[1].w);
            *reinterpret_cast<uint4*>(&As[s][rA * HSTR + t4 * 8]) = ha;
            ha.x = pk2(pa[2].x, pa[2].y); ha.y = pk2(pa[2].z, pa[2].w);
            ha.z = pk2(pa[3].x, pa[3].y); ha.w = pk2(pa[3].z, pa[3].w);
            *reinterpret_cast<uint4*>(&As[s][(64 + rA) * HSTR + t4 * 8]) = ha;
            *reinterpret_cast<uint4*>(&Bs[s][rA * HSTR + t4 * 8]) = pb[0];
            *reinterpret_cast<uint4*>(&Bs[s][(64 + rA) * HSTR + t4 * 8]) = pb[1];
        }
        if (kc + 1 < NKC) {
            const int off = (kc + 1) * 32 + t4 * 8;
            pa[0] = *reinterpret_cast<const float4*>(aptr0 + off);
            pa[1] = *reinterpret_cast<const float4*>(aptr0 + off + 4);
            pa[2] = *reinterpret_cast<const float4*>(aptr1 + off);
            pa[3] = *reinterpret_cast<const float4*>(aptr1 + off + 4);
            pb[0] = *reinterpret_cast<const uint4*>(bptr0 + off);
            pb[1] = *reinterpret_cast<const uint4*>(bptr1 + off);
        }
        __syncthreads();  // stage s visible

        const __half* as = As[s];
        const __half* bs = Bs[s];
#pragma unroll
        for (int kk = 0; kk < 32; kk += 16) {
            uint32_t af[2][4];
            uint32_t bf[8][2];
#pragma unroll
            for (int mt = 0; mt < 2; mt++) {
                const int r = warp_m * 32 + mt * 16 + g;
                af[mt][0] = *reinterpret_cast<const uint32_t*>(&as[r * HSTR + kk + 2 * tg]);
                af[mt][1] = *reinterpret_cast<const uint32_t*>(&as[(r + 8) * HSTR + kk + 2 * tg]);
                af[mt][2] = *reinterpret_cast<const uint32_t*>(&as[r * HSTR + kk + 2 * tg + 8]);
                af[mt][3] = *reinterpret_cast<const uint32_t*>(&as[(r + 8) * HSTR + kk + 2 * tg + 8]);
            }
#pragma unroll
            for (int nt = 0; nt < 8; nt++) {
                const int n = warp_n * 64 + nt * 8 + g;
                bf[nt][0] = *reinterpret_cast<const uint32_t*>(&bs[n * HSTR + kk + 2 * tg]);
                bf[nt][1] = *reinterpret_cast<const uint32_t*>(&bs[n * HSTR + kk + 2 * tg + 8]);
            }
#pragma unroll
            for (int mt = 0; mt < 2; mt++)
#pragma unroll
                for (int nt = 0; nt < 8; nt++)
                    mma16(acc[mt][nt], af[mt], bf[nt]);
        }
    }

    // ---- epilogue ----
#pragma unroll
    for (int mt = 0; mt < 2; mt++) {
        const int r0 = tileM + warp_m * 32 + mt * 16 + g;
#pragma unroll
        for (int nt = 0; nt < 8; nt++) {
            const int col = tileN + warp_n * 64 + nt * 8 + tg * 2;
            const float2 bv = *reinterpret_cast<const float2*>(bias + col);
#pragma unroll
            for (int half_ = 0; half_ < 2; half_++) {
                const int r = r0 + half_ * 8;
                float v0 = acc[mt][nt][half_ * 2 + 0] + bv.x;
                float v1 = acc[mt][nt][half_ * 2 + 1] + bv.y;
                if (EPI == 2) {
                    v0 = 0.5f * v0 * (1.0f + erff(v0 * 0.70710678118654752f));
                    v1 = 0.5f * v1 * (1.0f + erff(v1 * 0.70710678118654752f));
                }
                if (EPI == 3) {
                    const float2 rv = *reinterpret_cast<const float2*>(
                        resid + (size_t)r * N + col);
                    v0 += rv.x; v1 += rv.y;
                }
                float2 o; o.x = v0; o.y = v1;
                *reinterpret_cast<float2*>(C + (size_t)r * N + col) = o;
            }
        }
    }
}

// ---------------------------------------------------------------------------
// Flash attention v3: fp16 m16n8k16 HMMA, 256-row q tiles, 512 threads.
// grid (SEQ_N/256, HEADS). All smem half, stride 72 (word=36r+t, conflict-free).
// V comes pre-transposed from g_vT[dh_global][seq].
// ---------------------------------------------------------------------------
#define QROWS 256
#define HS 72
#define AQ_QS 0
#define AQ_KS (QROWS * HS)             // 18432
#define AQ_VS (AQ_KS + 64 * HS)        // 23040
#define AQ_PS (AQ_VS + 64 * HS)        // 27648
#define AQ_HALFS (AQ_PS + QROWS * HS)  // 46080
#define ATT_SMEM (AQ_HALFS * 2)        // 92160 B

__global__ void __launch_bounds__(512)
attn_kernel(const float* __restrict__ Q,
            const float* __restrict__ KV,
            const float* __restrict__ VT,
            float* __restrict__ O)
{
    extern __shared__ __half smh[];
    __half* Qs  = smh + AQ_QS;
    __half* Ks  = smh + AQ_KS;
    __half* VTs = smh + AQ_VS;
    __half* Ps  = smh + AQ_PS;

    const int h   = blockIdx.y;
    const int q0  = blockIdx.x * QROWS;
    const int tid = threadIdx.x;
    const int wid = tid >> 5;
    const int lane = tid & 31;
    const int g   = lane >> 2;
    const int tg  = lane & 3;
    const int wq0 = wid * 16;
    const float scale = 0.125f;

    // load Q tile (scaled, half)
    for (int e = tid; e < QROWS * 16; e += 512) {
        const int row = e >> 4, cc = e & 15;
        float4 v = *reinterpret_cast<const float4*>(
            Q + (size_t)(q0 + row) * DIM + h * DH + cc * 4);
        uint2 hv;
        hv.x = pk2(v.x * scale, v.y * scale);
        hv.y = pk2(v.z * scale, v.w * scale);
        *reinterpret_cast<uint2*>(&Qs[row * HS + cc * 4]) = hv;
    }

    float m0 = -1e30f, m1 = -1e30f, l0 = 0.0f, l1 = 0.0f;
    float accO[8][4];
#pragma unroll
    for (int nt = 0; nt < 8; nt++)
#pragma unroll
        for (int i = 0; i < 4; i++) accO[nt][i] = 0.0f;

    // prefetch tile 0 (K rows; VT rows = dh)
    float4 kr[2], vr[2];
#pragma unroll
    for (int i = 0; i < 2; i++) {
        const int e = tid + i * 512;
        const int row = e >> 4, cc = e & 15;
        kr[i] = *reinterpret_cast<const float4*>(
            KV + (size_t)row * (2 * DIM) + h * DH + cc * 4);
        vr[i] = *reinterpret_cast<const float4*>(
            VT + (size_t)(h * DH + row) * TOTK + cc * 4);
    }

    const int gq0 = q0 + wq0 + g;
    const int gq1 = gq0 + 8;

    int j0 = 0;
    while (j0 < TOTK) {
        int nj = j0 + 64;
        if (nj >= q0 + QROWS && nj < SEQ_N) nj = SEQ_N;  // causal tile skip

        __syncthreads();
#pragma unroll
        for (int i = 0; i < 2; i++) {
            const int e = tid + i * 512;
            const int row = e >> 4, cc = e & 15;
            uint2 hk; hk.x = pk2(kr[i].x, kr[i].y); hk.y = pk2(kr[i].z, kr[i].w);
            *reinterpret_cast<uint2*>(&Ks[row * HS + cc * 4]) = hk;
            uint2 hv; hv.x = pk2(vr[i].x, vr[i].y); hv.y = pk2(vr[i].z, vr[i].w);
            *reinterpret_cast<uint2*>(&VTs[row * HS + cc * 4]) = hv;
        }
        if (nj < TOTK) {
#pragma unroll
            for (int i = 0; i < 2; i++) {
                const int e = tid + i * 512;
                const int row = e >> 4, cc = e & 15;
                kr[i] = *reinterpret_cast<const float4*>(
                    KV + (size_t)(nj + row) * (2 * DIM) + h * DH + cc * 4);
                vr[i] = *reinterpret_cast<const float4*>(
                    VT + (size_t)(h * DH + row) * TOTK + nj + cc * 4);
            }
        }
        __syncthreads();

        // ---- S = Q @ K^T (4 k16 steps) ----
        float s[8][4];
#pragma unroll
        for (int nt = 0; nt < 8; nt++)
#pragma unroll
            for (int i = 0; i < 4; i++) s[nt][i] = 0.0f;
#pragma unroll
        for (int kf = 0; kf < 4; kf++) {
            const int kk = kf * 16;
            uint32_t a[4];
            const int r = wq0 + g;
            a[0] = *reinterpret_cast<const uint32_t*>(&Qs[r * HS + kk + 2 * tg]);
            a[1] = *reinterpret_cast<const uint32_t*>(&Qs[(r + 8) * HS + kk + 2 * tg]);
            a[2] = *reinterpret_cast<const uint32_t*>(&Qs[r * HS + kk + 2 * tg + 8]);
            a[3] = *reinterpret_cast<const uint32_t*>(&Qs[(r + 8) * HS + kk + 2 * tg + 8]);
#pragma unroll
            for (int nt = 0; nt < 8; nt++) {
                const int n = nt * 8 + g;
                uint32_t b[2];
                b[0] = *reinterpret_cast<const uint32_t*>(&Ks[n * HS + kk + 2 * tg]);
                b[1] = *reinterpret_cast<const uint32_t*>(&Ks[n * HS + kk + 2 * tg + 8]);
                mma16(s[nt], a, b);
            }
        }

        // ---- causal mask ----
        if (j0 < SEQ_N) {
#pragma unroll
            for (int nt = 0; nt < 8; nt++) {
                const int gk = j0 + nt * 8 + 2 * tg;
                if (gk > gq0)     s[nt][0] = MASK_VAL;
                if (gk + 1 > gq0) s[nt][1] = MASK_VAL;
                if (gk > gq1)     s[nt][2] = MASK_VAL;
                if (gk + 1 > gq1) s[nt][3] = MASK_VAL;
            }
        }

        // ---- online softmax ----
        float mx0 = -1e30f, mx1 = -1e30f;
#pragma unroll
        for (int nt = 0; nt < 8; nt++) {
            mx0 = fmaxf(mx0, fmaxf(s[nt][0], s[nt][1]));
            mx1 = fmaxf(mx1, fmaxf(s[nt][2], s[nt][3]));
        }
        mx0 = fmaxf(mx0, __shfl_xor_sync(0xffffffffu, mx0, 1));
        mx0 = fmaxf(mx0, __shfl_xor_sync(0xffffffffu, mx0, 2));
        mx1 = fmaxf(mx1, __shfl_xor_sync(0xffffffffu, mx1, 1));
        mx1 = fmaxf(mx1, __shfl_xor_sync(0xffffffffu, mx1, 2));
        const float mn0 = fmaxf(m0, mx0);
        const float mn1 = fmaxf(m1, mx1);
        const float fac0 = __expf(m0 - mn0);
        const float fac1 = __expf(m1 - mn1);
        float sum0 = 0.0f, sum1 = 0.0f;
#pragma unroll
        for (int nt = 0; nt < 8; nt++) {
            s[nt][0] = __expf(s[nt][0] - mn0);
            s[nt][1] = __expf(s[nt][1] - mn0);
            s[nt][2] = __expf(s[nt][2] - mn1);
            s[nt][3] = __expf(s[nt][3] - mn1);
            sum0 += s[nt][0] + s[nt][1];
            sum1 += s[nt][2] + s[nt][3];
        }
        sum0 += __shfl_xor_sync(0xffffffffu, sum0, 1);
        sum0 += __shfl_xor_sync(0xffffffffu, sum0, 2);
        sum1 += __shfl_xor_sync(0xffffffffu, sum1, 1);
        sum1 += __shfl_xor_sync(0xffffffffu, sum1, 2);
        l0 = l0 * fac0 + sum0;
        l1 = l1 * fac1 + sum1;
        m0 = mn0; m1 = mn1;
#pragma unroll
        for (int nt = 0; nt < 8; nt++) {
            accO[nt][0] *= fac0; accO[nt][1] *= fac0;
            accO[nt][2] *= fac1; accO[nt][3] *= fac1;
        }
        // store P (half) — warp-private rows
#pragma unroll
        for (int nt = 0; nt < 8; nt++) {
            *reinterpret_cast<uint32_t*>(&Ps[(wq0 + g) * HS + nt * 8 + 2 * tg]) =
                pk2(s[nt][0], s[nt][1]);
            *reinterpret_cast<uint32_t*>(&Ps[(wq0 + g + 8) * HS + nt * 8 + 2 * tg]) =
                pk2(s[nt][2], s[nt][3]);
        }
        __syncwarp();

        // ---- accO += P @ V (VT rows = dh) ----
#pragma unroll
        for (int kf = 0; kf < 4; kf++) {
            const int kk = kf * 16;
            uint32_t a[4];
            const int r = wq0 + g;
            a[0] = *reinterpret_cast<const uint32_t*>(&Ps[r * HS + kk + 2 * tg]);
            a[1] = *reinterpret_cast<const uint32_t*>(&Ps[(r + 8) * HS + kk + 2 * tg]);
            a[2] = *reinterpret_cast<const uint32_t*>(&Ps[r * HS + kk + 2 * tg + 8]);
            a[3] = *reinterpret_cast<const uint32_t*>(&Ps[(r + 8) * HS + kk + 2 * tg + 8]);
#pragma unroll
            for (int nt = 0; nt < 8; nt++) {
                const int n = nt * 8 + g;
                uint32_t b[2];
                b[0] = *reinterpret_cast<const uint32_t*>(&VTs[n * HS + kk + 2 * tg]);
                b[1] = *reinterpret_cast<const uint32_t*>(&VTs[n * HS + kk + 2 * tg + 8]);
                mma16(accO[nt], a, b);
            }
        }
        j0 = nj;
    }

    // ---- epilogue ----
    const float inv0 = 1.0f / l0;
    const float inv1 = 1.0f / l1;
#pragma unroll
    for (int nt = 0; nt < 8; nt++) {
        const int col = h * DH + nt * 8 + 2 * tg;
        float2 o0; o0.x = accO[nt][0] * inv0; o0.y = accO[nt][1] * inv0;
        float2 o1; o1.x = accO[nt][2] * inv1; o1.y = accO[nt][3] * inv1;
        *reinterpret_cast<float2*>(O + (size_t)gq0 * DIM + col) = o0;
        *reinterpret_cast<float2*>(O + (size_t)gq1 * DIM + col) = o1;
    }
}

// ---------------------------------------------------------------------------
// LayerNorm — unchanged.
// ---------------------------------------------------------------------------
__global__ void __launch_bounds__(256)
ln_kernel(const float* __restrict__ a, const float* __restrict__ g,
          const float* __restrict__ beta, float* __restrict__ out)
{
    const int row = blockIdx.x;
    const float* pa = a + (long)row * DIM;
    __shared__ float sh1[8], sh2[8];

    float v[4];
    float s = 0.0f;
#pragma unroll
    for (int i = 0; i < 4; i++) {
        v[i] = pa[threadIdx.x + i * 256];
        s += v[i];
    }
#pragma unroll
    for (int off = 16; off >= 1; off >>= 1) s += __shfl_xor_sync(0xffffffffu, s, off);
    if ((threadIdx.x & 31) == 0) sh1[threadIdx.x >> 5] = s;
    __syncthreads();
    float mu = 0.0f;
#pragma unroll
    for (int i = 0; i < 8; i++) mu += sh1[i];
    mu *= (1.0f / DIM);

    float vs = 0.0f;
#pragma unroll
    for (int i = 0; i < 4; i++) {
        float d = v[i] - mu;
        vs += d * d;
    }
#pragma unroll
    for (int off = 16; off >= 1; off >>= 1) vs += __shfl_xor_sync(0xffffffffu, vs, off);
    if ((threadIdx.x & 31) == 0) sh2[threadIdx.x >> 5] = vs;
    __syncthreads();
    float var = 0.0f;
#pragma unroll
    for (int i = 0; i < 8; i++) var += sh2[i];
    float inv = rsqrtf(var * (1.0f / DIM) + 1e-5f);

#pragma unroll
    for (int i = 0; i < 4; i++) {
        int c = threadIdx.x + i * 256;
        out[(long)row * DIM + c] = (v[i] - mu) * inv * g[c] + beta[c];
    }
}

// ---------------------------------------------------------------------------
// Launch
// ---------------------------------------------------------------------------
extern "C" void kernel_launch(void* const* d_in, const int* in_sizes, int n_in,
                              void* d_out, int out_size)
{
    const float* x     = (const float*)d_in[0];
    const float* ctx   = (const float*)d_in[1];
    const float* Wq    = (const float*)d_in[2];
    const float* bq    = (const float*)d_in[3];
    const float* Wkv   = (const float*)d_in[4];
    const float* bkv   = (const float*)d_in[5];
    const float* Wo    = (const float*)d_in[6];
    const float* bo    = (const float*)d_in[7];
    const float* ln1g  = (const float*)d_in[8];
    const float* ln1b  = (const float*)d_in[9];
    const float* W1    = (const float*)d_in[10];
    const float* bf1   = (const float*)d_in[11];
    const float* W2    = (const float*)d_in[12];
    const float* bf2   = (const float*)d_in[13];
    const float* ln2g  = (const float*)d_in[14];
    const float* ln2b  = (const float*)d_in[15];
    float* out = (float*)d_out;

    float *q, *kv, *vT, *attn, *t, *x1, *ff;
    __half *wqT, *wkvT, *woT, *w1T, *w2T;
    cudaGetSymbolAddress((void**)&q,    g_q);
    cudaGetSymbolAddress((void**)&kv,   g_kv);
    cudaGetSymbolAddress((void**)&vT,   g_vT);
    cudaGetSymbolAddress((void**)&attn, g_attn);
    cudaGetSymbolAddress((void**)&t,    g_t);
    cudaGetSymbolAddress((void**)&x1,   g_x1);
    cudaGetSymbolAddress((void**)&ff,   g_ff);
    cudaGetSymbolAddress((void**)&wqT,  g_wqT);
    cudaGetSymbolAddress((void**)&wkvT, g_wkvT);
    cudaGetSymbolAddress((void**)&woT,  g_woT);
    cudaGetSymbolAddress((void**)&w1T,  g_w1T);
    cudaGetSymbolAddress((void**)&w2T,  g_w2T);

    cudaFuncSetAttribute(attn_kernel, cudaFuncAttributeMaxDynamicSharedMemorySize, ATT_SMEM);

    // 0) transpose + fp16-convert all weights to K-major [N, K]
    transpose_h_kernel<<<dim3(DIM / 32, DIM / 32), 256>>>(Wq,  wqT,  DIM,  DIM);
    transpose_h_kernel<<<dim3(2 * DIM / 32, DIM / 32), 256>>>(Wkv, wkvT, DIM, 2 * DIM);
    transpose_h_kernel<<<dim3(DIM / 32, DIM / 32), 256>>>(Wo,  woT,  DIM,  DIM);
    transpose_h_kernel<<<dim3(DFF_ / 32, DIM / 32), 256>>>(W1,  w1T,  DIM,  DFF_);
    transpose_h_kernel<<<dim3(DIM / 32, DFF_ / 32), 256>>>(W2,  w2T,  DFF_, DIM);

    // 1) Q = x @ Wq + bq
    mma_gemm<1><<<dim3(DIM / 128, SEQ_N / 128), 256>>>(
        x, nullptr, 0, wqT, bq, nullptr, q, SEQ_N, DIM, DIM);

    // 2) KV = concat(x, ctx) @ Wkv + bkv
    mma_gemm<1><<<dim3(2 * DIM / 128, TOTK / 128), 256>>>(
        x, ctx, SEQ_N, wkvT, bkv, nullptr, kv, TOTK, 2 * DIM, DIM);

    // 2b) transpose V slice of kv -> vT[DIM][TOTK]
    transpose_f_kernel<<<dim3(DIM / 32, TOTK / 32), 256>>>(
        kv + DIM, vT, TOTK, DIM, 2 * DIM);

    // 3) attention (fp16 HMMA, 256-row q tiles)
    attn_kernel<<<dim3(SEQ_N / QROWS, HEADS), 512, ATT_SMEM>>>(q, kv, vT, attn);

    // 4) t = attn @ Wo + bo + x
    mma_gemm<3><<<dim3(DIM / 128, SEQ_N / 128), 256>>>(
        attn, nullptr, 0, woT, bo, x, t, SEQ_N, DIM, DIM);

    // 5) x1 = LN1(t)
    ln_kernel<<<SEQ_N, 256>>>(t, ln1g, ln1b, x1);

    // 6) ff = gelu(x1 @ W1 + bf1)
    mma_gemm<2><<<dim3(DFF_ / 128, SEQ_N / 128), 256>>>(
        x1, nullptr, 0, w1T, bf1, nullptr, ff, SEQ_N, DFF_, DIM);

    // 7) t = ff @ W2 + bf2 + x1
    mma_gemm<3><<<dim3(DIM / 128, SEQ_N / 128), 256>>>(
        ff, nullptr, 0, w2T, bf2, x1, t, SEQ_N, DIM, DFF_);

    // 8) out = LN2(t)
    ln_kernel<<<SEQ_N, 256>>>(t, ln2g, ln2b, out);
}

// round 8
// speedup vs baseline: 6.6269x; 1.2261x over previous
#include <cuda_runtime.h>
#include <cuda_fp16.h>
#include <math.h>
#include <stdint.h>

// R8 = R7 resubmission: R7 bench died with "GB300 container failed twice"
// (infra, same as R1). Source is unchanged.

// ---------------------------------------------------------------------------
// Problem constants
// ---------------------------------------------------------------------------
#define SEQ_N 2048
#define SEQ_M 2048
#define TOTK  (SEQ_N + SEQ_M)   // 4096
#define DIM   1024
#define HEADS 16
#define DH    64
#define DFF_  4096
#define MASK_VAL (-50000.0f)

// ---------------------------------------------------------------------------
// Scratch (device globals; no allocation allowed)
// ---------------------------------------------------------------------------
__device__ __half g_inh [TOTK * DIM];        // concat(x, ctx) in fp16
__device__ __half g_qh  [SEQ_N * DIM];       // q (pre-scaled by 1/8)
__device__ __half g_kvh [TOTK * 2 * DIM];    // K cols [0,1024), V cols [1024,2048)
__device__ __half g_vTh [DIM * TOTK];        // V^T [dh_global][seq]
__device__ __half g_attnh[SEQ_N * DIM];
__device__ __half g_x1h [SEQ_N * DIM];
__device__ __half g_ffh [SEQ_N * DFF_];
__device__ float  g_t   [SEQ_N * DIM];
__device__ float  g_x1  [SEQ_N * DIM];
// transposed fp16 weights (K-major [N,K])
__device__ __half g_wqT [DIM * DIM];
__device__ __half g_wkvT[2 * DIM * DIM];
__device__ __half g_woT [DIM * DIM];
__device__ __half g_w1T [DFF_ * DIM];
__device__ __half g_w2T [DIM * DFF_];

// ---------------------------------------------------------------------------
// Helpers
// ---------------------------------------------------------------------------
__device__ __forceinline__ uint32_t pk2(float a, float b) {
    __half2 h = __floats2half2_rn(a, b);
    return *reinterpret_cast<uint32_t*>(&h);
}
__device__ __forceinline__ void mma16(float* c, const uint32_t* a, const uint32_t* b) {
    asm volatile(
        "mma.sync.aligned.m16n8k16.row.col.f32.f16.f16.f32 "
        "{%0,%1,%2,%3}, {%4,%5,%6,%7}, {%8,%9}, {%0,%1,%2,%3};"
        : "+f"(c[0]), "+f"(c[1]), "+f"(c[2]), "+f"(c[3])
        : "r"(a[0]), "r"(a[1]), "r"(a[2]), "r"(a[3]), "r"(b[0]), "r"(b[1]));
}
__device__ __forceinline__ void ldsm4(uint32_t* r, uint32_t addr) {
    asm volatile("ldmatrix.sync.aligned.m8n8.x4.shared.b16 {%0,%1,%2,%3}, [%4];"
                 : "=r"(r[0]), "=r"(r[1]), "=r"(r[2]), "=r"(r[3]) : "r"(addr));
}
__device__ __forceinline__ void cp16(uint32_t saddr, const void* g) {
    asm volatile("cp.async.cg.shared.global [%0], [%1], 16;" :: "r"(saddr), "l"(g));
}
__device__ __forceinline__ void cp_commit() {
    asm volatile("cp.async.commit_group;" ::: "memory");
}
template <int NN>
__device__ __forceinline__ void cp_wait() {
    asm volatile("cp.async.wait_group %0;" :: "n"(NN) : "memory");
}

// ---------------------------------------------------------------------------
// convert concat(x, ctx) -> fp16 g_inh   (8 elems/thread)
// ---------------------------------------------------------------------------
__global__ void __launch_bounds__(256)
convert_h_kernel(const float* __restrict__ x, const float* __restrict__ ctx,
                 __half* __restrict__ out)
{
    const size_t i = ((size_t)blockIdx.x * 256 + threadIdx.x) * 8;
    const float* src = (i < (size_t)SEQ_N * DIM) ? x + i
                                                 : ctx + (i - (size_t)SEQ_N * DIM);
    const float4 a = *reinterpret_cast<const float4*>(src);
    const float4 b = *reinterpret_cast<const float4*>(src + 4);
    uint4 o;
    o.x = pk2(a.x, a.y); o.y = pk2(a.z, a.w);
    o.z = pk2(b.x, b.y); o.w = pk2(b.z, b.w);
    *reinterpret_cast<uint4*>(out + i) = o;
}

// ---------------------------------------------------------------------------
// Weight transpose + fp16: out[N][K] (half) = in[K][N]^T (float)
// ---------------------------------------------------------------------------
__global__ void __launch_bounds__(256)
transpose_h_kernel(const float* __restrict__ in, __half* __restrict__ out, int K, int N)
{
    __shared__ float t[32][33];
    const int bx = blockIdx.x * 32;
    const int by = blockIdx.y * 32;
    const int x = threadIdx.x & 31;
    const int y = threadIdx.x >> 5;
#pragma unroll
    for (int i = 0; i < 32; i += 8)
        t[y + i][x] = in[(size_t)(by + y + i) * N + bx + x];
    __syncthreads();
#pragma unroll
    for (int i = 0; i < 32; i += 8)
        out[(size_t)(bx + y + i) * K + by + x] = __float2half_rn(t[x][y + i]);
}

// ---------------------------------------------------------------------------
// V^T: out[c][r] = kvh[r][1024 + c]   (half), r < TOTK, c < DIM
// ---------------------------------------------------------------------------
__global__ void __launch_bounds__(256)
transpose_vh_kernel(const __half* __restrict__ in, __half* __restrict__ out)
{
    __shared__ __half t[32][33];
    const int bx = blockIdx.x * 32;   // V col (dh)
    const int by = blockIdx.y * 32;   // seq
    const int x = threadIdx.x & 31;
    const int y = threadIdx.x >> 5;
#pragma unroll
    for (int i = 0; i < 32; i += 8)
        t[y + i][x] = in[(size_t)(by + y + i) * (2 * DIM) + DIM + bx + x];
    __syncthreads();
#pragma unroll
    for (int i = 0; i < 32; i += 8)
        out[(size_t)(bx + y + i) * TOTK + by + x] = t[x][y + i];
}

// ---------------------------------------------------------------------------
// fp16 GEMM: C = Ah[M,K] @ Bt[N,K]^T (+epilogue), fp32 accum.
//   EPI 1: half out = (acc+bias)*alpha
//   EPI 2: half out = gelu(acc+bias)
//   EPI 3: float out = acc+bias+resid
// Tile 128x128, K-chunk 32, 256 thr, cp.async 3 stages, ldmatrix fragments.
// Smem row stride 40 halfs (80B) — conflict-free for cp.async & ldmatrix.
// ---------------------------------------------------------------------------
#define ABYTES 10240          // 128 rows * 80B
#define STAGE_B (2 * ABYTES)  // A + B
#define GEMM_SMEM (3 * STAGE_B)

template <int EPI>
__global__ void __launch_bounds__(256)
mma_gemm(const __half* __restrict__ Ah, const __half* __restrict__ Bt,
         const float* __restrict__ bias, const float* __restrict__ resid,
         float* __restrict__ Cf, __half* __restrict__ Ch, float alpha,
         int M, int N, int K)
{
    extern __shared__ __half smem_h[];
    const uint32_t smemU = (uint32_t)__cvta_generic_to_shared(smem_h);

    const int tid  = threadIdx.x;
    const int lane = tid & 31;
    const int wid  = tid >> 5;
    const int g    = lane >> 2;
    const int tg   = lane & 3;
    const int warp_m = wid >> 1;
    const int warp_n = wid & 1;
    const int tileM = blockIdx.y * 128;
    const int tileN = blockIdx.x * 128;

    const int NKC = K / 32;

    float acc[2][8][4];
#pragma unroll
    for (int i = 0; i < 2; i++)
#pragma unroll
        for (int j = 0; j < 8; j++)
#pragma unroll
            for (int l = 0; l < 4; l++) acc[i][j][l] = 0.0f;

    // cp.async issue: 512 16B chunks per matrix per stage, 2 per thread each
    const int crow0 = tid >> 2, cc0 = (tid & 3);
    const int crow1 = (tid + 256) >> 2, cc1 = (tid & 3);

    auto issue = [&](int chunk, int stage) {
        const uint32_t base = smemU + stage * STAGE_B;
        const size_t koff = (size_t)chunk * 32;
        cp16(base + crow0 * 80 + cc0 * 16,
             Ah + (size_t)(tileM + crow0) * K + koff + cc0 * 8);
        cp16(base + crow1 * 80 + cc1 * 16,
             Ah + (size_t)(tileM + crow1) * K + koff + cc1 * 8);
        cp16(base + ABYTES + crow0 * 80 + cc0 * 16,
             Bt + (size_t)(tileN + crow0) * K + koff + cc0 * 8);
        cp16(base + ABYTES + crow1 * 80 + cc1 * 16,
             Bt + (size_t)(tileN + crow1) * K + koff + cc1 * 8);
        cp_commit();
    };

    issue(0, 0);
    if (NKC > 1) issue(1, 1);

    // ldmatrix lane addressing (fixed per thread)
    const int arow = lane & 15;
    const int acol = (lane >> 4) * 8;
    const int brow = (lane & 7) + ((lane >> 4) & 1) * 8;
    const int bcol = ((lane >> 3) & 1) * 8;

    for (int kc = 0; kc < NKC; kc++) {
        const int s = kc % 3;
        if (kc < NKC - 1) cp_wait<1>(); else cp_wait<0>();
        __syncthreads();
        if (kc + 2 < NKC) issue(kc + 2, (kc + 2) % 3);

        const uint32_t aBase = smemU + s * STAGE_B;
        const uint32_t bBase = aBase + ABYTES;
#pragma unroll
        for (int kk = 0; kk < 32; kk += 16) {
            uint32_t af[2][4];
            uint32_t bf[4][4];
#pragma unroll
            for (int mt = 0; mt < 2; mt++)
                ldsm4(af[mt], aBase + (warp_m * 32 + mt * 16 + arow) * 80
                              + (kk + acol) * 2);
#pragma unroll
            for (int p = 0; p < 4; p++)
                ldsm4(bf[p], bBase + (warp_n * 64 + p * 16 + brow) * 80
                             + (kk + bcol) * 2);
#pragma unroll
            for (int mt = 0; mt < 2; mt++)
#pragma unroll
                for (int nt = 0; nt < 8; nt++)
                    mma16(acc[mt][nt], af[mt], &bf[nt >> 1][(nt & 1) * 2]);
        }
    }

    // ---- epilogue ----
#pragma unroll
    for (int mt = 0; mt < 2; mt++) {
        const int r0 = tileM + warp_m * 32 + mt * 16 + g;
#pragma unroll
        for (int nt = 0; nt < 8; nt++) {
            const int col = tileN + warp_n * 64 + nt * 8 + tg * 2;
            const float2 bv = *reinterpret_cast<const float2*>(bias + col);
#pragma unroll
            for (int hh = 0; hh < 2; hh++) {
                const int r = r0 + hh * 8;
                float v0 = acc[mt][nt][hh * 2 + 0] + bv.x;
                float v1 = acc[mt][nt][hh * 2 + 1] + bv.y;
                if (EPI == 1) {
                    v0 *= alpha; v1 *= alpha;
                    *reinterpret_cast<uint32_t*>(Ch + (size_t)r * N + col) = pk2(v0, v1);
                } else if (EPI == 2) {
                    v0 = 0.5f * v0 * (1.0f + erff(v0 * 0.70710678118654752f));
                    v1 = 0.5f * v1 * (1.0f + erff(v1 * 0.70710678118654752f));
                    *reinterpret_cast<uint32_t*>(Ch + (size_t)r * N + col) = pk2(v0, v1);
                } else {
                    const float2 rv = *reinterpret_cast<const float2*>(
                        resid + (size_t)r * N + col);
                    float2 o; o.x = v0 + rv.x; o.y = v1 + rv.y;
                    *reinterpret_cast<float2*>(Cf + (size_t)r * N + col) = o;
                }
            }
        }
    }
}

// ---------------------------------------------------------------------------
// Flash attention v4: all-half inputs, ldmatrix fragments.
// grid (SEQ_N/256, HEADS), 512 threads. Smem stride 72 halfs (144B).
// ---------------------------------------------------------------------------
#define QROWS 256
#define HS 72
#define AQ_QS 0
#define AQ_KS (QROWS * HS)
#define AQ_VS (AQ_KS + 64 * HS)
#define AQ_PS (AQ_VS + 64 * HS)
#define AQ_HALFS (AQ_PS + QROWS * HS)
#define ATT_SMEM (AQ_HALFS * 2)   // 92160 B

__global__ void __launch_bounds__(512)
attn_kernel(const __half* __restrict__ Qh,
            const __half* __restrict__ KVh,
            const __half* __restrict__ VTh,
            __half* __restrict__ Oh)
{
    extern __shared__ __half smh[];
    __half* Qs  = smh + AQ_QS;
    __half* Ks  = smh + AQ_KS;
    __half* VTs = smh + AQ_VS;
    __half* Ps  = smh + AQ_PS;
    const uint32_t uQs  = (uint32_t)__cvta_generic_to_shared(Qs);
    const uint32_t uKs  = (uint32_t)__cvta_generic_to_shared(Ks);
    const uint32_t uVTs = (uint32_t)__cvta_generic_to_shared(VTs);
    const uint32_t uPs  = (uint32_t)__cvta_generic_to_shared(Ps);

    const int h   = blockIdx.y;
    const int q0  = blockIdx.x * QROWS;
    const int tid = threadIdx.x;
    const int wid = tid >> 5;
    const int lane = tid & 31;
    const int g   = lane >> 2;
    const int tg  = lane & 3;
    const int wq0 = wid * 16;

    // load Q tile (half copy, already scaled)
    for (int e = tid; e < QROWS * 8; e += 512) {
        const int row = e >> 3, cc = e & 7;
        *reinterpret_cast<uint4*>(&Qs[row * HS + cc * 8]) =
            *reinterpret_cast<const uint4*>(Qh + (size_t)(q0 + row) * DIM + h * DH + cc * 8);
    }

    float m0 = -1e30f, m1 = -1e30f, l0 = 0.0f, l1 = 0.0f;
    float accO[8][4];
#pragma unroll
    for (int nt = 0; nt < 8; nt++)
#pragma unroll
        for (int i = 0; i < 4; i++) accO[nt][i] = 0.0f;

    // register prefetch tile 0 (1 uint4 per thread per matrix)
    const int prow = tid >> 3, pcc = tid & 7;
    uint4 kr, vr;
    kr = *reinterpret_cast<const uint4*>(KVh + (size_t)prow * (2 * DIM) + h * DH + pcc * 8);
    vr = *reinterpret_cast<const uint4*>(VTh + (size_t)(h * DH + prow) * TOTK + pcc * 8);

    const int gq0 = q0 + wq0 + g;
    const int gq1 = gq0 + 8;

    // ldmatrix lane addressing
    const int arow = lane & 15;
    const int acol = (lane >> 4) * 8;
    const int brow = (lane & 7) + ((lane >> 4) & 1) * 8;
    const int bcol = ((lane >> 3) & 1) * 8;

    int j0 = 0;
    while (j0 < TOTK) {
        int nj = j0 + 64;
        if (nj >= q0 + QROWS && nj < SEQ_N) nj = SEQ_N;  // causal tile skip

        __syncthreads();
        *reinterpret_cast<uint4*>(&Ks[prow * HS + pcc * 8]) = kr;
        *reinterpret_cast<uint4*>(&VTs[prow * HS + pcc * 8]) = vr;
        if (nj < TOTK) {
            kr = *reinterpret_cast<const uint4*>(
                KVh + (size_t)(nj + prow) * (2 * DIM) + h * DH + pcc * 8);
            vr = *reinterpret_cast<const uint4*>(
                VTh + (size_t)(h * DH + prow) * TOTK + nj + pcc * 8);
        }
        __syncthreads();

        // ---- S = Q @ K^T ----
        float s[8][4];
#pragma unroll
        for (int nt = 0; nt < 8; nt++)
#pragma unroll
            for (int i = 0; i < 4; i++) s[nt][i] = 0.0f;
#pragma unroll
        for (int kf = 0; kf < 4; kf++) {
            const int kk = kf * 16;
            uint32_t a[4];
            ldsm4(a, uQs + (wq0 + arow) * (HS * 2) + (kk + acol) * 2);
            uint32_t bf[4][4];
#pragma unroll
            for (int p = 0; p < 4; p++)
                ldsm4(bf[p], uKs + (p * 16 + brow) * (HS * 2) + (kk + bcol) * 2);
#pragma unroll
            for (int nt = 0; nt < 8; nt++)
                mma16(s[nt], a, &bf[nt >> 1][(nt & 1) * 2]);
        }

        // ---- causal mask ----
        if (j0 < SEQ_N) {
#pragma unroll
            for (int nt = 0; nt < 8; nt++) {
                const int gk = j0 + nt * 8 + 2 * tg;
                if (gk > gq0)     s[nt][0] = MASK_VAL;
                if (gk + 1 > gq0) s[nt][1] = MASK_VAL;
                if (gk > gq1)     s[nt][2] = MASK_VAL;
                if (gk + 1 > gq1) s[nt][3] = MASK_VAL;
            }
        }

        // ---- online softmax ----
        float mx0 = -1e30f, mx1 = -1e30f;
#pragma unroll
        for (int nt = 0; nt < 8; nt++) {
            mx0 = fmaxf(mx0, fmaxf(s[nt][0], s[nt][1]));
            mx1 = fmaxf(mx1, fmaxf(s[nt][2], s[nt][3]));
        }
        mx0 = fmaxf(mx0, __shfl_xor_sync(0xffffffffu, mx0, 1));
        mx0 = fmaxf(mx0, __shfl_xor_sync(0xffffffffu, mx0, 2));
        mx1 = fmaxf(mx1, __shfl_xor_sync(0xffffffffu, mx1, 1));
        mx1 = fmaxf(mx1, __shfl_xor_sync(0xffffffffu, mx1, 2));
        const float mn0 = fmaxf(m0, mx0);
        const float mn1 = fmaxf(m1, mx1);
        const float fac0 = __expf(m0 - mn0);
        const float fac1 = __expf(m1 - mn1);
        float sum0 = 0.0f, sum1 = 0.0f;
#pragma unroll
        for (int nt = 0; nt < 8; nt++) {
            s[nt][0] = __expf(s[nt][0] - mn0);
            s[nt][1] = __expf(s[nt][1] - mn0);
            s[nt][2] = __expf(s[nt][2] - mn1);
            s[nt][3] = __expf(s[nt][3] - mn1);
            sum0 += s[nt][0] + s[nt][1];
            sum1 += s[nt][2] + s[nt][3];
        }
        sum0 += __shfl_xor_sync(0xffffffffu, sum0, 1);
        sum0 += __shfl_xor_sync(0xffffffffu, sum0, 2);
        sum1 += __shfl_xor_sync(0xffffffffu, sum1, 1);
        sum1 += __shfl_xor_sync(0xffffffffu, sum1, 2);
        l0 = l0 * fac0 + sum0;
        l1 = l1 * fac1 + sum1;
        m0 = mn0; m1 = mn1;
#pragma unroll
        for (int nt = 0; nt < 8; nt++) {
            accO[nt][0] *= fac0; accO[nt][1] *= fac0;
            accO[nt][2] *= fac1; accO[nt][3] *= fac1;
        }
        // store P (half) — warp-private rows
#pragma unroll
        for (int nt = 0; nt < 8; nt++) {
            *reinterpret_cast<uint32_t*>(&Ps[(wq0 + g) * HS + nt * 8 + 2 * tg]) =
                pk2(s[nt][0], s[nt][1]);
            *reinterpret_cast<uint32_t*>(&Ps[(wq0 + g + 8) * HS + nt * 8 + 2 * tg]) =
                pk2(s[nt][2], s[nt][3]);
        }
        __syncwarp();

        // ---- accO += P @ V ----
#pragma unroll
        for (int kf = 0; kf < 4; kf++) {
            const int kk = kf * 16;
            uint32_t a[4];
            ldsm4(a, uPs + (wq0 + arow) * (HS * 2) + (kk + acol) * 2);
            uint32_t bf[4][4];
#pragma unroll
            for (int p = 0; p < 4; p++)
                ldsm4(bf[p], uVTs + (p * 16 + brow) * (HS * 2) + (kk + bcol) * 2);
#pragma unroll
            for (int nt = 0; nt < 8; nt++)
                mma16(accO[nt], a, &bf[nt >> 1][(nt & 1) * 2]);
        }
        j0 = nj;
    }

    // ---- epilogue (half out) ----
    const float inv0 = 1.0f / l0;
    const float inv1 = 1.0f / l1;
#pragma unroll
    for (int nt = 0; nt < 8; nt++) {
        const int col = h * DH + nt * 8 + 2 * tg;
        *reinterpret_cast<uint32_t*>(Oh + (size_t)gq0 * DIM + col) =
            pk2(accO[nt][0] * inv0, accO[nt][1] * inv0);
        *reinterpret_cast<uint32_t*>(Oh + (size_t)gq1 * DIM + col) =
            pk2(accO[nt][2] * inv1, accO[nt][3] * inv1);
    }
}

// ---------------------------------------------------------------------------
// LayerNorm: float in; float out (+ optional half out).
// ---------------------------------------------------------------------------
template <bool WH>
__global__ void __launch_bounds__(256)
ln_kernel(const float* __restrict__ a, const float* __restrict__ g,
          const float* __restrict__ beta, float* __restrict__ out,
          __half* __restrict__ outh)
{
    const int row = blockIdx.x;
    const float* pa = a + (size_t)row * DIM;
    __shared__ float sh1[8], sh2[8];

    float v[4];
    float s = 0.0f;
#pragma unroll
    for (int i = 0; i < 4; i++) {
        v[i] = pa[threadIdx.x + i * 256];
        s += v[i];
    }
#pragma unroll
    for (int off = 16; off >= 1; off >>= 1) s += __shfl_xor_sync(0xffffffffu, s, off);
    if ((threadIdx.x & 31) == 0) sh1[threadIdx.x >> 5] = s;
    __syncthreads();
    float mu = 0.0f;
#pragma unroll
    for (int i = 0; i < 8; i++) mu += sh1[i];
    mu *= (1.0f / DIM);

    float vs = 0.0f;
#pragma unroll
    for (int i = 0; i < 4; i++) {
        float d = v[i] - mu;
        vs += d * d;
    }
#pragma unroll
    for (int off = 16; off >= 1; off >>= 1) vs += __shfl_xor_sync(0xffffffffu, vs, off);
    if ((threadIdx.x & 31) == 0) sh2[threadIdx.x >> 5] = vs;
    __syncthreads();
    float var = 0.0f;
#pragma unroll
    for (int i = 0; i < 8; i++) var += sh2[i];
    float inv = rsqrtf(var * (1.0f / DIM) + 1e-5f);

#pragma unroll
    for (int i = 0; i < 4; i++) {
        int c = threadIdx.x + i * 256;
        float o = (v[i] - mu) * inv * g[c] + beta[c];
        out[(size_t)row * DIM + c] = o;
        if (WH) outh[(size_t)row * DIM + c] = __float2half_rn(o);
    }
}

// ---------------------------------------------------------------------------
// Launch
// ---------------------------------------------------------------------------
extern "C" void kernel_launch(void* const* d_in, const int* in_sizes, int n_in,
                              void* d_out, int out_size)
{
    const float* x     = (const float*)d_in[0];
    const float* ctx   = (const float*)d_in[1];
    const float* Wq    = (const float*)d_in[2];
    const float* bq    = (const float*)d_in[3];
    const float* Wkv   = (const float*)d_in[4];
    const float* bkv   = (const float*)d_in[5];
    const float* Wo    = (const float*)d_in[6];
    const float* bo    = (const float*)d_in[7];
    const float* ln1g  = (const float*)d_in[8];
    const float* ln1b  = (const float*)d_in[9];
    const float* W1    = (const float*)d_in[10];
    const float* bf1   = (const float*)d_in[11];
    const float* W2    = (const float*)d_in[12];
    const float* bf2   = (const float*)d_in[13];
    const float* ln2g  = (const float*)d_in[14];
    const float* ln2b  = (const float*)d_in[15];
    float* out = (float*)d_out;

    __half *inh, *qh, *kvh, *vTh, *attnh, *x1h, *ffh, *wqT, *wkvT, *woT, *w1T, *w2T;
    float *t, *x1;
    cudaGetSymbolAddress((void**)&inh,   g_inh);
    cudaGetSymbolAddress((void**)&qh,    g_qh);
    cudaGetSymbolAddress((void**)&kvh,   g_kvh);
    cudaGetSymbolAddress((void**)&vTh,   g_vTh);
    cudaGetSymbolAddress((void**)&attnh, g_attnh);
    cudaGetSymbolAddress((void**)&x1h,   g_x1h);
    cudaGetSymbolAddress((void**)&ffh,   g_ffh);
    cudaGetSymbolAddress((void**)&t,     g_t);
    cudaGetSymbolAddress((void**)&x1,    g_x1);
    cudaGetSymbolAddress((void**)&wqT,   g_wqT);
    cudaGetSymbolAddress((void**)&wkvT,  g_wkvT);
    cudaGetSymbolAddress((void**)&woT,   g_woT);
    cudaGetSymbolAddress((void**)&w1T,   g_w1T);
    cudaGetSymbolAddress((void**)&w2T,   g_w2T);

    cudaFuncSetAttribute(attn_kernel, cudaFuncAttributeMaxDynamicSharedMemorySize, ATT_SMEM);
    cudaFuncSetAttribute(mma_gemm<1>, cudaFuncAttributeMaxDynamicSharedMemorySize, GEMM_SMEM);
    cudaFuncSetAttribute(mma_gemm<2>, cudaFuncAttributeMaxDynamicSharedMemorySize, GEMM_SMEM);
    cudaFuncSetAttribute(mma_gemm<3>, cudaFuncAttributeMaxDynamicSharedMemorySize, GEMM_SMEM);

    // 0) prep: weights -> [N,K] fp16; activations -> fp16
    transpose_h_kernel<<<dim3(DIM / 32, DIM / 32), 256>>>(Wq,  wqT,  DIM,  DIM);
    transpose_h_kernel<<<dim3(2 * DIM / 32, DIM / 32), 256>>>(Wkv, wkvT, DIM, 2 * DIM);
    transpose_h_kernel<<<dim3(DIM / 32, DIM / 32), 256>>>(Wo,  woT,  DIM,  DIM);
    transpose_h_kernel<<<dim3(DFF_ / 32, DIM / 32), 256>>>(W1,  w1T,  DIM,  DFF_);
    transpose_h_kernel<<<dim3(DIM / 32, DFF_ / 32), 256>>>(W2,  w2T,  DFF_, DIM);
    convert_h_kernel<<<TOTK * DIM / (256 * 8), 256>>>(x, ctx, inh);

    // 1) qh = (x @ Wq + bq) * 0.125   (scale folded)
    mma_gemm<1><<<dim3(DIM / 128, SEQ_N / 128), 256, GEMM_SMEM>>>(
        inh, wqT, bq, nullptr, nullptr, qh, 0.125f, SEQ_N, DIM, DIM);

    // 2) kvh = concat(x, ctx) @ Wkv + bkv
    mma_gemm<1><<<dim3(2 * DIM / 128, TOTK / 128), 256, GEMM_SMEM>>>(
        inh, wkvT, bkv, nullptr, nullptr, kvh, 1.0f, TOTK, 2 * DIM, DIM);

    // 2b) V^T
    transpose_vh_kernel<<<dim3(DIM / 32, TOTK / 32), 256>>>(kvh, vTh);

    // 3) attention -> attnh
    attn_kernel<<<dim3(SEQ_N / QROWS, HEADS), 512, ATT_SMEM>>>(qh, kvh, vTh, attnh);

    // 4) t = attn @ Wo + bo + x
    mma_gemm<3><<<dim3(DIM / 128, SEQ_N / 128), 256, GEMM_SMEM>>>(
        attnh, woT, bo, x, t, nullptr, 1.0f, SEQ_N, DIM, DIM);

    // 5) x1 = LN1(t)  (float + half)
    ln_kernel<true><<<SEQ_N, 256>>>(t, ln1g, ln1b, x1, x1h);

    // 6) ffh = gelu(x1 @ W1 + bf1)
    mma_gemm<2><<<dim3(DFF_ / 128, SEQ_N / 128), 256, GEMM_SMEM>>>(
        x1h, w1T, bf1, nullptr, nullptr, ffh, 1.0f, SEQ_N, DFF_, DIM);

    // 7) t = ff @ W2 + bf2 + x1
    mma_gemm<3><<<dim3(DIM / 128, SEQ_N / 128), 256, GEMM_SMEM>>>(
        ffh, w2T, bf2, x1, t, nullptr, 1.0f, SEQ_N, DIM, DFF_);

    // 8) out = LN2(t)
    ln_kernel<false><<<SEQ_N, 256>>>(t, ln2g, ln2b, out, nullptr);
}

// round 9
// speedup vs baseline: 6.9007x; 1.0413x over previous
#include <cuda_runtime.h>
#include <cuda_fp16.h>
#include <math.h>
#include <stdint.h>

// ---------------------------------------------------------------------------
// Problem constants
// ---------------------------------------------------------------------------
#define SEQ_N 2048
#define SEQ_M 2048
#define TOTK  (SEQ_N + SEQ_M)   // 4096
#define DIM   1024
#define HEADS 16
#define DH    64
#define DFF_  4096
#define MASK_VAL (-50000.0f)

// ---------------------------------------------------------------------------
// Scratch (device globals; no allocation allowed)
// ---------------------------------------------------------------------------
__device__ __half g_inh [TOTK * DIM];        // concat(x, ctx) in fp16
__device__ __half g_qh  [SEQ_N * DIM];       // q (pre-scaled by log2e/8)
__device__ __half g_kvh [TOTK * 2 * DIM];    // K cols [0,1024), V cols [1024,2048)
__device__ __half g_attnh[SEQ_N * DIM];
__device__ __half g_x1h [SEQ_N * DIM];
__device__ __half g_ffh [SEQ_N * DFF_];
__device__ float  g_t   [SEQ_N * DIM];
__device__ float  g_x1  [SEQ_N * DIM];
// transposed fp16 weights (K-major [N,K])
__device__ __half g_wqT [DIM * DIM];
__device__ __half g_wkvT[2 * DIM * DIM];
__device__ __half g_woT [DIM * DIM];
__device__ __half g_w1T [DFF_ * DIM];
__device__ __half g_w2T [DIM * DFF_];

// ---------------------------------------------------------------------------
// Helpers
// ---------------------------------------------------------------------------
__device__ __forceinline__ uint32_t pk2(float a, float b) {
    __half2 h = __floats2half2_rn(a, b);
    return *reinterpret_cast<uint32_t*>(&h);
}
__device__ __forceinline__ void mma16(float* c, const uint32_t* a, const uint32_t* b) {
    asm volatile(
        "mma.sync.aligned.m16n8k16.row.col.f32.f16.f16.f32 "
        "{%0,%1,%2,%3}, {%4,%5,%6,%7}, {%8,%9}, {%0,%1,%2,%3};"
        : "+f"(c[0]), "+f"(c[1]), "+f"(c[2]), "+f"(c[3])
        : "r"(a[0]), "r"(a[1]), "r"(a[2]), "r"(a[3]), "r"(b[0]), "r"(b[1]));
}
__device__ __forceinline__ void ldsm4(uint32_t* r, uint32_t addr) {
    asm volatile("ldmatrix.sync.aligned.m8n8.x4.shared.b16 {%0,%1,%2,%3}, [%4];"
                 : "=r"(r[0]), "=r"(r[1]), "=r"(r[2]), "=r"(r[3]) : "r"(addr));
}
__device__ __forceinline__ void ldsm4t(uint32_t* r, uint32_t addr) {
    asm volatile("ldmatrix.sync.aligned.m8n8.x4.trans.shared.b16 {%0,%1,%2,%3}, [%4];"
                 : "=r"(r[0]), "=r"(r[1]), "=r"(r[2]), "=r"(r[3]) : "r"(addr));
}
__device__ __forceinline__ void cp16(uint32_t saddr, const void* g) {
    asm volatile("cp.async.cg.shared.global [%0], [%1], 16;" :: "r"(saddr), "l"(g));
}
__device__ __forceinline__ void cp_commit() {
    asm volatile("cp.async.commit_group;" ::: "memory");
}
template <int NN>
__device__ __forceinline__ void cp_wait() {
    asm volatile("cp.async.wait_group %0;" :: "n"(NN) : "memory");
}

// ---------------------------------------------------------------------------
// convert concat(x, ctx) -> fp16 g_inh   (8 elems/thread)
// ---------------------------------------------------------------------------
__global__ void __launch_bounds__(256)
convert_h_kernel(const float* __restrict__ x, const float* __restrict__ ctx,
                 __half* __restrict__ out)
{
    const size_t i = ((size_t)blockIdx.x * 256 + threadIdx.x) * 8;
    const float* src = (i < (size_t)SEQ_N * DIM) ? x + i
                                                 : ctx + (i - (size_t)SEQ_N * DIM);
    const float4 a = *reinterpret_cast<const float4*>(src);
    const float4 b = *reinterpret_cast<const float4*>(src + 4);
    uint4 o;
    o.x = pk2(a.x, a.y); o.y = pk2(a.z, a.w);
    o.z = pk2(b.x, b.y); o.w = pk2(b.z, b.w);
    *reinterpret_cast<uint4*>(out + i) = o;
}

// ---------------------------------------------------------------------------
// Weight transpose + fp16: out[N][K] (half) = in[K][N]^T (float)
// ---------------------------------------------------------------------------
__global__ void __launch_bounds__(256)
transpose_h_kernel(const float* __restrict__ in, __half* __restrict__ out, int K, int N)
{
    __shared__ float t[32][33];
    const int bx = blockIdx.x * 32;
    const int by = blockIdx.y * 32;
    const int x = threadIdx.x & 31;
    const int y = threadIdx.x >> 5;
#pragma unroll
    for (int i = 0; i < 32; i += 8)
        t[y + i][x] = in[(size_t)(by + y + i) * N + bx + x];
    __syncthreads();
#pragma unroll
    for (int i = 0; i < 32; i += 8)
        out[(size_t)(bx + y + i) * K + by + x] = __float2half_rn(t[x][y + i]);
}

// ---------------------------------------------------------------------------
// fp16 GEMM v3: C = Ah[M,K] @ Bt[N,K]^T (+epilogue), fp32 accum.
//   EPI 1: half out = (acc+bias)*alpha
//   EPI 2: half out = gelu(acc+bias)
//   EPI 3: float out = acc+bias+resid
// Tile 128x128, K-chunk 32, **128 threads (4 warps 2x2, warp tile 64x64)**,
// cp.async 3 stages, ldmatrix fragments. Smem row stride 40 halfs (80B).
// ---------------------------------------------------------------------------
#define ABYTES 10240          // 128 rows * 80B
#define STAGE_B (2 * ABYTES)  // A + B
#define GEMM_SMEM (3 * STAGE_B)

template <int EPI>
__global__ void __launch_bounds__(128)
mma_gemm(const __half* __restrict__ Ah, const __half* __restrict__ Bt,
         const float* __restrict__ bias, const float* __restrict__ resid,
         float* __restrict__ Cf, __half* __restrict__ Ch, float alpha,
         int M, int N, int K)
{
    extern __shared__ __half smem_h[];
    const uint32_t smemU = (uint32_t)__cvta_generic_to_shared(smem_h);

    const int tid  = threadIdx.x;
    const int lane = tid & 31;
    const int wid  = tid >> 5;
    const int g    = lane >> 2;
    const int tg   = lane & 3;
    const int warp_m = wid >> 1;   // 0..1
    const int warp_n = wid & 1;    // 0..1
    const int tileM = blockIdx.y * 128;
    const int tileN = blockIdx.x * 128;

    const int NKC = K / 32;

    float acc[4][8][4];
#pragma unroll
    for (int i = 0; i < 4; i++)
#pragma unroll
        for (int j = 0; j < 8; j++)
#pragma unroll
            for (int l = 0; l < 4; l++) acc[i][j][l] = 0.0f;

    // cp.async: per stage 512 16B chunks per matrix; 128 threads x 4 rows each
    const int crow = tid >> 2;    // 0..31
    const int cq   = tid & 3;     // quad within 64B row

    auto issue = [&](int chunk, int stage) {
        const uint32_t base = smemU + stage * STAGE_B;
        const size_t koff = (size_t)chunk * 32 + cq * 8;
#pragma unroll
        for (int rr = 0; rr < 4; rr++) {
            const int row = crow + rr * 32;
            cp16(base + row * 80 + cq * 16,
                 Ah + (size_t)(tileM + row) * K + koff);
            cp16(base + ABYTES + row * 80 + cq * 16,
                 Bt + (size_t)(tileN + row) * K + koff);
        }
        cp_commit();
    };

    issue(0, 0);
    if (NKC > 1) issue(1, 1);

    // ldmatrix lane addressing (fixed per thread)
    const int arow = lane & 15;
    const int acol = (lane >> 4) * 8;
    const int brow = (lane & 7) + ((lane >> 4) & 1) * 8;
    const int bcol = ((lane >> 3) & 1) * 8;

    for (int kc = 0; kc < NKC; kc++) {
        const int s = kc % 3;
        if (kc < NKC - 1) cp_wait<1>(); else cp_wait<0>();
        __syncthreads();
        if (kc + 2 < NKC) issue(kc + 2, (kc + 2) % 3);

        const uint32_t aBase = smemU + s * STAGE_B;
        const uint32_t bBase = aBase + ABYTES;
#pragma unroll
        for (int kk = 0; kk < 32; kk += 16) {
            uint32_t af[4][4];
            uint32_t bf[4][4];
#pragma unroll
            for (int mt = 0; mt < 4; mt++)
                ldsm4(af[mt], aBase + (warp_m * 64 + mt * 16 + arow) * 80
                              + (kk + acol) * 2);
#pragma unroll
            for (int p = 0; p < 4; p++)
                ldsm4(bf[p], bBase + (warp_n * 64 + p * 16 + brow) * 80
                             + (kk + bcol) * 2);
#pragma unroll
            for (int mt = 0; mt < 4; mt++)
#pragma unroll
                for (int nt = 0; nt < 8; nt++)
                    mma16(acc[mt][nt], af[mt], &bf[nt >> 1][(nt & 1) * 2]);
        }
    }

    // ---- epilogue ----
#pragma unroll
    for (int mt = 0; mt < 4; mt++) {
        const int r0 = tileM + warp_m * 64 + mt * 16 + g;
#pragma unroll
        for (int nt = 0; nt < 8; nt++) {
            const int col = tileN + warp_n * 64 + nt * 8 + tg * 2;
            const float2 bv = *reinterpret_cast<const float2*>(bias + col);
#pragma unroll
            for (int hh = 0; hh < 2; hh++) {
                const int r = r0 + hh * 8;
                float v0 = acc[mt][nt][hh * 2 + 0] + bv.x;
                float v1 = acc[mt][nt][hh * 2 + 1] + bv.y;
                if (EPI == 1) {
                    v0 *= alpha; v1 *= alpha;
                    *reinterpret_cast<uint32_t*>(Ch + (size_t)r * N + col) = pk2(v0, v1);
                } else if (EPI == 2) {
                    v0 = 0.5f * v0 * (1.0f + erff(v0 * 0.70710678118654752f));
                    v1 = 0.5f * v1 * (1.0f + erff(v1 * 0.70710678118654752f));
                    *reinterpret_cast<uint32_t*>(Ch + (size_t)r * N + col) = pk2(v0, v1);
                } else {
                    const float2 rv = *reinterpret_cast<const float2*>(
                        resid + (size_t)r * N + col);
                    float2 o; o.x = v0 + rv.x; o.y = v1 + rv.y;
                    *reinterpret_cast<float2*>(Cf + (size_t)r * N + col) = o;
                }
            }
        }
    }
}

// ---------------------------------------------------------------------------
// Flash attention v5: V row-major via ldmatrix.trans (no V^T in gmem),
// exp2-domain softmax (log2e folded into Q scale).
// grid (SEQ_N/256, HEADS), 512 threads. Smem stride 72 halfs (144B).
// ---------------------------------------------------------------------------
#define QROWS 256
#define HS 72
#define AQ_QS 0
#define AQ_KS (QROWS * HS)
#define AQ_VS (AQ_KS + 64 * HS)
#define AQ_PS (AQ_VS + 64 * HS)
#define AQ_HALFS (AQ_PS + QROWS * HS)
#define ATT_SMEM (AQ_HALFS * 2)   // 92160 B

__global__ void __launch_bounds__(512)
attn_kernel(const __half* __restrict__ Qh,
            const __half* __restrict__ KVh,
            __half* __restrict__ Oh)
{
    extern __shared__ __half smh[];
    __half* Qs = smh + AQ_QS;
    __half* Ks = smh + AQ_KS;
    __half* Vs = smh + AQ_VS;   // [64 seq rows][64 dh], row-major like Ks
    __half* Ps = smh + AQ_PS;
    const uint32_t uQs = (uint32_t)__cvta_generic_to_shared(Qs);
    const uint32_t uKs = (uint32_t)__cvta_generic_to_shared(Ks);
    const uint32_t uVs = (uint32_t)__cvta_generic_to_shared(Vs);
    const uint32_t uPs = (uint32_t)__cvta_generic_to_shared(Ps);

    const int h   = blockIdx.y;
    const int q0  = blockIdx.x * QROWS;
    const int tid = threadIdx.x;
    const int wid = tid >> 5;
    const int lane = tid & 31;
    const int g   = lane >> 2;
    const int tg  = lane & 3;
    const int wq0 = wid * 16;

    // load Q tile (half copy; scale incl. log2e already folded)
    for (int e = tid; e < QROWS * 8; e += 512) {
        const int row = e >> 3, cc = e & 7;
        *reinterpret_cast<uint4*>(&Qs[row * HS + cc * 8]) =
            *reinterpret_cast<const uint4*>(Qh + (size_t)(q0 + row) * DIM + h * DH + cc * 8);
    }

    float m0 = -1e30f, m1 = -1e30f, l0 = 0.0f, l1 = 0.0f;
    float accO[8][4];
#pragma unroll
    for (int nt = 0; nt < 8; nt++)
#pragma unroll
        for (int i = 0; i < 4; i++) accO[nt][i] = 0.0f;

    // register prefetch tile 0 (K and V both row-major from KVh)
    const int prow = tid >> 3, pcc = tid & 7;
    uint4 kr, vr;
    kr = *reinterpret_cast<const uint4*>(KVh + (size_t)prow * (2 * DIM) + h * DH + pcc * 8);
    vr = *reinterpret_cast<const uint4*>(KVh + (size_t)prow * (2 * DIM) + DIM + h * DH + pcc * 8);

    const int gq0 = q0 + wq0 + g;
    const int gq1 = gq0 + 8;

    // ldmatrix lane addressing
    const int arow = lane & 15;
    const int acol = (lane >> 4) * 8;
    const int brow = (lane & 7) + ((lane >> 4) & 1) * 8;
    const int bcol = ((lane >> 3) & 1) * 8;
    // trans-ldsm addressing for V (k rows in storage, n cols)
    const int vkrow = (lane & 7) + ((lane >> 3) & 1) * 8;
    const int vncol = ((lane >> 4) & 1) * 8;

    int j0 = 0;
    while (j0 < TOTK) {
        int nj = j0 + 64;
        if (nj >= q0 + QROWS && nj < SEQ_N) nj = SEQ_N;  // causal tile skip

        __syncthreads();
        *reinterpret_cast<uint4*>(&Ks[prow * HS + pcc * 8]) = kr;
        *reinterpret_cast<uint4*>(&Vs[prow * HS + pcc * 8]) = vr;
        if (nj < TOTK) {
            kr = *reinterpret_cast<const uint4*>(
                KVh + (size_t)(nj + prow) * (2 * DIM) + h * DH + pcc * 8);
            vr = *reinterpret_cast<const uint4*>(
                KVh + (size_t)(nj + prow) * (2 * DIM) + DIM + h * DH + pcc * 8);
        }
        __syncthreads();

        // ---- S = Q @ K^T (log2 domain) ----
        float s[8][4];
#pragma unroll
        for (int nt = 0; nt < 8; nt++)
#pragma unroll
            for (int i = 0; i < 4; i++) s[nt][i] = 0.0f;
#pragma unroll
        for (int kf = 0; kf < 4; kf++) {
            const int kk = kf * 16;
            uint32_t a[4];
            ldsm4(a, uQs + (wq0 + arow) * (HS * 2) + (kk + acol) * 2);
            uint32_t bf[4][4];
#pragma unroll
            for (int p = 0; p < 4; p++)
                ldsm4(bf[p], uKs + (p * 16 + brow) * (HS * 2) + (kk + bcol) * 2);
#pragma unroll
            for (int nt = 0; nt < 8; nt++)
                mma16(s[nt], a, &bf[nt >> 1][(nt & 1) * 2]);
        }

        // ---- causal mask ----
        if (j0 < SEQ_N) {
#pragma unroll
            for (int nt = 0; nt < 8; nt++) {
                const int gk = j0 + nt * 8 + 2 * tg;
                if (gk > gq0)     s[nt][0] = MASK_VAL;
                if (gk + 1 > gq0) s[nt][1] = MASK_VAL;
                if (gk > gq1)     s[nt][2] = MASK_VAL;
                if (gk + 1 > gq1) s[nt][3] = MASK_VAL;
            }
        }

        // ---- online softmax (base-2) ----
        float mx0 = -1e30f, mx1 = -1e30f;
#pragma unroll
        for (int nt = 0; nt < 8; nt++) {
            mx0 = fmaxf(mx0, fmaxf(s[nt][0], s[nt][1]));
            mx1 = fmaxf(mx1, fmaxf(s[nt][2], s[nt][3]));
        }
        mx0 = fmaxf(mx0, __shfl_xor_sync(0xffffffffu, mx0, 1));
        mx0 = fmaxf(mx0, __shfl_xor_sync(0xffffffffu, mx0, 2));
        mx1 = fmaxf(mx1, __shfl_xor_sync(0xffffffffu, mx1, 1));
        mx1 = fmaxf(mx1, __shfl_xor_sync(0xffffffffu, mx1, 2));
        const float mn0 = fmaxf(m0, mx0);
        const float mn1 = fmaxf(m1, mx1);
        const float fac0 = exp2f(m0 - mn0);
        const float fac1 = exp2f(m1 - mn1);
        float sum0 = 0.0f, sum1 = 0.0f;
#pragma unroll
        for (int nt = 0; nt < 8; nt++) {
            s[nt][0] = exp2f(s[nt][0] - mn0);
            s[nt][1] = exp2f(s[nt][1] - mn0);
            s[nt][2] = exp2f(s[nt][2] - mn1);
            s[nt][3] = exp2f(s[nt][3] - mn1);
            sum0 += s[nt][0] + s[nt][1];
            sum1 += s[nt][2] + s[nt][3];
        }
        sum0 += __shfl_xor_sync(0xffffffffu, sum0, 1);
        sum0 += __shfl_xor_sync(0xffffffffu, sum0, 2);
        sum1 += __shfl_xor_sync(0xffffffffu, sum1, 1);
        sum1 += __shfl_xor_sync(0xffffffffu, sum1, 2);
        l0 = l0 * fac0 + sum0;
        l1 = l1 * fac1 + sum1;
        m0 = mn0; m1 = mn1;
#pragma unroll
        for (int nt = 0; nt < 8; nt++) {
            accO[nt][0] *= fac0; accO[nt][1] *= fac0;
            accO[nt][2] *= fac1; accO[nt][3] *= fac1;
        }
        // store P (half) — warp-private rows
#pragma unroll
        for (int nt = 0; nt < 8; nt++) {
            *reinterpret_cast<uint32_t*>(&Ps[(wq0 + g) * HS + nt * 8 + 2 * tg]) =
                pk2(s[nt][0], s[nt][1]);
            *reinterpret_cast<uint32_t*>(&Ps[(wq0 + g + 8) * HS + nt * 8 + 2 * tg]) =
                pk2(s[nt][2], s[nt][3]);
        }
        __syncwarp();

        // ---- accO += P @ V  (V row-major [seq][dh] -> trans ldsm) ----
#pragma unroll
        for (int kf = 0; kf < 4; kf++) {
            const int kk = kf * 16;
            uint32_t a[4];
            ldsm4(a, uPs + (wq0 + arow) * (HS * 2) + (kk + acol) * 2);
            uint32_t bf[4][4];
#pragma unroll
            for (int p = 0; p < 4; p++)
                ldsm4t(bf[p], uVs + (kk + vkrow) * (HS * 2) + (p * 16 + vncol) * 2);
#pragma unroll
            for (int nt = 0; nt < 8; nt++)
                mma16(accO[nt], a, &bf[nt >> 1][(nt & 1) * 2]);
        }
        j0 = nj;
    }

    // ---- epilogue (half out) ----
    const float inv0 = 1.0f / l0;
    const float inv1 = 1.0f / l1;
#pragma unroll
    for (int nt = 0; nt < 8; nt++) {
        const int col = h * DH + nt * 8 + 2 * tg;
        *reinterpret_cast<uint32_t*>(Oh + (size_t)gq0 * DIM + col) =
            pk2(accO[nt][0] * inv0, accO[nt][1] * inv0);
        *reinterpret_cast<uint32_t*>(Oh + (size_t)gq1 * DIM + col) =
            pk2(accO[nt][2] * inv1, accO[nt][3] * inv1);
    }
}

// ---------------------------------------------------------------------------
// LayerNorm: float in; float out (+ optional half out).
// ---------------------------------------------------------------------------
template <bool WH>
__global__ void __launch_bounds__(256)
ln_kernel(const float* __restrict__ a, const float* __restrict__ g,
          const float* __restrict__ beta, float* __restrict__ out,
          __half* __restrict__ outh)
{
    const int row = blockIdx.x;
    const float* pa = a + (size_t)row * DIM;
    __shared__ float sh1[8], sh2[8];

    float v[4];
    float s = 0.0f;
#pragma unroll
    for (int i = 0; i < 4; i++) {
        v[i] = pa[threadIdx.x + i * 256];
        s += v[i];
    }
#pragma unroll
    for (int off = 16; off >= 1; off >>= 1) s += __shfl_xor_sync(0xffffffffu, s, off);
    if ((threadIdx.x & 31) == 0) sh1[threadIdx.x >> 5] = s;
    __syncthreads();
    float mu = 0.0f;
#pragma unroll
    for (int i = 0; i < 8; i++) mu += sh1[i];
    mu *= (1.0f / DIM);

    float vs = 0.0f;
#pragma unroll
    for (int i = 0; i < 4; i++) {
        float d = v[i] - mu;
        vs += d * d;
    }
#pragma unroll
    for (int off = 16; off >= 1; off >>= 1) vs += __shfl_xor_sync(0xffffffffu, vs, off);
    if ((threadIdx.x & 31) == 0) sh2[threadIdx.x >> 5] = vs;
    __syncthreads();
    float var = 0.0f;
#pragma unroll
    for (int i = 0; i < 8; i++) var += sh2[i];
    float inv = rsqrtf(var * (1.0f / DIM) + 1e-5f);

#pragma unroll
    for (int i = 0; i < 4; i++) {
        int c = threadIdx.x + i * 256;
        float o = (v[i] - mu) * inv * g[c] + beta[c];
        out[(size_t)row * DIM + c] = o;
        if (WH) outh[(size_t)row * DIM + c] = __float2half_rn(o);
    }
}

// ---------------------------------------------------------------------------
// Launch
// ---------------------------------------------------------------------------
extern "C" void kernel_launch(void* const* d_in, const int* in_sizes, int n_in,
                              void* d_out, int out_size)
{
    const float* x     = (const float*)d_in[0];
    const float* ctx   = (const float*)d_in[1];
    const float* Wq    = (const float*)d_in[2];
    const float* bq    = (const float*)d_in[3];
    const float* Wkv   = (const float*)d_in[4];
    const float* bkv   = (const float*)d_in[5];
    const float* Wo    = (const float*)d_in[6];
    const float* bo    = (const float*)d_in[7];
    const float* ln1g  = (const float*)d_in[8];
    const float* ln1b  = (const float*)d_in[9];
    const float* W1    = (const float*)d_in[10];
    const float* bf1   = (const float*)d_in[11];
    const float* W2    = (const float*)d_in[12];
    const float* bf2   = (const float*)d_in[13];
    const float* ln2g  = (const float*)d_in[14];
    const float* ln2b  = (const float*)d_in[15];
    float* out = (float*)d_out;

    __half *inh, *qh, *kvh, *attnh, *x1h, *ffh, *wqT, *wkvT, *woT, *w1T, *w2T;
    float *t, *x1;
    cudaGetSymbolAddress((void**)&inh,   g_inh);
    cudaGetSymbolAddress((void**)&qh,    g_qh);
    cudaGetSymbolAddress((void**)&kvh,   g_kvh);
    cudaGetSymbolAddress((void**)&attnh, g_attnh);
    cudaGetSymbolAddress((void**)&x1h,   g_x1h);
    cudaGetSymbolAddress((void**)&ffh,   g_ffh);
    cudaGetSymbolAddress((void**)&t,     g_t);
    cudaGetSymbolAddress((void**)&x1,    g_x1);
    cudaGetSymbolAddress((void**)&wqT,   g_wqT);
    cudaGetSymbolAddress((void**)&wkvT,  g_wkvT);
    cudaGetSymbolAddress((void**)&woT,   g_woT);
    cudaGetSymbolAddress((void**)&w1T,   g_w1T);
    cudaGetSymbolAddress((void**)&w2T,   g_w2T);

    cudaFuncSetAttribute(attn_kernel, cudaFuncAttributeMaxDynamicSharedMemorySize, ATT_SMEM);
    cudaFuncSetAttribute(mma_gemm<1>, cudaFuncAttributeMaxDynamicSharedMemorySize, GEMM_SMEM);
    cudaFuncSetAttribute(mma_gemm<2>, cudaFuncAttributeMaxDynamicSharedMemorySize, GEMM_SMEM);
    cudaFuncSetAttribute(mma_gemm<3>, cudaFuncAttributeMaxDynamicSharedMemorySize, GEMM_SMEM);

    // 0) prep: weights -> [N,K] fp16; activations -> fp16
    transpose_h_kernel<<<dim3(DIM / 32, DIM / 32), 256>>>(Wq,  wqT,  DIM,  DIM);
    transpose_h_kernel<<<dim3(2 * DIM / 32, DIM / 32), 256>>>(Wkv, wkvT, DIM, 2 * DIM);
    transpose_h_kernel<<<dim3(DIM / 32, DIM / 32), 256>>>(Wo,  woT,  DIM,  DIM);
    transpose_h_kernel<<<dim3(DFF_ / 32, DIM / 32), 256>>>(W1,  w1T,  DIM,  DFF_);
    transpose_h_kernel<<<dim3(DIM / 32, DFF_ / 32), 256>>>(W2,  w2T,  DFF_, DIM);
    convert_h_kernel<<<TOTK * DIM / (256 * 8), 256>>>(x, ctx, inh);

    // 1) qh = (x @ Wq + bq) * (log2e / 8)   (softmax scale + base-2 fold)
    mma_gemm<1><<<dim3(DIM / 128, SEQ_N / 128), 128, GEMM_SMEM>>>(
        inh, wqT, bq, nullptr, nullptr, qh, 0.18033688011112042f, SEQ_N, DIM, DIM);

    // 2) kvh = concat(x, ctx) @ Wkv + bkv
    mma_gemm<1><<<dim3(2 * DIM / 128, TOTK / 128), 128, GEMM_SMEM>>>(
        inh, wkvT, bkv, nullptr, nullptr, kvh, 1.0f, TOTK, 2 * DIM, DIM);

    // 3) attention -> attnh   (V read in-place, no transpose kernel)
    attn_kernel<<<dim3(SEQ_N / QROWS, HEADS), 512, ATT_SMEM>>>(qh, kvh, attnh);

    // 4) t = attn @ Wo + bo + x
    mma_gemm<3><<<dim3(DIM / 128, SEQ_N / 128), 128, GEMM_SMEM>>>(
        attnh, woT, bo, x, t, nullptr, 1.0f, SEQ_N, DIM, DIM);

    // 5) x1 = LN1(t)  (float + half)
    ln_kernel<true><<<SEQ_N, 256>>>(t, ln1g, ln1b, x1, x1h);

    // 6) ffh = gelu(x1 @ W1 + bf1)
    mma_gemm<2><<<dim3(DFF_ / 128, SEQ_N / 128), 128, GEMM_SMEM>>>(
        x1h, w1T, bf1, nullptr, nullptr, ffh, 1.0f, SEQ_N, DFF_, DIM);

    // 7) t = ff @ W2 + bf2 + x1
    mma_gemm<3><<<dim3(DIM / 128, SEQ_N / 128), 128, GEMM_SMEM>>>(
        ffh, w2T, bf2, x1, t, nullptr, 1.0f, SEQ_N, DIM, DFF_);

    // 8) out = LN2(t)
    ln_kernel<false><<<SEQ_N, 256>>>(t, ln2g, ln2b, out, nullptr);
}

// round 10
// speedup vs baseline: 7.0024x; 1.0147x over previous
#include <cuda_runtime.h>
#include <cuda_fp16.h>
#include <math.h>
#include <stdint.h>

// R10: same compute kernels as R9 (GEMM at legacy-HMMA throughput wall).
// Change: stream fork/join to overlap weight transposes (memory-bound) with
// GEMMs/attention (tensor-bound); LN vectorized.

// ---------------------------------------------------------------------------
// Problem constants
// ---------------------------------------------------------------------------
#define SEQ_N 2048
#define SEQ_M 2048
#define TOTK  (SEQ_N + SEQ_M)   // 4096
#define DIM   1024
#define HEADS 16
#define DH    64
#define DFF_  4096
#define MASK_VAL (-50000.0f)

// ---------------------------------------------------------------------------
// Scratch (device globals; no allocation allowed)
// ---------------------------------------------------------------------------
__device__ __half g_inh [TOTK * DIM];        // concat(x, ctx) in fp16
__device__ __half g_qh  [SEQ_N * DIM];       // q (pre-scaled by log2e/8)
__device__ __half g_kvh [TOTK * 2 * DIM];    // K cols [0,1024), V cols [1024,2048)
__device__ __half g_attnh[SEQ_N * DIM];
__device__ __half g_x1h [SEQ_N * DIM];
__device__ __half g_ffh [SEQ_N * DFF_];
__device__ float  g_t   [SEQ_N * DIM];
__device__ float  g_x1  [SEQ_N * DIM];
// transposed fp16 weights (K-major [N,K])
__device__ __half g_wqT [DIM * DIM];
__device__ __half g_wkvT[2 * DIM * DIM];
__device__ __half g_woT [DIM * DIM];
__device__ __half g_w1T [DFF_ * DIM];
__device__ __half g_w2T [DIM * DFF_];

// ---------------------------------------------------------------------------
// Helpers
// ---------------------------------------------------------------------------
__device__ __forceinline__ uint32_t pk2(float a, float b) {
    __half2 h = __floats2half2_rn(a, b);
    return *reinterpret_cast<uint32_t*>(&h);
}
__device__ __forceinline__ void mma16(float* c, const uint32_t* a, const uint32_t* b) {
    asm volatile(
        "mma.sync.aligned.m16n8k16.row.col.f32.f16.f16.f32 "
        "{%0,%1,%2,%3}, {%4,%5,%6,%7}, {%8,%9}, {%0,%1,%2,%3};"
        : "+f"(c[0]), "+f"(c[1]), "+f"(c[2]), "+f"(c[3])
        : "r"(a[0]), "r"(a[1]), "r"(a[2]), "r"(a[3]), "r"(b[0]), "r"(b[1]));
}
__device__ __forceinline__ void ldsm4(uint32_t* r, uint32_t addr) {
    asm volatile("ldmatrix.sync.aligned.m8n8.x4.shared.b16 {%0,%1,%2,%3}, [%4];"
                 : "=r"(r[0]), "=r"(r[1]), "=r"(r[2]), "=r"(r[3]) : "r"(addr));
}
__device__ __forceinline__ void ldsm4t(uint32_t* r, uint32_t addr) {
    asm volatile("ldmatrix.sync.aligned.m8n8.x4.trans.shared.b16 {%0,%1,%2,%3}, [%4];"
                 : "=r"(r[0]), "=r"(r[1]), "=r"(r[2]), "=r"(r[3]) : "r"(addr));
}
__device__ __forceinline__ void cp16(uint32_t saddr, const void* g) {
    asm volatile("cp.async.cg.shared.global [%0], [%1], 16;" :: "r"(saddr), "l"(g));
}
__device__ __forceinline__ void cp_commit() {
    asm volatile("cp.async.commit_group;" ::: "memory");
}
template <int NN>
__device__ __forceinline__ void cp_wait() {
    asm volatile("cp.async.wait_group %0;" :: "n"(NN) : "memory");
}

// ---------------------------------------------------------------------------
// convert concat(x, ctx) -> fp16 g_inh   (8 elems/thread)
// ---------------------------------------------------------------------------
__global__ void __launch_bounds__(256)
convert_h_kernel(const float* __restrict__ x, const float* __restrict__ ctx,
                 __half* __restrict__ out)
{
    const size_t i = ((size_t)blockIdx.x * 256 + threadIdx.x) * 8;
    const float* src = (i < (size_t)SEQ_N * DIM) ? x + i
                                                 : ctx + (i - (size_t)SEQ_N * DIM);
    const float4 a = *reinterpret_cast<const float4*>(src);
    const float4 b = *reinterpret_cast<const float4*>(src + 4);
    uint4 o;
    o.x = pk2(a.x, a.y); o.y = pk2(a.z, a.w);
    o.z = pk2(b.x, b.y); o.w = pk2(b.z, b.w);
    *reinterpret_cast<uint4*>(out + i) = o;
}

// ---------------------------------------------------------------------------
// Weight transpose + fp16: out[N][K] (half) = in[K][N]^T (float)
// ---------------------------------------------------------------------------
__global__ void __launch_bounds__(256)
transpose_h_kernel(const float* __restrict__ in, __half* __restrict__ out, int K, int N)
{
    __shared__ float t[32][33];
    const int bx = blockIdx.x * 32;
    const int by = blockIdx.y * 32;
    const int x = threadIdx.x & 31;
    const int y = threadIdx.x >> 5;
#pragma unroll
    for (int i = 0; i < 32; i += 8)
        t[y + i][x] = in[(size_t)(by + y + i) * N + bx + x];
    __syncthreads();
#pragma unroll
    for (int i = 0; i < 32; i += 8)
        out[(size_t)(bx + y + i) * K + by + x] = __float2half_rn(t[x][y + i]);
}

// ---------------------------------------------------------------------------
// fp16 GEMM v3: C = Ah[M,K] @ Bt[N,K]^T (+epilogue), fp32 accum.
//   EPI 1: half out = (acc+bias)*alpha
//   EPI 2: half out = gelu(acc+bias)
//   EPI 3: float out = acc+bias+resid
// Tile 128x128, K-chunk 32, 128 threads (4 warps 2x2, warp tile 64x64),
// cp.async 3 stages, ldmatrix fragments. Smem row stride 40 halfs (80B).
// ---------------------------------------------------------------------------
#define ABYTES 10240          // 128 rows * 80B
#define STAGE_B (2 * ABYTES)  // A + B
#define GEMM_SMEM (3 * STAGE_B)

template <int EPI>
__global__ void __launch_bounds__(128)
mma_gemm(const __half* __restrict__ Ah, const __half* __restrict__ Bt,
         const float* __restrict__ bias, const float* __restrict__ resid,
         float* __restrict__ Cf, __half* __restrict__ Ch, float alpha,
         int M, int N, int K)
{
    extern __shared__ __half smem_h[];
    const uint32_t smemU = (uint32_t)__cvta_generic_to_shared(smem_h);

    const int tid  = threadIdx.x;
    const int lane = tid & 31;
    const int wid  = tid >> 5;
    const int g    = lane >> 2;
    const int tg   = lane & 3;
    const int warp_m = wid >> 1;   // 0..1
    const int warp_n = wid & 1;    // 0..1
    const int tileM = blockIdx.y * 128;
    const int tileN = blockIdx.x * 128;

    const int NKC = K / 32;

    float acc[4][8][4];
#pragma unroll
    for (int i = 0; i < 4; i++)
#pragma unroll
        for (int j = 0; j < 8; j++)
#pragma unroll
            for (int l = 0; l < 4; l++) acc[i][j][l] = 0.0f;

    // cp.async: per stage 512 16B chunks per matrix; 128 threads x 4 rows each
    const int crow = tid >> 2;    // 0..31
    const int cq   = tid & 3;     // quad within 64B row

    auto issue = [&](int chunk, int stage) {
        const uint32_t base = smemU + stage * STAGE_B;
        const size_t koff = (size_t)chunk * 32 + cq * 8;
#pragma unroll
        for (int rr = 0; rr < 4; rr++) {
            const int row = crow + rr * 32;
            cp16(base + row * 80 + cq * 16,
                 Ah + (size_t)(tileM + row) * K + koff);
            cp16(base + ABYTES + row * 80 + cq * 16,
                 Bt + (size_t)(tileN + row) * K + koff);
        }
        cp_commit();
    };

    issue(0, 0);
    if (NKC > 1) issue(1, 1);

    // ldmatrix lane addressing (fixed per thread)
    const int arow = lane & 15;
    const int acol = (lane >> 4) * 8;
    const int brow = (lane & 7) + ((lane >> 4) & 1) * 8;
    const int bcol = ((lane >> 3) & 1) * 8;

    for (int kc = 0; kc < NKC; kc++) {
        const int s = kc % 3;
        if (kc < NKC - 1) cp_wait<1>(); else cp_wait<0>();
        __syncthreads();
        if (kc + 2 < NKC) issue(kc + 2, (kc + 2) % 3);

        const uint32_t aBase = smemU + s * STAGE_B;
        const uint32_t bBase = aBase + ABYTES;
#pragma unroll
        for (int kk = 0; kk < 32; kk += 16) {
            uint32_t af[4][4];
            uint32_t bf[4][4];
#pragma unroll
            for (int mt = 0; mt < 4; mt++)
                ldsm4(af[mt], aBase + (warp_m * 64 + mt * 16 + arow) * 80
                              + (kk + acol) * 2);
#pragma unroll
            for (int p = 0; p < 4; p++)
                ldsm4(bf[p], bBase + (warp_n * 64 + p * 16 + brow) * 80
                             + (kk + bcol) * 2);
#pragma unroll
            for (int mt = 0; mt < 4; mt++)
#pragma unroll
                for (int nt = 0; nt < 8; nt++)
                    mma16(acc[mt][nt], af[mt], &bf[nt >> 1][(nt & 1) * 2]);
        }
    }

    // ---- epilogue ----
#pragma unroll
    for (int mt = 0; mt < 4; mt++) {
        const int r0 = tileM + warp_m * 64 + mt * 16 + g;
#pragma unroll
        for (int nt = 0; nt < 8; nt++) {
            const int col = tileN + warp_n * 64 + nt * 8 + tg * 2;
            const float2 bv = *reinterpret_cast<const float2*>(bias + col);
#pragma unroll
            for (int hh = 0; hh < 2; hh++) {
                const int r = r0 + hh * 8;
                float v0 = acc[mt][nt][hh * 2 + 0] + bv.x;
                float v1 = acc[mt][nt][hh * 2 + 1] + bv.y;
                if (EPI == 1) {
                    v0 *= alpha; v1 *= alpha;
                    *reinterpret_cast<uint32_t*>(Ch + (size_t)r * N + col) = pk2(v0, v1);
                } else if (EPI == 2) {
                    v0 = 0.5f * v0 * (1.0f + erff(v0 * 0.70710678118654752f));
                    v1 = 0.5f * v1 * (1.0f + erff(v1 * 0.70710678118654752f));
                    *reinterpret_cast<uint32_t*>(Ch + (size_t)r * N + col) = pk2(v0, v1);
                } else {
                    const float2 rv = *reinterpret_cast<const float2*>(
                        resid + (size_t)r * N + col);
                    float2 o; o.x = v0 + rv.x; o.y = v1 + rv.y;
                    *reinterpret_cast<float2*>(Cf + (size_t)r * N + col) = o;
                }
            }
        }
    }
}

// ---------------------------------------------------------------------------
// Flash attention v5: V row-major via ldmatrix.trans, exp2-domain softmax.
// grid (SEQ_N/256, HEADS), 512 threads. Smem stride 72 halfs (144B).
// ---------------------------------------------------------------------------
#define QROWS 256
#define HS 72
#define AQ_QS 0
#define AQ_KS (QROWS * HS)
#define AQ_VS (AQ_KS + 64 * HS)
#define AQ_PS (AQ_VS + 64 * HS)
#define AQ_HALFS (AQ_PS + QROWS * HS)
#define ATT_SMEM (AQ_HALFS * 2)   // 92160 B

__global__ void __launch_bounds__(512)
attn_kernel(const __half* __restrict__ Qh,
            const __half* __restrict__ KVh,
            __half* __restrict__ Oh)
{
    extern __shared__ __half smh[];
    __half* Qs = smh + AQ_QS;
    __half* Ks = smh + AQ_KS;
    __half* Vs = smh + AQ_VS;
    __half* Ps = smh + AQ_PS;
    const uint32_t uQs = (uint32_t)__cvta_generic_to_shared(Qs);
    const uint32_t uKs = (uint32_t)__cvta_generic_to_shared(Ks);
    const uint32_t uVs = (uint32_t)__cvta_generic_to_shared(Vs);
    const uint32_t uPs = (uint32_t)__cvta_generic_to_shared(Ps);

    const int h   = blockIdx.y;
    const int q0  = blockIdx.x * QROWS;
    const int tid = threadIdx.x;
    const int wid = tid >> 5;
    const int lane = tid & 31;
    const int g   = lane >> 2;
    const int tg  = lane & 3;
    const int wq0 = wid * 16;

    // load Q tile (half copy; scale incl. log2e already folded)
    for (int e = tid; e < QROWS * 8; e += 512) {
        const int row = e >> 3, cc = e & 7;
        *reinterpret_cast<uint4*>(&Qs[row * HS + cc * 8]) =
            *reinterpret_cast<const uint4*>(Qh + (size_t)(q0 + row) * DIM + h * DH + cc * 8);
    }

    float m0 = -1e30f, m1 = -1e30f, l0 = 0.0f, l1 = 0.0f;
    float accO[8][4];
#pragma unroll
    for (int nt = 0; nt < 8; nt++)
#pragma unroll
        for (int i = 0; i < 4; i++) accO[nt][i] = 0.0f;

    // register prefetch tile 0 (K and V both row-major from KVh)
    const int prow = tid >> 3, pcc = tid & 7;
    uint4 kr, vr;
    kr = *reinterpret_cast<const uint4*>(KVh + (size_t)prow * (2 * DIM) + h * DH + pcc * 8);
    vr = *reinterpret_cast<const uint4*>(KVh + (size_t)prow * (2 * DIM) + DIM + h * DH + pcc * 8);

    const int gq0 = q0 + wq0 + g;
    const int gq1 = gq0 + 8;

    // ldmatrix lane addressing
    const int arow = lane & 15;
    const int acol = (lane >> 4) * 8;
    const int brow = (lane & 7) + ((lane >> 4) & 1) * 8;
    const int bcol = ((lane >> 3) & 1) * 8;
    const int vkrow = (lane & 7) + ((lane >> 3) & 1) * 8;
    const int vncol = ((lane >> 4) & 1) * 8;

    int j0 = 0;
    while (j0 < TOTK) {
        int nj = j0 + 64;
        if (nj >= q0 + QROWS && nj < SEQ_N) nj = SEQ_N;  // causal tile skip

        __syncthreads();
        *reinterpret_cast<uint4*>(&Ks[prow * HS + pcc * 8]) = kr;
        *reinterpret_cast<uint4*>(&Vs[prow * HS + pcc * 8]) = vr;
        if (nj < TOTK) {
            kr = *reinterpret_cast<const uint4*>(
                KVh + (size_t)(nj + prow) * (2 * DIM) + h * DH + pcc * 8);
            vr = *reinterpret_cast<const uint4*>(
                KVh + (size_t)(nj + prow) * (2 * DIM) + DIM + h * DH + pcc * 8);
        }
        __syncthreads();

        // ---- S = Q @ K^T (log2 domain) ----
        float s[8][4];
#pragma unroll
        for (int nt = 0; nt < 8; nt++)
#pragma unroll
            for (int i = 0; i < 4; i++) s[nt][i] = 0.0f;
#pragma unroll
        for (int kf = 0; kf < 4; kf++) {
            const int kk = kf * 16;
            uint32_t a[4];
            ldsm4(a, uQs + (wq0 + arow) * (HS * 2) + (kk + acol) * 2);
            uint32_t bf[4][4];
#pragma unroll
            for (int p = 0; p < 4; p++)
                ldsm4(bf[p], uKs + (p * 16 + brow) * (HS * 2) + (kk + bcol) * 2);
#pragma unroll
            for (int nt = 0; nt < 8; nt++)
                mma16(s[nt], a, &bf[nt >> 1][(nt & 1) * 2]);
        }

        // ---- causal mask ----
        if (j0 < SEQ_N) {
#pragma unroll
            for (int nt = 0; nt < 8; nt++) {
                const int gk = j0 + nt * 8 + 2 * tg;
                if (gk > gq0)     s[nt][0] = MASK_VAL;
                if (gk + 1 > gq0) s[nt][1] = MASK_VAL;
                if (gk > gq1)     s[nt][2] = MASK_VAL;
                if (gk + 1 > gq1) s[nt][3] = MASK_VAL;
            }
        }

        // ---- online softmax (base-2) ----
        float mx0 = -1e30f, mx1 = -1e30f;
#pragma unroll
        for (int nt = 0; nt < 8; nt++) {
            mx0 = fmaxf(mx0, fmaxf(s[nt][0], s[nt][1]));
            mx1 = fmaxf(mx1, fmaxf(s[nt][2], s[nt][3]));
        }
        mx0 = fmaxf(mx0, __shfl_xor_sync(0xffffffffu, mx0, 1));
        mx0 = fmaxf(mx0, __shfl_xor_sync(0xffffffffu, mx0, 2));
        mx1 = fmaxf(mx1, __shfl_xor_sync(0xffffffffu, mx1, 1));
        mx1 = fmaxf(mx1, __shfl_xor_sync(0xffffffffu, mx1, 2));
        const float mn0 = fmaxf(m0, mx0);
        const float mn1 = fmaxf(m1, mx1);
        const float fac0 = exp2f(m0 - mn0);
        const float fac1 = exp2f(m1 - mn1);
        float sum0 = 0.0f, sum1 = 0.0f;
#pragma unroll
        for (int nt = 0; nt < 8; nt++) {
            s[nt][0] = exp2f(s[nt][0] - mn0);
            s[nt][1] = exp2f(s[nt][1] - mn0);
            s[nt][2] = exp2f(s[nt][2] - mn1);
            s[nt][3] = exp2f(s[nt][3] - mn1);
            sum0 += s[nt][0] + s[nt][1];
            sum1 += s[nt][2] + s[nt][3];
        }
        sum0 += __shfl_xor_sync(0xffffffffu, sum0, 1);
        sum0 += __shfl_xor_sync(0xffffffffu, sum0, 2);
        sum1 += __shfl_xor_sync(0xffffffffu, sum1, 1);
        sum1 += __shfl_xor_sync(0xffffffffu, sum1, 2);
        l0 = l0 * fac0 + sum0;
        l1 = l1 * fac1 + sum1;
        m0 = mn0; m1 = mn1;
#pragma unroll
        for (int nt = 0; nt < 8; nt++) {
            accO[nt][0] *= fac0; accO[nt][1] *= fac0;
            accO[nt][2] *= fac1; accO[nt][3] *= fac1;
        }
        // store P (half) — warp-private rows
#pragma unroll
        for (int nt = 0; nt < 8; nt++) {
            *reinterpret_cast<uint32_t*>(&Ps[(wq0 + g) * HS + nt * 8 + 2 * tg]) =
                pk2(s[nt][0], s[nt][1]);
            *reinterpret_cast<uint32_t*>(&Ps[(wq0 + g + 8) * HS + nt * 8 + 2 * tg]) =
                pk2(s[nt][2], s[nt][3]);
        }
        __syncwarp();

        // ---- accO += P @ V  (V row-major [seq][dh] -> trans ldsm) ----
#pragma unroll
        for (int kf = 0; kf < 4; kf++) {
            const int kk = kf * 16;
            uint32_t a[4];
            ldsm4(a, uPs + (wq0 + arow) * (HS * 2) + (kk + acol) * 2);
            uint32_t bf[4][4];
#pragma unroll
            for (int p = 0; p < 4; p++)
                ldsm4t(bf[p], uVs + (kk + vkrow) * (HS * 2) + (p * 16 + vncol) * 2);
#pragma unroll
            for (int nt = 0; nt < 8; nt++)
                mma16(accO[nt], a, &bf[nt >> 1][(nt & 1) * 2]);
        }
        j0 = nj;
    }

    // ---- epilogue (half out) ----
    const float inv0 = 1.0f / l0;
    const float inv1 = 1.0f / l1;
#pragma unroll
    for (int nt = 0; nt < 8; nt++) {
        const int col = h * DH + nt * 8 + 2 * tg;
        *reinterpret_cast<uint32_t*>(Oh + (size_t)gq0 * DIM + col) =
            pk2(accO[nt][0] * inv0, accO[nt][1] * inv0);
        *reinterpret_cast<uint32_t*>(Oh + (size_t)gq1 * DIM + col) =
            pk2(accO[nt][2] * inv1, accO[nt][3] * inv1);
    }
}

// ---------------------------------------------------------------------------
// LayerNorm: float in; float out (+ optional half out). Vectorized.
// ---------------------------------------------------------------------------
template <bool WH>
__global__ void __launch_bounds__(256)
ln_kernel(const float* __restrict__ a, const float* __restrict__ g,
          const float* __restrict__ beta, float* __restrict__ out,
          __half* __restrict__ outh)
{
    const int row = blockIdx.x;
    const int c0 = threadIdx.x * 4;
    __shared__ float sh1[8], sh2[8];

    const float4 v = *reinterpret_cast<const float4*>(a + (size_t)row * DIM + c0);
    float s = v.x + v.y + v.z + v.w;
#pragma unroll
    for (int off = 16; off >= 1; off >>= 1) s += __shfl_xor_sync(0xffffffffu, s, off);
    if ((threadIdx.x & 31) == 0) sh1[threadIdx.x >> 5] = s;
    __syncthreads();
    float mu = 0.0f;
#pragma unroll
    for (int i = 0; i < 8; i++) mu += sh1[i];
    mu *= (1.0f / DIM);

    float d0 = v.x - mu, d1 = v.y - mu, d2 = v.z - mu, d3 = v.w - mu;
    float vs = d0 * d0 + d1 * d1 + d2 * d2 + d3 * d3;
#pragma unroll
    for (int off = 16; off >= 1; off >>= 1) vs += __shfl_xor_sync(0xffffffffu, vs, off);
    if ((threadIdx.x & 31) == 0) sh2[threadIdx.x >> 5] = vs;
    __syncthreads();
    float var = 0.0f;
#pragma unroll
    for (int i = 0; i < 8; i++) var += sh2[i];
    const float inv = rsqrtf(var * (1.0f / DIM) + 1e-5f);

    const float4 gv = *reinterpret_cast<const float4*>(g + c0);
    const float4 bv = *reinterpret_cast<const float4*>(beta + c0);
    float4 o;
    o.x = d0 * inv * gv.x + bv.x;
    o.y = d1 * inv * gv.y + bv.y;
    o.z = d2 * inv * gv.z + bv.z;
    o.w = d3 * inv * gv.w + bv.w;
    *reinterpret_cast<float4*>(out + (size_t)row * DIM + c0) = o;
    if (WH) {
        uint2 ho; ho.x = pk2(o.x, o.y); ho.y = pk2(o.z, o.w);
        *reinterpret_cast<uint2*>(outh + (size_t)row * DIM + c0) = ho;
    }
}

// ---------------------------------------------------------------------------
// Launch (stream fork/join to overlap weight prep with GEMMs)
// ---------------------------------------------------------------------------
extern "C" void kernel_launch(void* const* d_in, const int* in_sizes, int n_in,
                              void* d_out, int out_size)
{
    const float* x     = (const float*)d_in[0];
    const float* ctx   = (const float*)d_in[1];
    const float* Wq    = (const float*)d_in[2];
    const float* bq    = (const float*)d_in[3];
    const float* Wkv   = (const float*)d_in[4];
    const float* bkv   = (const float*)d_in[5];
    const float* Wo    = (const float*)d_in[6];
    const float* bo    = (const float*)d_in[7];
    const float* ln1g  = (const float*)d_in[8];
    const float* ln1b  = (const float*)d_in[9];
    const float* W1    = (const float*)d_in[10];
    const float* bf1   = (const float*)d_in[11];
    const float* W2    = (const float*)d_in[12];
    const float* bf2   = (const float*)d_in[13];
    const float* ln2g  = (const float*)d_in[14];
    const float* ln2b  = (const float*)d_in[15];
    float* out = (float*)d_out;

    __half *inh, *qh, *kvh, *attnh, *x1h, *ffh, *wqT, *wkvT, *woT, *w1T, *w2T;
    float *t, *x1;
    cudaGetSymbolAddress((void**)&inh,   g_inh);
    cudaGetSymbolAddress((void**)&qh,    g_qh);
    cudaGetSymbolAddress((void**)&kvh,   g_kvh);
    cudaGetSymbolAddress((void**)&attnh, g_attnh);
    cudaGetSymbolAddress((void**)&x1h,   g_x1h);
    cudaGetSymbolAddress((void**)&ffh,   g_ffh);
    cudaGetSymbolAddress((void**)&t,     g_t);
    cudaGetSymbolAddress((void**)&x1,    g_x1);
    cudaGetSymbolAddress((void**)&wqT,   g_wqT);
    cudaGetSymbolAddress((void**)&wkvT,  g_wkvT);
    cudaGetSymbolAddress((void**)&woT,   g_woT);
    cudaGetSymbolAddress((void**)&w1T,   g_w1T);
    cudaGetSymbolAddress((void**)&w2T,   g_w2T);

    cudaFuncSetAttribute(attn_kernel, cudaFuncAttributeMaxDynamicSharedMemorySize, ATT_SMEM);
    cudaFuncSetAttribute(mma_gemm<1>, cudaFuncAttributeMaxDynamicSharedMemorySize, GEMM_SMEM);
    cudaFuncSetAttribute(mma_gemm<2>, cudaFuncAttributeMaxDynamicSharedMemorySize, GEMM_SMEM);
    cudaFuncSetAttribute(mma_gemm<3>, cudaFuncAttributeMaxDynamicSharedMemorySize, GEMM_SMEM);

    // one-time host-side resources (no device memory involved)
    static cudaStream_t s2 = nullptr;
    static cudaEvent_t eBegin = nullptr, eKvW = nullptr, eQW = nullptr, eW = nullptr;
    if (s2 == nullptr) {
        cudaStreamCreateWithFlags(&s2, cudaStreamNonBlocking);
        cudaEventCreateWithFlags(&eBegin, cudaEventDisableTiming);
        cudaEventCreateWithFlags(&eKvW,   cudaEventDisableTiming);
        cudaEventCreateWithFlags(&eQW,    cudaEventDisableTiming);
        cudaEventCreateWithFlags(&eW,     cudaEventDisableTiming);
    }

    // ---- fork: weight transposes on s2, activations on main ----
    cudaEventRecord(eBegin, 0);
    cudaStreamWaitEvent(s2, eBegin, 0);

    transpose_h_kernel<<<dim3(2 * DIM / 32, DIM / 32), 256, 0, s2>>>(Wkv, wkvT, DIM, 2 * DIM);
    cudaEventRecord(eKvW, s2);
    transpose_h_kernel<<<dim3(DIM / 32, DIM / 32), 256, 0, s2>>>(Wq,  wqT,  DIM,  DIM);
    cudaEventRecord(eQW, s2);
    transpose_h_kernel<<<dim3(DIM / 32, DIM / 32), 256, 0, s2>>>(Wo,  woT,  DIM,  DIM);
    transpose_h_kernel<<<dim3(DFF_ / 32, DIM / 32), 256, 0, s2>>>(W1,  w1T,  DIM,  DFF_);
    transpose_h_kernel<<<dim3(DIM / 32, DFF_ / 32), 256, 0, s2>>>(W2,  w2T,  DFF_, DIM);
    cudaEventRecord(eW, s2);

    // main: activation convert (needed by both projections)
    convert_h_kernel<<<TOTK * DIM / (256 * 8), 256>>>(x, ctx, inh);

    // 2) kvh = concat(x, ctx) @ Wkv + bkv
    cudaStreamWaitEvent(0, eKvW, 0);
    mma_gemm<1><<<dim3(2 * DIM / 128, TOTK / 128), 128, GEMM_SMEM>>>(
        inh, wkvT, bkv, nullptr, nullptr, kvh, 1.0f, TOTK, 2 * DIM, DIM);

    // 1) qh = (x @ Wq + bq) * (log2e / 8)
    cudaStreamWaitEvent(0, eQW, 0);
    mma_gemm<1><<<dim3(DIM / 128, SEQ_N / 128), 128, GEMM_SMEM>>>(
        inh, wqT, bq, nullptr, nullptr, qh, 0.18033688011112042f, SEQ_N, DIM, DIM);

    // 3) attention -> attnh
    attn_kernel<<<dim3(SEQ_N / QROWS, HEADS), 512, ATT_SMEM>>>(qh, kvh, attnh);

    // ---- join: remaining weights ready ----
    cudaStreamWaitEvent(0, eW, 0);

    // 4) t = attn @ Wo + bo + x
    mma_gemm<3><<<dim3(DIM / 128, SEQ_N / 128), 128, GEMM_SMEM>>>(
        attnh, woT, bo, x, t, nullptr, 1.0f, SEQ_N, DIM, DIM);

    // 5) x1 = LN1(t)  (float + half)
    ln_kernel<true><<<SEQ_N, 256>>>(t, ln1g, ln1b, x1, x1h);

    // 6) ffh = gelu(x1 @ W1 + bf1)
    mma_gemm<2><<<dim3(DFF_ / 128, SEQ_N / 128), 128, GEMM_SMEM>>>(
        x1h, w1T, bf1, nullptr, nullptr, ffh, 1.0f, SEQ_N, DFF_, DIM);

    // 7) t = ff @ W2 + bf2 + x1
    mma_gemm<3><<<dim3(DIM / 128, SEQ_N / 128), 128, GEMM_SMEM>>>(
        ffh, w2T, bf2, x1, t, nullptr, 1.0f, SEQ_N, DIM, DFF_);

    // 8) out = LN2(t)
    ln_kernel<false><<<SEQ_N, 256>>>(t, ln2g, ln2b, out, nullptr);
}

// round 11
// speedup vs baseline: 7.0757x; 1.0105x over previous
#include <cuda_runtime.h>
#include <cuda_fp16.h>
#include <math.h>
#include <stdint.h>

// R11: merged QKV projection (single 640-tile launch) + attention with
// cp.async double-buffered K/V tiles. GEMM core unchanged (HMMA wall).

// ---------------------------------------------------------------------------
// Problem constants
// ---------------------------------------------------------------------------
#define SEQ_N 2048
#define SEQ_M 2048
#define TOTK  (SEQ_N + SEQ_M)   // 4096
#define DIM   1024
#define HEADS 16
#define DH    64
#define DFF_  4096
#define MASK_VAL (-50000.0f)

// ---------------------------------------------------------------------------
// Scratch (device globals; no allocation allowed)
// ---------------------------------------------------------------------------
__device__ __half g_inh [TOTK * DIM];        // concat(x, ctx) in fp16
__device__ __half g_qh  [SEQ_N * DIM];       // q (pre-scaled by log2e/8)
__device__ __half g_kvh [TOTK * 2 * DIM];    // K cols [0,1024), V cols [1024,2048)
__device__ __half g_attnh[SEQ_N * DIM];
__device__ __half g_x1h [SEQ_N * DIM];
__device__ __half g_ffh [SEQ_N * DFF_];
__device__ float  g_t   [SEQ_N * DIM];
__device__ float  g_x1  [SEQ_N * DIM];
// transposed fp16 weights (K-major [N,K])
__device__ __half g_wqT [DIM * DIM];
__device__ __half g_wkvT[2 * DIM * DIM];
__device__ __half g_woT [DIM * DIM];
__device__ __half g_w1T [DFF_ * DIM];
__device__ __half g_w2T [DIM * DFF_];

// ---------------------------------------------------------------------------
// Helpers
// ---------------------------------------------------------------------------
__device__ __forceinline__ uint32_t pk2(float a, float b) {
    __half2 h = __floats2half2_rn(a, b);
    return *reinterpret_cast<uint32_t*>(&h);
}
__device__ __forceinline__ void mma16(float* c, const uint32_t* a, const uint32_t* b) {
    asm volatile(
        "mma.sync.aligned.m16n8k16.row.col.f32.f16.f16.f32 "
        "{%0,%1,%2,%3}, {%4,%5,%6,%7}, {%8,%9}, {%0,%1,%2,%3};"
        : "+f"(c[0]), "+f"(c[1]), "+f"(c[2]), "+f"(c[3])
        : "r"(a[0]), "r"(a[1]), "r"(a[2]), "r"(a[3]), "r"(b[0]), "r"(b[1]));
}
__device__ __forceinline__ void ldsm4(uint32_t* r, uint32_t addr) {
    asm volatile("ldmatrix.sync.aligned.m8n8.x4.shared.b16 {%0,%1,%2,%3}, [%4];"
                 : "=r"(r[0]), "=r"(r[1]), "=r"(r[2]), "=r"(r[3]) : "r"(addr));
}
__device__ __forceinline__ void ldsm4t(uint32_t* r, uint32_t addr) {
    asm volatile("ldmatrix.sync.aligned.m8n8.x4.trans.shared.b16 {%0,%1,%2,%3}, [%4];"
                 : "=r"(r[0]), "=r"(r[1]), "=r"(r[2]), "=r"(r[3]) : "r"(addr));
}
__device__ __forceinline__ void cp16(uint32_t saddr, const void* g) {
    asm volatile("cp.async.cg.shared.global [%0], [%1], 16;" :: "r"(saddr), "l"(g));
}
__device__ __forceinline__ void cp_commit() {
    asm volatile("cp.async.commit_group;" ::: "memory");
}
template <int NN>
__device__ __forceinline__ void cp_wait() {
    asm volatile("cp.async.wait_group %0;" :: "n"(NN) : "memory");
}

// ---------------------------------------------------------------------------
// convert concat(x, ctx) -> fp16 g_inh
// ---------------------------------------------------------------------------
__global__ void __launch_bounds__(256)
convert_h_kernel(const float* __restrict__ x, const float* __restrict__ ctx,
                 __half* __restrict__ out)
{
    const size_t i = ((size_t)blockIdx.x * 256 + threadIdx.x) * 8;
    const float* src = (i < (size_t)SEQ_N * DIM) ? x + i
                                                 : ctx + (i - (size_t)SEQ_N * DIM);
    const float4 a = *reinterpret_cast<const float4*>(src);
    const float4 b = *reinterpret_cast<const float4*>(src + 4);
    uint4 o;
    o.x = pk2(a.x, a.y); o.y = pk2(a.z, a.w);
    o.z = pk2(b.x, b.y); o.w = pk2(b.z, b.w);
    *reinterpret_cast<uint4*>(out + i) = o;
}

// ---------------------------------------------------------------------------
// Weight transpose + fp16
// ---------------------------------------------------------------------------
__global__ void __launch_bounds__(256)
transpose_h_kernel(const float* __restrict__ in, __half* __restrict__ out, int K, int N)
{
    __shared__ float t[32][33];
    const int bx = blockIdx.x * 32;
    const int by = blockIdx.y * 32;
    const int x = threadIdx.x & 31;
    const int y = threadIdx.x >> 5;
#pragma unroll
    for (int i = 0; i < 32; i += 8)
        t[y + i][x] = in[(size_t)(by + y + i) * N + bx + x];
    __syncthreads();
#pragma unroll
    for (int i = 0; i < 32; i += 8)
        out[(size_t)(bx + y + i) * K + by + x] = __float2half_rn(t[x][y + i]);
}

// ---------------------------------------------------------------------------
// GEMM core pieces (tile 128x128, K-chunk 32, 128 threads, cp.async 3 stage)
// ---------------------------------------------------------------------------
#define ABYTES 10240          // 128 rows * 80B
#define STAGE_B (2 * ABYTES)
#define GEMM_SMEM (3 * STAGE_B)

struct GemmCtx {
    uint32_t smemU;
    int lane, g, tg, warp_m, warp_n, crow, cq;
    int arow, acol, brow, bcol;
};
__device__ __forceinline__ GemmCtx gemm_ctx(uint32_t smemU) {
    GemmCtx c;
    const int tid = threadIdx.x;
    c.smemU = smemU;
    c.lane = tid & 31;
    const int wid = tid >> 5;
    c.g = c.lane >> 2; c.tg = c.lane & 3;
    c.warp_m = wid >> 1; c.warp_n = wid & 1;
    c.crow = tid >> 2; c.cq = tid & 3;
    c.arow = c.lane & 15;
    c.acol = (c.lane >> 4) * 8;
    c.brow = (c.lane & 7) + ((c.lane >> 4) & 1) * 8;
    c.bcol = ((c.lane >> 3) & 1) * 8;
    return c;
}

__device__ __forceinline__ void gemm_issue(const GemmCtx& c, const __half* Ah,
                                           const __half* Bt, int tileM, int tileN,
                                           int K, int chunk, int stage) {
    const uint32_t base = c.smemU + stage * STAGE_B;
    const size_t koff = (size_t)chunk * 32 + c.cq * 8;
#pragma unroll
    for (int rr = 0; rr < 4; rr++) {
        const int row = c.crow + rr * 32;
        cp16(base + row * 80 + c.cq * 16, Ah + (size_t)(tileM + row) * K + koff);
        cp16(base + ABYTES + row * 80 + c.cq * 16, Bt + (size_t)(tileN + row) * K + koff);
    }
    cp_commit();
}

__device__ __forceinline__ void gemm_main(const GemmCtx& c, const __half* Ah,
                                          const __half* Bt, int tileM, int tileN,
                                          int K, float acc[4][8][4]) {
#pragma unroll
    for (int i = 0; i < 4; i++)
#pragma unroll
        for (int j = 0; j < 8; j++)
#pragma unroll
            for (int l = 0; l < 4; l++) acc[i][j][l] = 0.0f;

    const int NKC = K / 32;
    gemm_issue(c, Ah, Bt, tileM, tileN, K, 0, 0);
    if (NKC > 1) gemm_issue(c, Ah, Bt, tileM, tileN, K, 1, 1);

    for (int kc = 0; kc < NKC; kc++) {
        const int s = kc % 3;
        if (kc < NKC - 1) cp_wait<1>(); else cp_wait<0>();
        __syncthreads();
        if (kc + 2 < NKC) gemm_issue(c, Ah, Bt, tileM, tileN, K, kc + 2, (kc + 2) % 3);

        const uint32_t aBase = c.smemU + s * STAGE_B;
        const uint32_t bBase = aBase + ABYTES;
#pragma unroll
        for (int kk = 0; kk < 32; kk += 16) {
            uint32_t af[4][4];
            uint32_t bf[4][4];
#pragma unroll
            for (int mt = 0; mt < 4; mt++)
                ldsm4(af[mt], aBase + (c.warp_m * 64 + mt * 16 + c.arow) * 80
                              + (kk + c.acol) * 2);
#pragma unroll
            for (int p = 0; p < 4; p++)
                ldsm4(bf[p], bBase + (c.warp_n * 64 + p * 16 + c.brow) * 80
                             + (kk + c.bcol) * 2);
#pragma unroll
            for (int mt = 0; mt < 4; mt++)
#pragma unroll
                for (int nt = 0; nt < 8; nt++)
                    mma16(acc[mt][nt], af[mt], &bf[nt >> 1][(nt & 1) * 2]);
        }
    }
}

// ---------------------------------------------------------------------------
// Merged QKV projection: 640 tiles. idx<512 -> KV [4096,2048]; else Q [2048,1024].
// ---------------------------------------------------------------------------
__global__ void __launch_bounds__(128)
qkv_gemm(const __half* __restrict__ Ah,
         const __half* __restrict__ wqT, const __half* __restrict__ wkvT,
         const float* __restrict__ bq, const float* __restrict__ bkv,
         __half* __restrict__ qh, __half* __restrict__ kvh, float alphaQ)
{
    extern __shared__ __half smem_h[];
    GemmCtx c = gemm_ctx((uint32_t)__cvta_generic_to_shared(smem_h));

    const int idx = blockIdx.x;
    int tileM, tileN, N;
    const __half* Bt;
    const float* bias;
    __half* Ch;
    float alpha;
    if (idx < 512) {
        tileM = (idx >> 4) * 128; tileN = (idx & 15) * 128;
        N = 2 * DIM; Bt = wkvT; bias = bkv; Ch = kvh; alpha = 1.0f;
    } else {
        const int q = idx - 512;
        tileM = (q >> 3) * 128; tileN = (q & 7) * 128;
        N = DIM; Bt = wqT; bias = bq; Ch = qh; alpha = alphaQ;
    }

    float acc[4][8][4];
    gemm_main(c, Ah, Bt, tileM, tileN, DIM, acc);

#pragma unroll
    for (int mt = 0; mt < 4; mt++) {
        const int r0 = tileM + c.warp_m * 64 + mt * 16 + c.g;
#pragma unroll
        for (int nt = 0; nt < 8; nt++) {
            const int col = tileN + c.warp_n * 64 + nt * 8 + c.tg * 2;
            const float2 bv = *reinterpret_cast<const float2*>(bias + col);
#pragma unroll
            for (int hh = 0; hh < 2; hh++) {
                const int r = r0 + hh * 8;
                const float v0 = (acc[mt][nt][hh * 2 + 0] + bv.x) * alpha;
                const float v1 = (acc[mt][nt][hh * 2 + 1] + bv.y) * alpha;
                *reinterpret_cast<uint32_t*>(Ch + (size_t)r * N + col) = pk2(v0, v1);
            }
        }
    }
}

// ---------------------------------------------------------------------------
// General GEMM: EPI 2: half out = gelu(acc+bias); EPI 3: float out = acc+bias+resid
// ---------------------------------------------------------------------------
template <int EPI>
__global__ void __launch_bounds__(128)
mma_gemm(const __half* __restrict__ Ah, const __half* __restrict__ Bt,
         const float* __restrict__ bias, const float* __restrict__ resid,
         float* __restrict__ Cf, __half* __restrict__ Ch,
         int M, int N, int K)
{
    extern __shared__ __half smem_h[];
    GemmCtx c = gemm_ctx((uint32_t)__cvta_generic_to_shared(smem_h));

    const int tileM = blockIdx.y * 128;
    const int tileN = blockIdx.x * 128;

    float acc[4][8][4];
    gemm_main(c, Ah, Bt, tileM, tileN, K, acc);

#pragma unroll
    for (int mt = 0; mt < 4; mt++) {
        const int r0 = tileM + c.warp_m * 64 + mt * 16 + c.g;
#pragma unroll
        for (int nt = 0; nt < 8; nt++) {
            const int col = tileN + c.warp_n * 64 + nt * 8 + c.tg * 2;
            const float2 bv = *reinterpret_cast<const float2*>(bias + col);
#pragma unroll
            for (int hh = 0; hh < 2; hh++) {
                const int r = r0 + hh * 8;
                float v0 = acc[mt][nt][hh * 2 + 0] + bv.x;
                float v1 = acc[mt][nt][hh * 2 + 1] + bv.y;
                if (EPI == 2) {
                    v0 = 0.5f * v0 * (1.0f + erff(v0 * 0.70710678118654752f));
                    v1 = 0.5f * v1 * (1.0f + erff(v1 * 0.70710678118654752f));
                    *reinterpret_cast<uint32_t*>(Ch + (size_t)r * N + col) = pk2(v0, v1);
                } else {
                    const float2 rv = *reinterpret_cast<const float2*>(
                        resid + (size_t)r * N + col);
                    float2 o; o.x = v0 + rv.x; o.y = v1 + rv.y;
                    *reinterpret_cast<float2*>(Cf + (size_t)r * N + col) = o;
                }
            }
        }
    }
}

// ---------------------------------------------------------------------------
// Flash attention v6: cp.async double-buffered K/V, V via ldmatrix.trans,
// exp2-domain softmax. grid (SEQ_N/256, HEADS), 512 threads.
// Layout (halfs): Qs[256*72] K0[64*72] V0[64*72] K1[64*72] V1[64*72] Ps[256*72]
// ---------------------------------------------------------------------------
#define QROWS 256
#define HS 72
#define AQ_QS 0
#define AQ_K0 (QROWS * HS)               // 18432
#define AQ_PS (AQ_K0 + 4 * 64 * HS)      // 36864
#define AQ_HALFS (AQ_PS + QROWS * HS)    // 55296
#define ATT_SMEM (AQ_HALFS * 2)          // 110592 B

__global__ void __launch_bounds__(512)
attn_kernel(const __half* __restrict__ Qh,
            const __half* __restrict__ KVh,
            __half* __restrict__ Oh)
{
    extern __shared__ __half smh[];
    const uint32_t uBase = (uint32_t)__cvta_generic_to_shared(smh);
    const uint32_t uQs = uBase;
    const uint32_t uPs = uBase + AQ_PS * 2;

    const int h   = blockIdx.y;
    const int q0  = blockIdx.x * QROWS;
    const int tid = threadIdx.x;
    const int wid = tid >> 5;
    const int lane = tid & 31;
    const int g   = lane >> 2;
    const int tg  = lane & 3;
    const int wq0 = wid * 16;

    // load Q tile (plain copy; scale incl. log2e folded upstream)
    __half* Qs = smh + AQ_QS;
    for (int e = tid; e < QROWS * 8; e += 512) {
        const int row = e >> 3, cc = e & 7;
        *reinterpret_cast<uint4*>(&Qs[row * HS + cc * 8]) =
            *reinterpret_cast<const uint4*>(Qh + (size_t)(q0 + row) * DIM + h * DH + cc * 8);
    }

    float m0 = -1e30f, m1 = -1e30f, l0 = 0.0f, l1 = 0.0f;
    float accO[8][4];
#pragma unroll
    for (int nt = 0; nt < 8; nt++)
#pragma unroll
        for (int i = 0; i < 4; i++) accO[nt][i] = 0.0f;

    // cp.async K/V: thread -> (row, chunk); 64 rows x 8 chunks = 512
    const int prow = tid >> 3, pcc = tid & 7;
    auto issue_kv = [&](int j, int s) {
        const uint32_t uK = uBase + (AQ_K0 + s * 2 * 64 * HS) * 2;
        const uint32_t uV = uK + 64 * HS * 2;
        const __half* src = KVh + (size_t)(j + prow) * (2 * DIM) + h * DH + pcc * 8;
        cp16(uK + prow * (HS * 2) + pcc * 16, src);
        cp16(uV + prow * (HS * 2) + pcc * 16, src + DIM);
        cp_commit();
    };

    const int gq0 = q0 + wq0 + g;
    const int gq1 = gq0 + 8;

    // ldmatrix lane addressing
    const int arow = lane & 15;
    const int acol = (lane >> 4) * 8;
    const int brow = (lane & 7) + ((lane >> 4) & 1) * 8;
    const int bcol = ((lane >> 3) & 1) * 8;
    const int vkrow = (lane & 7) + ((lane >> 3) & 1) * 8;
    const int vncol = ((lane >> 4) & 1) * 8;

    int j0 = 0;
    int stage = 0;
    issue_kv(0, 0);
    while (j0 < TOTK) {
        int nj = j0 + 64;
        if (nj >= q0 + QROWS && nj < SEQ_N) nj = SEQ_N;  // causal tile skip

        __syncthreads();  // all warps done reading buffer stage^1 (prev tile)
        if (nj < TOTK) {
            issue_kv(nj, stage ^ 1);
            cp_wait<1>();
        } else {
            cp_wait<0>();
        }
        __syncthreads();  // tile j0 data visible

        const uint32_t uKs = uBase + (AQ_K0 + stage * 2 * 64 * HS) * 2;
        const uint32_t uVs = uKs + 64 * HS * 2;

        // ---- S = Q @ K^T (log2 domain) ----
        float s[8][4];
#pragma unroll
        for (int nt = 0; nt < 8; nt++)
#pragma unroll
            for (int i = 0; i < 4; i++) s[nt][i] = 0.0f;
#pragma unroll
        for (int kf = 0; kf < 4; kf++) {
            const int kk = kf * 16;
            uint32_t a[4];
            ldsm4(a, uQs + (wq0 + arow) * (HS * 2) + (kk + acol) * 2);
            uint32_t bf[4][4];
#pragma unroll
            for (int p = 0; p < 4; p++)
                ldsm4(bf[p], uKs + (p * 16 + brow) * (HS * 2) + (kk + bcol) * 2);
#pragma unroll
            for (int nt = 0; nt < 8; nt++)
                mma16(s[nt], a, &bf[nt >> 1][(nt & 1) * 2]);
        }

        // ---- causal mask ----
        if (j0 < SEQ_N) {
#pragma unroll
            for (int nt = 0; nt < 8; nt++) {
                const int gk = j0 + nt * 8 + 2 * tg;
                if (gk > gq0)     s[nt][0] = MASK_VAL;
                if (gk + 1 > gq0) s[nt][1] = MASK_VAL;
                if (gk > gq1)     s[nt][2] = MASK_VAL;
                if (gk + 1 > gq1) s[nt][3] = MASK_VAL;
            }
        }

        // ---- online softmax (base-2) ----
        float mx0 = -1e30f, mx1 = -1e30f;
#pragma unroll
        for (int nt = 0; nt < 8; nt++) {
            mx0 = fmaxf(mx0, fmaxf(s[nt][0], s[nt][1]));
            mx1 = fmaxf(mx1, fmaxf(s[nt][2], s[nt][3]));
        }
        mx0 = fmaxf(mx0, __shfl_xor_sync(0xffffffffu, mx0, 1));
        mx0 = fmaxf(mx0, __shfl_xor_sync(0xffffffffu, mx0, 2));
        mx1 = fmaxf(mx1, __shfl_xor_sync(0xffffffffu, mx1, 1));
        mx1 = fmaxf(mx1, __shfl_xor_sync(0xffffffffu, mx1, 2));
        const float mn0 = fmaxf(m0, mx0);
        const float mn1 = fmaxf(m1, mx1);
        const float fac0 = exp2f(m0 - mn0);
        const float fac1 = exp2f(m1 - mn1);
        float sum0 = 0.0f, sum1 = 0.0f;
#pragma unroll
        for (int nt = 0; nt < 8; nt++) {
            s[nt][0] = exp2f(s[nt][0] - mn0);
            s[nt][1] = exp2f(s[nt][1] - mn0);
            s[nt][2] = exp2f(s[nt][2] - mn1);
            s[nt][3] = exp2f(s[nt][3] - mn1);
            sum0 += s[nt][0] + s[nt][1];
            sum1 += s[nt][2] + s[nt][3];
        }
        sum0 += __shfl_xor_sync(0xffffffffu, sum0, 1);
        sum0 += __shfl_xor_sync(0xffffffffu, sum0, 2);
        sum1 += __shfl_xor_sync(0xffffffffu, sum1, 1);
        sum1 += __shfl_xor_sync(0xffffffffu, sum1, 2);
        l0 = l0 * fac0 + sum0;
        l1 = l1 * fac1 + sum1;
        m0 = mn0; m1 = mn1;
#pragma unroll
        for (int nt = 0; nt < 8; nt++) {
            accO[nt][0] *= fac0; accO[nt][1] *= fac0;
            accO[nt][2] *= fac1; accO[nt][3] *= fac1;
        }
        // store P (half) — warp-private rows
        __half* Ps = smh + AQ_PS;
#pragma unroll
        for (int nt = 0; nt < 8; nt++) {
            *reinterpret_cast<uint32_t*>(&Ps[(wq0 + g) * HS + nt * 8 + 2 * tg]) =
                pk2(s[nt][0], s[nt][1]);
            *reinterpret_cast<uint32_t*>(&Ps[(wq0 + g + 8) * HS + nt * 8 + 2 * tg]) =
                pk2(s[nt][2], s[nt][3]);
        }
        __syncwarp();

        // ---- accO += P @ V  (V row-major [seq][dh] -> trans ldsm) ----
#pragma unroll
        for (int kf = 0; kf < 4; kf++) {
            const int kk = kf * 16;
            uint32_t a[4];
            ldsm4(a, uPs + (wq0 + arow) * (HS * 2) + (kk + acol) * 2);
            uint32_t bf[4][4];
#pragma unroll
            for (int p = 0; p < 4; p++)
                ldsm4t(bf[p], uVs + (kk + vkrow) * (HS * 2) + (p * 16 + vncol) * 2);
#pragma unroll
            for (int nt = 0; nt < 8; nt++)
                mma16(accO[nt], a, &bf[nt >> 1][(nt & 1) * 2]);
        }
        stage ^= 1;
        j0 = nj;
    }

    // ---- epilogue (half out) ----
    const float inv0 = 1.0f / l0;
    const float inv1 = 1.0f / l1;
#pragma unroll
    for (int nt = 0; nt < 8; nt++) {
        const int col = h * DH + nt * 8 + 2 * tg;
        *reinterpret_cast<uint32_t*>(Oh + (size_t)gq0 * DIM + col) =
            pk2(accO[nt][0] * inv0, accO[nt][1] * inv0);
        *reinterpret_cast<uint32_t*>(Oh + (size_t)gq1 * DIM + col) =
            pk2(accO[nt][2] * inv1, accO[nt][3] * inv1);
    }
}

// ---------------------------------------------------------------------------
// LayerNorm: float in; float out (+ optional half out). Vectorized.
// ---------------------------------------------------------------------------
template <bool WH>
__global__ void __launch_bounds__(256)
ln_kernel(const float* __restrict__ a, const float* __restrict__ g,
          const float* __restrict__ beta, float* __restrict__ out,
          __half* __restrict__ outh)
{
    const int row = blockIdx.x;
    const int c0 = threadIdx.x * 4;
    __shared__ float sh1[8], sh2[8];

    const float4 v = *reinterpret_cast<const float4*>(a + (size_t)row * DIM + c0);
    float s = v.x + v.y + v.z + v.w;
#pragma unroll
    for (int off = 16; off >= 1; off >>= 1) s += __shfl_xor_sync(0xffffffffu, s, off);
    if ((threadIdx.x & 31) == 0) sh1[threadIdx.x >> 5] = s;
    __syncthreads();
    float mu = 0.0f;
#pragma unroll
    for (int i = 0; i < 8; i++) mu += sh1[i];
    mu *= (1.0f / DIM);

    float d0 = v.x - mu, d1 = v.y - mu, d2 = v.z - mu, d3 = v.w - mu;
    float vs = d0 * d0 + d1 * d1 + d2 * d2 + d3 * d3;
#pragma unroll
    for (int off = 16; off >= 1; off >>= 1) vs += __shfl_xor_sync(0xffffffffu, vs, off);
    if ((threadIdx.x & 31) == 0) sh2[threadIdx.x >> 5] = vs;
    __syncthreads();
    float var = 0.0f;
#pragma unroll
    for (int i = 0; i < 8; i++) var += sh2[i];
    const float inv = rsqrtf(var * (1.0f / DIM) + 1e-5f);

    const float4 gv = *reinterpret_cast<const float4*>(g + c0);
    const float4 bv = *reinterpret_cast<const float4*>(beta + c0);
    float4 o;
    o.x = d0 * inv * gv.x + bv.x;
    o.y = d1 * inv * gv.y + bv.y;
    o.z = d2 * inv * gv.z + bv.z;
    o.w = d3 * inv * gv.w + bv.w;
    *reinterpret_cast<float4*>(out + (size_t)row * DIM + c0) = o;
    if (WH) {
        uint2 ho; ho.x = pk2(o.x, o.y); ho.y = pk2(o.z, o.w);
        *reinterpret_cast<uint2*>(outh + (size_t)row * DIM + c0) = ho;
    }
}

// ---------------------------------------------------------------------------
// Launch
// ---------------------------------------------------------------------------
extern "C" void kernel_launch(void* const* d_in, const int* in_sizes, int n_in,
                              void* d_out, int out_size)
{
    const float* x     = (const float*)d_in[0];
    const float* ctx   = (const float*)d_in[1];
    const float* Wq    = (const float*)d_in[2];
    const float* bq    = (const float*)d_in[3];
    const float* Wkv   = (const float*)d_in[4];
    const float* bkv   = (const float*)d_in[5];
    const float* Wo    = (const float*)d_in[6];
    const float* bo    = (const float*)d_in[7];
    const float* ln1g  = (const float*)d_in[8];
    const float* ln1b  = (const float*)d_in[9];
    const float* W1    = (const float*)d_in[10];
    const float* bf1   = (const float*)d_in[11];
    const float* W2    = (const float*)d_in[12];
    const float* bf2   = (const float*)d_in[13];
    const float* ln2g  = (const float*)d_in[14];
    const float* ln2b  = (const float*)d_in[15];
    float* out = (float*)d_out;

    __half *inh, *qh, *kvh, *attnh, *x1h, *ffh, *wqT, *wkvT, *woT, *w1T, *w2T;
    float *t, *x1;
    cudaGetSymbolAddress((void**)&inh,   g_inh);
    cudaGetSymbolAddress((void**)&qh,    g_qh);
    cudaGetSymbolAddress((void**)&kvh,   g_kvh);
    cudaGetSymbolAddress((void**)&attnh, g_attnh);
    cudaGetSymbolAddress((void**)&x1h,   g_x1h);
    cudaGetSymbolAddress((void**)&ffh,   g_ffh);
    cudaGetSymbolAddress((void**)&t,     g_t);
    cudaGetSymbolAddress((void**)&x1,    g_x1);
    cudaGetSymbolAddress((void**)&wqT,   g_wqT);
    cudaGetSymbolAddress((void**)&wkvT,  g_wkvT);
    cudaGetSymbolAddress((void**)&woT,   g_woT);
    cudaGetSymbolAddress((void**)&w1T,   g_w1T);
    cudaGetSymbolAddress((void**)&w2T,   g_w2T);

    cudaFuncSetAttribute(attn_kernel, cudaFuncAttributeMaxDynamicSharedMemorySize, ATT_SMEM);
    cudaFuncSetAttribute(qkv_gemm,    cudaFuncAttributeMaxDynamicSharedMemorySize, GEMM_SMEM);
    cudaFuncSetAttribute(mma_gemm<2>, cudaFuncAttributeMaxDynamicSharedMemorySize, GEMM_SMEM);
    cudaFuncSetAttribute(mma_gemm<3>, cudaFuncAttributeMaxDynamicSharedMemorySize, GEMM_SMEM);

    // one-time host-side resources
    static cudaStream_t s2 = nullptr;
    static cudaEvent_t eBegin = nullptr, eQKV = nullptr, eW = nullptr;
    if (s2 == nullptr) {
        cudaStreamCreateWithFlags(&s2, cudaStreamNonBlocking);
        cudaEventCreateWithFlags(&eBegin, cudaEventDisableTiming);
        cudaEventCreateWithFlags(&eQKV,   cudaEventDisableTiming);
        cudaEventCreateWithFlags(&eW,     cudaEventDisableTiming);
    }

    // ---- fork: weight transposes on s2 ----
    cudaEventRecord(eBegin, 0);
    cudaStreamWaitEvent(s2, eBegin, 0);

    transpose_h_kernel<<<dim3(DIM / 32, DIM / 32), 256, 0, s2>>>(Wq,  wqT,  DIM,  DIM);
    transpose_h_kernel<<<dim3(2 * DIM / 32, DIM / 32), 256, 0, s2>>>(Wkv, wkvT, DIM, 2 * DIM);
    cudaEventRecord(eQKV, s2);
    transpose_h_kernel<<<dim3(DIM / 32, DIM / 32), 256, 0, s2>>>(Wo,  woT,  DIM,  DIM);
    transpose_h_kernel<<<dim3(DFF_ / 32, DIM / 32), 256, 0, s2>>>(W1,  w1T,  DIM,  DFF_);
    transpose_h_kernel<<<dim3(DIM / 32, DFF_ / 32), 256, 0, s2>>>(W2,  w2T,  DFF_, DIM);
    cudaEventRecord(eW, s2);

    // main: activation convert
    convert_h_kernel<<<TOTK * DIM / (256 * 8), 256>>>(x, ctx, inh);

    // 1+2) merged QKV projection (Q gets alpha = log2e/8)
    cudaStreamWaitEvent(0, eQKV, 0);
    qkv_gemm<<<640, 128, GEMM_SMEM>>>(inh, wqT, wkvT, bq, bkv, qh, kvh,
                                      0.18033688011112042f);

    // 3) attention -> attnh
    attn_kernel<<<dim3(SEQ_N / QROWS, HEADS), 512, ATT_SMEM>>>(qh, kvh, attnh);

    // ---- join: remaining weights ready ----
    cudaStreamWaitEvent(0, eW, 0);

    // 4) t = attn @ Wo + bo + x
    mma_gemm<3><<<dim3(DIM / 128, SEQ_N / 128), 128, GEMM_SMEM>>>(
        attnh, woT, bo, x, t, nullptr, SEQ_N, DIM, DIM);

    // 5) x1 = LN1(t)  (float + half)
    ln_kernel<true><<<SEQ_N, 256>>>(t, ln1g, ln1b, x1, x1h);

    // 6) ffh = gelu(x1 @ W1 + bf1)
    mma_gemm<2><<<dim3(DFF_ / 128, SEQ_N / 128), 128, GEMM_SMEM>>>(
        x1h, w1T, bf1, nullptr, nullptr, ffh, SEQ_N, DFF_, DIM);

    // 7) t = ff @ W2 + bf2 + x1
    mma_gemm<3><<<dim3(DIM / 128, SEQ_N / 128), 128, GEMM_SMEM>>>(
        ffh, w2T, bf2, x1, t, nullptr, SEQ_N, DIM, DFF_);

    // 8) out = LN2(t)
    ln_kernel<false><<<SEQ_N, 256>>>(t, ln2g, ln2b, out, nullptr);
}